// round 11
// baseline (speedup 1.0000x reference)
#include <cuda_runtime.h>
#include <cuda_bf16.h>
#include <math.h>
#include <stdint.h>

// Problem constants
constexpr int Bsz = 2, Lsz = 2048, DM = 1024, DI = 2048, DS = 16, DR = 64;
constexpr int M = Bsz * Lsz;          // 4096
constexpr int XZ_N = 2 * DI;          // 4096
constexpr int DBC_LD = 128;           // padded dbc row stride (real cols: 96)
constexpr int NC = 64, LC = 32;       // scan chunking: 64 chunks x 32 steps
constexpr int NCH = Bsz * DI;         // 4096 channels
constexpr int KSPLIT = 4;             // split-K factor for dbc GEMM

// fp32 scratch
__device__ float g_xz[(size_t)M * XZ_N];
__device__ float g_xc[(size_t)M * DI];
__device__ float g_dbcp[(size_t)M * DBC_LD];
__device__ float g_dbcpart[(size_t)KSPLIT * M * DBC_LD];
__device__ float g_delta[(size_t)M * DI];
__device__ float g_yz[(size_t)M * DI];           // raw local scan y
// scan chunk state
__device__ float g_hend[(size_t)NC * NCH * DS];
__device__ float g_ptot[(size_t)NC * NCH * DS];
__device__ float g_hin [(size_t)NC * NCH * DS];
// bf16 split operands (A row-major [rows,K]; B stored K-major as [N,K])
__device__ __nv_bfloat16 g_xh[(size_t)M * DM],      g_xl[(size_t)M * DM];
__device__ __nv_bfloat16 g_winh[(size_t)XZ_N * DM], g_winl[(size_t)XZ_N * DM];
__device__ __nv_bfloat16 g_xch[(size_t)M * DI],     g_xcl[(size_t)M * DI];
__device__ __nv_bfloat16 g_wxh[(size_t)DBC_LD * DI], g_wxl[(size_t)DBC_LD * DI];
__device__ __nv_bfloat16 g_yzh[(size_t)M * DI],     g_yzl[(size_t)M * DI];
__device__ __nv_bfloat16 g_wouth[(size_t)DM * DI],  g_woutl[(size_t)DM * DI];

__device__ __forceinline__ float sigmoidf_fast(float x) {
    return 1.0f / (1.0f + __expf(-x));
}
__device__ __forceinline__ float softplusf(float x) {
    return (x > 20.0f) ? x : log1pf(expf(x));
}

// ---------------------------------------------------------------------------
// PTX helpers (portable sm_80+ PTX only)
// ---------------------------------------------------------------------------
__device__ __forceinline__ void cp_async16(uint32_t dst, const void* src) {
    asm volatile("cp.async.cg.shared.global [%0], [%1], 16;"
                 :: "r"(dst), "l"(src) : "memory");
}
__device__ __forceinline__ void cp_commit() {
    asm volatile("cp.async.commit_group;" ::: "memory");
}
template <int N>
__device__ __forceinline__ void cp_wait() {
    asm volatile("cp.async.wait_group %0;" :: "n"(N) : "memory");
}
__device__ __forceinline__ void ldsm_x4(uint32_t* r, uint32_t addr) {
    asm volatile("ldmatrix.sync.aligned.m8n8.x4.shared.b16 {%0,%1,%2,%3}, [%4];"
                 : "=r"(r[0]), "=r"(r[1]), "=r"(r[2]), "=r"(r[3]) : "r"(addr));
}
__device__ __forceinline__ void mma16816(float* c, const uint32_t* a,
                                         uint32_t b0, uint32_t b1) {
    asm volatile(
        "mma.sync.aligned.m16n8k16.row.col.f32.bf16.bf16.f32 "
        "{%0,%1,%2,%3}, {%4,%5,%6,%7}, {%8,%9}, {%0,%1,%2,%3};"
        : "+f"(c[0]), "+f"(c[1]), "+f"(c[2]), "+f"(c[3])
        : "r"(a[0]), "r"(a[1]), "r"(a[2]), "r"(a[3]), "r"(b0), "r"(b1));
}

// ---------------------------------------------------------------------------
// Split fp32 -> (hi, lo) bf16, same layout
// ---------------------------------------------------------------------------
__global__ void split_k(const float* __restrict__ in,
                        __nv_bfloat16* __restrict__ hi,
                        __nv_bfloat16* __restrict__ lo, int n4)
{
    int i = blockIdx.x * blockDim.x + threadIdx.x;
    if (i >= n4) return;
    float4 v = ((const float4*)in)[i];
    __nv_bfloat16 h0 = __float2bfloat16(v.x);
    __nv_bfloat16 h1 = __float2bfloat16(v.y);
    __nv_bfloat16 h2 = __float2bfloat16(v.z);
    __nv_bfloat16 h3 = __float2bfloat16(v.w);
    ushort4 hh, ll;
    hh.x = __bfloat16_as_ushort(h0); hh.y = __bfloat16_as_ushort(h1);
    hh.z = __bfloat16_as_ushort(h2); hh.w = __bfloat16_as_ushort(h3);
    ll.x = __bfloat16_as_ushort(__float2bfloat16(v.x - __bfloat162float(h0)));
    ll.y = __bfloat16_as_ushort(__float2bfloat16(v.y - __bfloat162float(h1)));
    ll.z = __bfloat16_as_ushort(__float2bfloat16(v.z - __bfloat162float(h2)));
    ll.w = __bfloat16_as_ushort(__float2bfloat16(v.w - __bfloat162float(h3)));
    ((ushort4*)hi)[i] = hh;
    ((ushort4*)lo)[i] = ll;
}

// ---------------------------------------------------------------------------
// Transpose + split: in [K,N] fp32 row-major -> hi/lo [N,K] bf16
// ---------------------------------------------------------------------------
__global__ void tsplit_k(const float* __restrict__ in, int Kdim, int Ndim,
                         __nv_bfloat16* __restrict__ hi,
                         __nv_bfloat16* __restrict__ lo)
{
    __shared__ float t[32][33];
    const int n0 = blockIdx.x * 32, k0 = blockIdx.y * 32;
    const int tx = threadIdx.x, ty = threadIdx.y;  // block (32, 8)
    for (int i = ty; i < 32; i += 8)
        t[i][tx] = in[(size_t)(k0 + i) * Ndim + n0 + tx];
    __syncthreads();
    for (int i = ty; i < 32; i += 8) {
        float v = t[tx][i];  // = in[k0+tx][n0+i]
        __nv_bfloat16 h = __float2bfloat16(v);
        hi[(size_t)(n0 + i) * Kdim + k0 + tx] = h;
        lo[(size_t)(n0 + i) * Kdim + k0 + tx] =
            __float2bfloat16(v - __bfloat162float(h));
    }
}

__global__ void padzero_k(__nv_bfloat16* __restrict__ a,
                          __nv_bfloat16* __restrict__ b, int n)
{
    int i = blockIdx.x * blockDim.x + threadIdx.x;
    if (i < n) { a[i] = __float2bfloat16(0.0f); b[i] = __float2bfloat16(0.0f); }
}

// Reduce KSPLIT partial C buffers into one (float4 vectorized)
__global__ void reduce_part_k(const float* __restrict__ part,
                              float* __restrict__ out, int n4, size_t zstride4)
{
    int i = blockIdx.x * blockDim.x + threadIdx.x;
    if (i >= n4) return;
    float4 a = ((const float4*)part)[i];
#pragma unroll
    for (int z = 1; z < KSPLIT; z++) {
        float4 b = ((const float4*)part)[(size_t)z * zstride4 + i];
        a.x += b.x; a.y += b.y; a.z += b.z; a.w += b.w;
    }
    ((float4*)out)[i] = a;
}

// ---------------------------------------------------------------------------
// mma.sync split-bf16 GEMM: C[M,N] = A[M,K] @ B_t[N,K]^T (fp32 out)
// CTA tile 128x128, BK=32, 256 threads (8 warps, 4Mx2N), warp tile 32x64.
// 4-buffer / depth-3 cp.async pipeline with a SINGLE barrier per chunk:
//   iter c: wait<2>; sync; prefetch chunk c+3 into (c+3)%4; MMA on c%4.
// Buffer (c+3)%4 was last read at iter c-1, ordered by this iter's barrier.
// Interleaved MMA order (proven fastest). Split-K via blockIdx.z.
// ---------------------------------------------------------------------------
constexpr int BK = 32;
constexpr int ROWB = 80;
constexpr int TILEB = 128 * ROWB;
constexpr int STAGEB = 4 * TILEB;
constexpr int NSTAGE = 4;
constexpr int SMEM_MMA = NSTAGE * STAGEB;  // 163840 B

__global__ void __launch_bounds__(256, 1) mma_gemm_k(
    const __nv_bfloat16* __restrict__ Ah, const __nv_bfloat16* __restrict__ Al,
    const __nv_bfloat16* __restrict__ Bh, const __nv_bfloat16* __restrict__ Bl,
    float* __restrict__ C, int lda, int ldc, int kspan, size_t zstride)
{
    extern __shared__ __align__(16) char smem[];
    const uint32_t sb = (uint32_t)__cvta_generic_to_shared(smem);
    const int tid = threadIdx.x;
    const int wid = tid >> 5, lid = tid & 31;
    const int warpM = wid & 3, warpN = wid >> 2;   // 4 x 2

    const int rowBase = blockIdx.y * 128;
    const int colBase = blockIdx.x * 128;
    const int kstart = blockIdx.z * kspan;
    const int nch = kspan / BK;
    C += (size_t)blockIdx.z * zstride;

    float acc[2][8][4];
#pragma unroll
    for (int i = 0; i < 2; i++)
#pragma unroll
        for (int j = 0; j < 8; j++)
#pragma unroll
            for (int q = 0; q < 4; q++) acc[i][j][q] = 0.0f;

    auto load_chunk = [&](int c, int buf) {
        const uint32_t st = sb + buf * STAGEB;
        const int k0 = kstart + c * BK;
#pragma unroll
        for (int ch = tid; ch < 512; ch += 256) {
            const int row = ch >> 2;
            const int kc = ch & 3;
            const uint32_t so = row * ROWB + kc * 16;
            const size_t go = (size_t)k0 + kc * 8;
            cp_async16(st + so,             Ah + (size_t)(rowBase + row) * lda + go);
            cp_async16(st + TILEB + so,     Al + (size_t)(rowBase + row) * lda + go);
            cp_async16(st + 2 * TILEB + so, Bh + (size_t)(colBase + row) * lda + go);
            cp_async16(st + 3 * TILEB + so, Bl + (size_t)(colBase + row) * lda + go);
        }
        cp_commit();
    };

    // depth-3 prologue (all call sites have nch >= 16)
    load_chunk(0, 0);
    load_chunk(1, 1);
    load_chunk(2, 2);

    const int lr = lid & 15;
    const int lc16 = (lid >> 4) * 16;

    for (int c = 0; c < nch; c++) {
        const int buf = c & 3;
        cp_wait<2>();
        __syncthreads();          // single barrier per chunk
        // prefetch chunk c+3 into buffer (c+3)%4 (last read at iter c-1)
        if (c + 3 < nch) load_chunk(c + 3, (c + 3) & 3);
        else cp_commit();         // dummy group keeps wait<2> invariant

        const uint32_t st = sb + buf * STAGEB;
#pragma unroll
        for (int kk = 0; kk < 2; kk++) {
            const uint32_t kb = kk * 32;
            uint32_t ah[2][4], al[2][4];
#pragma unroll
            for (int mf = 0; mf < 2; mf++) {
                const uint32_t a =
                    st + (warpM * 32 + mf * 16 + lr) * ROWB + kb + lc16;
                ldsm_x4(ah[mf], a);
                ldsm_x4(al[mf], a + TILEB);
            }
            uint32_t bh[8][2], bl[8][2];
#pragma unroll
            for (int np = 0; np < 4; np++) {
                const uint32_t a =
                    st + 2 * TILEB + (warpN * 64 + np * 16 + lr) * ROWB + kb + lc16;
                uint32_t t[4];
                ldsm_x4(t, a);
                bh[2 * np][0] = t[0]; bh[2 * np + 1][0] = t[1];
                bh[2 * np][1] = t[2]; bh[2 * np + 1][1] = t[3];
                ldsm_x4(t, a + TILEB);
                bl[2 * np][0] = t[0]; bl[2 * np + 1][0] = t[1];
                bl[2 * np][1] = t[2]; bl[2 * np + 1][1] = t[3];
            }
            // interleaved MMA order (proven fastest)
#pragma unroll
            for (int mf = 0; mf < 2; mf++)
#pragma unroll
                for (int nf = 0; nf < 8; nf++) {
                    mma16816(acc[mf][nf], ah[mf], bh[nf][0], bh[nf][1]);
                    mma16816(acc[mf][nf], ah[mf], bl[nf][0], bl[nf][1]);
                    mma16816(acc[mf][nf], al[mf], bh[nf][0], bh[nf][1]);
                }
        }
    }

    const int r = lid >> 2, cq = (lid & 3) * 2;
    float* Cw = C + (size_t)(rowBase + warpM * 32) * ldc + colBase + warpN * 64;
#pragma unroll
    for (int mf = 0; mf < 2; mf++)
#pragma unroll
        for (int nf = 0; nf < 8; nf++) {
            float2 v0 = make_float2(acc[mf][nf][0], acc[mf][nf][1]);
            float2 v1 = make_float2(acc[mf][nf][2], acc[mf][nf][3]);
            *(float2*)&Cw[(size_t)(mf * 16 + r) * ldc + nf * 8 + cq] = v0;
            *(float2*)&Cw[(size_t)(mf * 16 + r + 8) * ldc + nf * 8 + cq] = v1;
        }
}

// ---------------------------------------------------------------------------
// SIMT GEMM (delta). EPI: 0 none, 1 softplus(x + bias[col])
// ---------------------------------------------------------------------------
template <int BM, int BN, int BKt, int TM, int TN, int EPI>
__global__ void __launch_bounds__((BM / TM) * (BN / TN))
gemm_k(const float* __restrict__ A, int lda,
       const float* __restrict__ B, int ldb,
       float* __restrict__ C, int ldc,
       int Kdim, const float* __restrict__ bias)
{
    constexpr int THREADS = (BM / TM) * (BN / TN);
    __shared__ __align__(16) float As[BKt][BM];
    __shared__ __align__(16) float Bs[BKt][BN];

    const int tid = threadIdx.x;
    const int blockRow = blockIdx.y * BM;
    const int blockCol = blockIdx.x * BN;
    const int tRow = (tid / (BN / TN)) * TM;
    const int tCol = (tid % (BN / TN)) * TN;

    float acc[TM][TN];
#pragma unroll
    for (int i = 0; i < TM; i++)
#pragma unroll
        for (int j = 0; j < TN; j++) acc[i][j] = 0.0f;

    constexpr int A_F4_PER_ROW = BKt / 4;
    const int aRow = tid / A_F4_PER_ROW;
    const int aK = (tid % A_F4_PER_ROW) * 4;
    constexpr int A_ROWS_PER_PASS = THREADS / A_F4_PER_ROW;
    constexpr int B_F4_PER_ROW = BN / 4;
    const int bRow = tid / B_F4_PER_ROW;
    const int bCol = (tid % B_F4_PER_ROW) * 4;
    constexpr int B_ROWS_PER_PASS = THREADS / B_F4_PER_ROW;

    for (int k0 = 0; k0 < Kdim; k0 += BKt) {
#pragma unroll 1
        for (int rr = aRow; rr < BM; rr += A_ROWS_PER_PASS) {
            float4 v = *(const float4*)&A[(size_t)(blockRow + rr) * lda + k0 + aK];
            As[aK + 0][rr] = v.x; As[aK + 1][rr] = v.y;
            As[aK + 2][rr] = v.z; As[aK + 3][rr] = v.w;
        }
#pragma unroll 1
        for (int rr = bRow; rr < BKt; rr += B_ROWS_PER_PASS) {
            *(float4*)&Bs[rr][bCol] =
                *(const float4*)&B[(size_t)(k0 + rr) * ldb + blockCol + bCol];
        }
        __syncthreads();

#pragma unroll
        for (int kk = 0; kk < BKt; kk++) {
            float a[TM], bf[TN];
#pragma unroll
            for (int i = 0; i < TM; i += 4) {
                float4 v = *(const float4*)&As[kk][tRow + i];
                a[i] = v.x; a[i + 1] = v.y; a[i + 2] = v.z; a[i + 3] = v.w;
            }
#pragma unroll
            for (int j = 0; j < TN; j += 4) {
                float4 v = *(const float4*)&Bs[kk][tCol + j];
                bf[j] = v.x; bf[j + 1] = v.y; bf[j + 2] = v.z; bf[j + 3] = v.w;
            }
#pragma unroll
            for (int i = 0; i < TM; i++)
#pragma unroll
                for (int j = 0; j < TN; j++)
                    acc[i][j] = fmaf(a[i], bf[j], acc[i][j]);
        }
        __syncthreads();
    }

#pragma unroll
    for (int i = 0; i < TM; i++) {
        const int rr = blockRow + tRow + i;
#pragma unroll
        for (int j = 0; j < TN; j += 4) {
            const int cc = blockCol + tCol + j;
            float4 v;
            float v0 = acc[i][j + 0], v1 = acc[i][j + 1],
                  v2 = acc[i][j + 2], v3 = acc[i][j + 3];
            if (EPI == 1) {
                v0 = softplusf(v0 + bias[cc + 0]);
                v1 = softplusf(v1 + bias[cc + 1]);
                v2 = softplusf(v2 + bias[cc + 2]);
                v3 = softplusf(v3 + bias[cc + 3]);
            }
            v.x = v0; v.y = v1; v.z = v2; v.w = v3;
            *(float4*)&C[(size_t)rr * ldc + cc] = v;
        }
    }
}

// ---------------------------------------------------------------------------
// Depthwise causal conv (width 4) + SiLU + fused bf16 split output
// ---------------------------------------------------------------------------
__global__ void conv_silu_k(const float* __restrict__ xz,
                            const float* __restrict__ w,
                            const float* __restrict__ bias,
                            float* __restrict__ xc,
                            __nv_bfloat16* __restrict__ xch,
                            __nv_bfloat16* __restrict__ xcl)
{
    const int idx = blockIdx.x * blockDim.x + threadIdx.x;
    if (idx >= M * DI) return;
    const int d = idx % DI;
    const int m = idx / DI;
    const int l = m % Lsz;

    float acc = bias[d];
    const float w0 = w[d * 4 + 0], w1 = w[d * 4 + 1],
                w2 = w[d * 4 + 2], w3 = w[d * 4 + 3];
    if (l >= 3) acc = fmaf(w0, xz[(size_t)(m - 3) * XZ_N + d], acc);
    if (l >= 2) acc = fmaf(w1, xz[(size_t)(m - 2) * XZ_N + d], acc);
    if (l >= 1) acc = fmaf(w2, xz[(size_t)(m - 1) * XZ_N + d], acc);
    acc = fmaf(w3, xz[(size_t)m * XZ_N + d], acc);
    const float v = acc * sigmoidf_fast(acc);
    xc[idx] = v;
    const __nv_bfloat16 h = __float2bfloat16(v);
    xch[idx] = h;
    xcl[idx] = __float2bfloat16(v - __bfloat162float(h));
}

// ---------------------------------------------------------------------------
// Parallel selective scan, register-state version (round-10 winning config).
// ---------------------------------------------------------------------------
__global__ void __launch_bounds__(256) scan1_k(
    const float* __restrict__ delta_, const float* __restrict__ xc,
    const float* __restrict__ dbcp, const float* __restrict__ A_log,
    float* __restrict__ yz, float* __restrict__ hend, float* __restrict__ ptot)
{
    __shared__ float sB[LC][DS];
    __shared__ float sC[LC][DS];
    const int tid = threadIdx.x;
    const int blk = blockIdx.x;
    const int c = blk & (NC - 1);
    const int t = blk >> 6;            // 0..15
    const int b = t >> 3;
    const int d = ((t & 7) << 8) + tid;
    const size_t mbase = (size_t)b * Lsz + c * LC;

    for (int i = tid; i < LC * 32; i += 256) {
        const int row = i >> 5, col = i & 31;
        const float v = dbcp[(mbase + row) * DBC_LD + DR + col];
        if (col < DS) sB[row][col] = v;
        else          sC[row][col - DS] = v;
    }
    float Aneg[DS];
#pragma unroll
    for (int s = 0; s < DS; s++) Aneg[s] = -__expf(A_log[d * DS + s]);
    __syncthreads();

    float h[DS], p[DS];
#pragma unroll
    for (int s = 0; s < DS; s++) { h[s] = 0.0f; p[s] = 1.0f; }

#pragma unroll 2
    for (int k = 0; k < LC; k++) {
        const size_t m = mbase + k;
        const float delta = delta_[m * DI + d];
        const float du = delta * xc[m * DI + d];
        float y = 0.0f;
#pragma unroll
        for (int s = 0; s < DS; s++) {
            const float a = __expf(delta * Aneg[s]);
            p[s] *= a;
            h[s] = fmaf(a, h[s], du * sB[k][s]);
            y = fmaf(h[s], sC[k][s], y);
        }
        yz[m * DI + d] = y;
    }
    const size_t idx = (size_t)c * (NCH * DS) + ((size_t)(b * DI + d)) * DS;
#pragma unroll
    for (int s = 0; s < DS; s++) { hend[idx + s] = h[s]; ptot[idx + s] = p[s]; }
}

__global__ void __launch_bounds__(256) combine_k(
    const float* __restrict__ hend, const float* __restrict__ ptot,
    float* __restrict__ hin)
{
    const int i = blockIdx.x * 256 + threadIdx.x;  // NCH*DS = 65536
    float H = 0.0f;
#pragma unroll
    for (int c = 0; c < NC; c++) {
        const size_t idx = (size_t)c * (NCH * DS) + i;
        hin[idx] = H;
        H = fmaf(ptot[idx], H, hend[idx]);
    }
}

__global__ void __launch_bounds__(256) scan2_k(
    const float* __restrict__ delta_, const float* __restrict__ xc,
    const float* __restrict__ dbcp, const float* __restrict__ xz,
    const float* __restrict__ A_log, const float* __restrict__ D_skip,
    const float* __restrict__ hin_, const float* __restrict__ yz,
    __nv_bfloat16* __restrict__ yzh, __nv_bfloat16* __restrict__ yzl)
{
    __shared__ float sC[LC][DS];
    const int tid = threadIdx.x;
    const int blk = blockIdx.x;
    const int c = blk & (NC - 1);
    const int t = blk >> 6;
    const int b = t >> 3;
    const int d = ((t & 7) << 8) + tid;
    const size_t mbase = (size_t)b * Lsz + c * LC;

    for (int i = tid; i < LC * DS; i += 256) {
        const int row = i >> 4, col = i & 15;
        sC[row][col] = dbcp[(mbase + row) * DBC_LD + DR + DS + col];
    }
    float Aneg[DS];
#pragma unroll
    for (int s = 0; s < DS; s++) Aneg[s] = -__expf(A_log[d * DS + s]);
    const float dskip = D_skip[d];

    float hin[DS], p[DS];
    const size_t hidx = (size_t)c * (NCH * DS) + ((size_t)(b * DI + d)) * DS;
#pragma unroll
    for (int s = 0; s < DS; s++) { hin[s] = hin_[hidx + s]; p[s] = 1.0f; }
    __syncthreads();

#pragma unroll 2
    for (int k = 0; k < LC; k++) {
        const size_t m = mbase + k;
        const float delta = delta_[m * DI + d];
        float yc = 0.0f;
#pragma unroll
        for (int s = 0; s < DS; s++) {
            const float a = __expf(delta * Aneg[s]);
            p[s] *= a;
            yc = fmaf(hin[s] * p[s], sC[k][s], yc);
        }
        const float u = xc[m * DI + d];
        const float z = xz[m * XZ_N + DI + d];
        const float y = yz[m * DI + d] + yc + u * dskip;
        const float val = y * (z * sigmoidf_fast(z));
        const __nv_bfloat16 hh = __float2bfloat16(val);
        yzh[m * DI + d] = hh;
        yzl[m * DI + d] = __float2bfloat16(val - __bfloat162float(hh));
    }
}

// ---------------------------------------------------------------------------
extern "C" void kernel_launch(void* const* d_in, const int* in_sizes, int n_in,
                              void* d_out, int out_size)
{
    const float* x      = (const float*)d_in[0];
    const float* W_in   = (const float*)d_in[1];
    const float* conv_w = (const float*)d_in[2];
    const float* conv_b = (const float*)d_in[3];
    const float* W_xprj = (const float*)d_in[4];
    const float* W_dt   = (const float*)d_in[5];
    const float* b_dt   = (const float*)d_in[6];
    const float* A_log  = (const float*)d_in[7];
    const float* D_skip = (const float*)d_in[8];
    const float* W_out  = (const float*)d_in[9];
    float* out = (float*)d_out;

    float *xz, *xc, *dbcp, *dbcpart, *delta, *yz, *hend, *ptot, *hin;
    cudaGetSymbolAddress((void**)&xz, g_xz);
    cudaGetSymbolAddress((void**)&xc, g_xc);
    cudaGetSymbolAddress((void**)&dbcp, g_dbcp);
    cudaGetSymbolAddress((void**)&dbcpart, g_dbcpart);
    cudaGetSymbolAddress((void**)&delta, g_delta);
    cudaGetSymbolAddress((void**)&yz, g_yz);
    cudaGetSymbolAddress((void**)&hend, g_hend);
    cudaGetSymbolAddress((void**)&ptot, g_ptot);
    cudaGetSymbolAddress((void**)&hin, g_hin);
    __nv_bfloat16 *xh, *xl, *winh, *winl, *xch, *xcl, *wxh, *wxl,
                  *yzh, *yzl, *wouth, *woutl;
    cudaGetSymbolAddress((void**)&xh, g_xh);
    cudaGetSymbolAddress((void**)&xl, g_xl);
    cudaGetSymbolAddress((void**)&winh, g_winh);
    cudaGetSymbolAddress((void**)&winl, g_winl);
    cudaGetSymbolAddress((void**)&xch, g_xch);
    cudaGetSymbolAddress((void**)&xcl, g_xcl);
    cudaGetSymbolAddress((void**)&wxh, g_wxh);
    cudaGetSymbolAddress((void**)&wxl, g_wxl);
    cudaGetSymbolAddress((void**)&yzh, g_yzh);
    cudaGetSymbolAddress((void**)&yzl, g_yzl);
    cudaGetSymbolAddress((void**)&wouth, g_wouth);
    cudaGetSymbolAddress((void**)&woutl, g_woutl);

    cudaFuncSetAttribute(mma_gemm_k, cudaFuncAttributeMaxDynamicSharedMemorySize,
                         SMEM_MMA);

    // 0) operand prep
    split_k<<<(M * DM / 4 + 255) / 256, 256>>>(x, xh, xl, M * DM / 4);
    {   // W_in [DM, XZ_N] -> [XZ_N, DM]
        dim3 grid(XZ_N / 32, DM / 32);
        tsplit_k<<<grid, dim3(32, 8)>>>(W_in, DM, XZ_N, winh, winl);
    }
    {   // W_out [DI, DM] -> [DM, DI]
        dim3 grid(DM / 32, DI / 32);
        tsplit_k<<<grid, dim3(32, 8)>>>(W_out, DI, DM, wouth, woutl);
    }
    {   // W_xproj [DI, 96] -> [96, DI], pad rows 96..127 with zeros
        dim3 grid(96 / 32, DI / 32);
        tsplit_k<<<grid, dim3(32, 8)>>>(W_xprj, DI, 96, wxh, wxl);
        padzero_k<<<(32 * DI + 255) / 256, 256>>>(wxh + (size_t)96 * DI,
                                                  wxl + (size_t)96 * DI, 32 * DI);
    }

    // 1) xz = x @ W_in
    {
        dim3 grid(XZ_N / 128, M / 128, 1);
        mma_gemm_k<<<grid, 256, SMEM_MMA>>>(xh, xl, winh, winl, xz, DM, XZ_N,
                                            DM, 0);
    }
    // 2) conv + silu (+ bf16 split)
    conv_silu_k<<<(M * DI) / 256, 256>>>(xz, conv_w, conv_b, xc, xch, xcl);
    // 3) dbc = xc @ W_xproj (mma, padded N=128, split-K x4)
    {
        dim3 grid(1, M / 128, KSPLIT);
        mma_gemm_k<<<grid, 256, SMEM_MMA>>>(xch, xcl, wxh, wxl, dbcpart, DI,
                                            DBC_LD, DI / KSPLIT,
                                            (size_t)M * DBC_LD);
        reduce_part_k<<<(M * DBC_LD / 4 + 255) / 256, 256>>>(
            dbcpart, dbcp, M * DBC_LD / 4, (size_t)M * DBC_LD / 4);
    }
    // 4) delta = softplus(dt_lo @ W_dt + b_dt) (SIMT, K=64)
    {
        dim3 grid(DI / 128, M / 128);
        gemm_k<128, 128, 8, 8, 8, 1><<<grid, 256>>>(dbcp, DBC_LD, W_dt, DI,
                                                    delta, DI, DR, b_dt);
    }
    // 5) parallel selective scan (register-state version)
    {
        const int blocks = Bsz * (DI / 256) * NC;  // 1024
        scan1_k<<<blocks, 256>>>(delta, xc, dbcp, A_log, yz, hend, ptot);
        combine_k<<<(NCH * DS) / 256, 256>>>(hend, ptot, hin);
        scan2_k<<<blocks, 256>>>(delta, xc, dbcp, xz, A_log, D_skip, hin,
                                 yz, yzh, yzl);
    }
    // 6) out = yz @ W_out
    {
        dim3 grid(DM / 128, M / 128, 1);
        mma_gemm_k<<<grid, 256, SMEM_MMA>>>(yzh, yzl, wouth, woutl, out, DI, DM,
                                            DI, 0);
    }
}

// round 12
// speedup vs baseline: 1.4909x; 1.4909x over previous
#include <cuda_runtime.h>
#include <cuda_bf16.h>
#include <math.h>
#include <stdint.h>

// Problem constants
constexpr int Bsz = 2, Lsz = 2048, DM = 1024, DI = 2048, DS = 16, DR = 64;
constexpr int M = Bsz * Lsz;          // 4096
constexpr int XZ_N = 2 * DI;          // 4096
constexpr int DBC_LD = 128;           // padded dbc row stride (real cols: 96)
constexpr int NC = 64, LC = 32;       // scan chunking: 64 chunks x 32 steps
constexpr int NCH = Bsz * DI;         // 4096 channels
constexpr int KSPLIT = 4;             // split-K factor for dbc GEMM

// fp32 scratch
__device__ float g_xz[(size_t)M * XZ_N];
__device__ float g_xc[(size_t)M * DI];
__device__ float g_dbcp[(size_t)M * DBC_LD];
__device__ float g_dbcpart[(size_t)KSPLIT * M * DBC_LD];
__device__ float g_delta[(size_t)M * DI];
__device__ float g_yz[(size_t)M * DI];           // raw local scan y
// scan chunk state
__device__ float g_hend[(size_t)NC * NCH * DS];
__device__ float g_ptot[(size_t)NC * NCH * DS];
__device__ float g_hin [(size_t)NC * NCH * DS];
// bf16 split operands (A row-major [rows,K]; B stored K-major as [N,K])
__device__ __nv_bfloat16 g_xh[(size_t)M * DM],      g_xl[(size_t)M * DM];
__device__ __nv_bfloat16 g_winh[(size_t)XZ_N * DM], g_winl[(size_t)XZ_N * DM];
__device__ __nv_bfloat16 g_xch[(size_t)M * DI],     g_xcl[(size_t)M * DI];
__device__ __nv_bfloat16 g_wxh[(size_t)DBC_LD * DI], g_wxl[(size_t)DBC_LD * DI];
__device__ __nv_bfloat16 g_dth[(size_t)M * DR],     g_dtl[(size_t)M * DR];
__device__ __nv_bfloat16 g_wdth[(size_t)DI * DR],   g_wdtl[(size_t)DI * DR];
__device__ __nv_bfloat16 g_yzh[(size_t)M * DI],     g_yzl[(size_t)M * DI];
__device__ __nv_bfloat16 g_wouth[(size_t)DM * DI],  g_woutl[(size_t)DM * DI];

__device__ __forceinline__ float sigmoidf_fast(float x) {
    return 1.0f / (1.0f + __expf(-x));
}
__device__ __forceinline__ float softplusf(float x) {
    return (x > 20.0f) ? x : log1pf(expf(x));
}

// ---------------------------------------------------------------------------
// PTX helpers (portable sm_80+ PTX only)
// ---------------------------------------------------------------------------
__device__ __forceinline__ void cp_async16(uint32_t dst, const void* src) {
    asm volatile("cp.async.cg.shared.global [%0], [%1], 16;"
                 :: "r"(dst), "l"(src) : "memory");
}
__device__ __forceinline__ void cp_commit() {
    asm volatile("cp.async.commit_group;" ::: "memory");
}
template <int N>
__device__ __forceinline__ void cp_wait() {
    asm volatile("cp.async.wait_group %0;" :: "n"(N) : "memory");
}
__device__ __forceinline__ void ldsm_x4(uint32_t* r, uint32_t addr) {
    asm volatile("ldmatrix.sync.aligned.m8n8.x4.shared.b16 {%0,%1,%2,%3}, [%4];"
                 : "=r"(r[0]), "=r"(r[1]), "=r"(r[2]), "=r"(r[3]) : "r"(addr));
}
__device__ __forceinline__ void mma16816(float* c, const uint32_t* a,
                                         uint32_t b0, uint32_t b1) {
    asm volatile(
        "mma.sync.aligned.m16n8k16.row.col.f32.bf16.bf16.f32 "
        "{%0,%1,%2,%3}, {%4,%5,%6,%7}, {%8,%9}, {%0,%1,%2,%3};"
        : "+f"(c[0]), "+f"(c[1]), "+f"(c[2]), "+f"(c[3])
        : "r"(a[0]), "r"(a[1]), "r"(a[2]), "r"(a[3]), "r"(b0), "r"(b1));
}

// ---------------------------------------------------------------------------
// Split fp32 -> (hi, lo) bf16, same layout
// ---------------------------------------------------------------------------
__global__ void split_k(const float* __restrict__ in,
                        __nv_bfloat16* __restrict__ hi,
                        __nv_bfloat16* __restrict__ lo, int n4)
{
    int i = blockIdx.x * blockDim.x + threadIdx.x;
    if (i >= n4) return;
    float4 v = ((const float4*)in)[i];
    __nv_bfloat16 h0 = __float2bfloat16(v.x);
    __nv_bfloat16 h1 = __float2bfloat16(v.y);
    __nv_bfloat16 h2 = __float2bfloat16(v.z);
    __nv_bfloat16 h3 = __float2bfloat16(v.w);
    ushort4 hh, ll;
    hh.x = __bfloat16_as_ushort(h0); hh.y = __bfloat16_as_ushort(h1);
    hh.z = __bfloat16_as_ushort(h2); hh.w = __bfloat16_as_ushort(h3);
    ll.x = __bfloat16_as_ushort(__float2bfloat16(v.x - __bfloat162float(h0)));
    ll.y = __bfloat16_as_ushort(__float2bfloat16(v.y - __bfloat162float(h1)));
    ll.z = __bfloat16_as_ushort(__float2bfloat16(v.z - __bfloat162float(h2)));
    ll.w = __bfloat16_as_ushort(__float2bfloat16(v.w - __bfloat162float(h3)));
    ((ushort4*)hi)[i] = hh;
    ((ushort4*)lo)[i] = ll;
}

// Split with strided source rows: in [rows, ncol] with leading dim ld.
// Output packed [rows, ncol] bf16 hi/lo. ncol multiple of 4.
__global__ void split_strided_k(const float* __restrict__ in, int ld, int ncol,
                                __nv_bfloat16* __restrict__ hi,
                                __nv_bfloat16* __restrict__ lo, int n4)
{
    int i = blockIdx.x * blockDim.x + threadIdx.x;
    if (i >= n4) return;
    const int per_row = ncol / 4;
    const int row = i / per_row;
    const int c4 = (i % per_row) * 4;
    float4 v = *(const float4*)&in[(size_t)row * ld + c4];
    __nv_bfloat16 h0 = __float2bfloat16(v.x);
    __nv_bfloat16 h1 = __float2bfloat16(v.y);
    __nv_bfloat16 h2 = __float2bfloat16(v.z);
    __nv_bfloat16 h3 = __float2bfloat16(v.w);
    ushort4 hh, ll;
    hh.x = __bfloat16_as_ushort(h0); hh.y = __bfloat16_as_ushort(h1);
    hh.z = __bfloat16_as_ushort(h2); hh.w = __bfloat16_as_ushort(h3);
    ll.x = __bfloat16_as_ushort(__float2bfloat16(v.x - __bfloat162float(h0)));
    ll.y = __bfloat16_as_ushort(__float2bfloat16(v.y - __bfloat162float(h1)));
    ll.z = __bfloat16_as_ushort(__float2bfloat16(v.z - __bfloat162float(h2)));
    ll.w = __bfloat16_as_ushort(__float2bfloat16(v.w - __bfloat162float(h3)));
    ((ushort4*)hi)[i] = hh;
    ((ushort4*)lo)[i] = ll;
}

// ---------------------------------------------------------------------------
// Transpose + split: in [K,N] fp32 row-major -> hi/lo [N,K] bf16
// ---------------------------------------------------------------------------
__global__ void tsplit_k(const float* __restrict__ in, int Kdim, int Ndim,
                         __nv_bfloat16* __restrict__ hi,
                         __nv_bfloat16* __restrict__ lo)
{
    __shared__ float t[32][33];
    const int n0 = blockIdx.x * 32, k0 = blockIdx.y * 32;
    const int tx = threadIdx.x, ty = threadIdx.y;  // block (32, 8)
    for (int i = ty; i < 32; i += 8)
        t[i][tx] = in[(size_t)(k0 + i) * Ndim + n0 + tx];
    __syncthreads();
    for (int i = ty; i < 32; i += 8) {
        float v = t[tx][i];  // = in[k0+tx][n0+i]
        __nv_bfloat16 h = __float2bfloat16(v);
        hi[(size_t)(n0 + i) * Kdim + k0 + tx] = h;
        lo[(size_t)(n0 + i) * Kdim + k0 + tx] =
            __float2bfloat16(v - __bfloat162float(h));
    }
}

__global__ void padzero_k(__nv_bfloat16* __restrict__ a,
                          __nv_bfloat16* __restrict__ b, int n)
{
    int i = blockIdx.x * blockDim.x + threadIdx.x;
    if (i < n) { a[i] = __float2bfloat16(0.0f); b[i] = __float2bfloat16(0.0f); }
}

// Reduce KSPLIT partial C buffers into one (float4 vectorized)
__global__ void reduce_part_k(const float* __restrict__ part,
                              float* __restrict__ out, int n4, size_t zstride4)
{
    int i = blockIdx.x * blockDim.x + threadIdx.x;
    if (i >= n4) return;
    float4 a = ((const float4*)part)[i];
#pragma unroll
    for (int z = 1; z < KSPLIT; z++) {
        float4 b = ((const float4*)part)[(size_t)z * zstride4 + i];
        a.x += b.x; a.y += b.y; a.z += b.z; a.w += b.w;
    }
    ((float4*)out)[i] = a;
}

// ---------------------------------------------------------------------------
// mma.sync split-bf16 GEMM (round-10 winning mainloop, FROZEN).
// Additions kept OUTSIDE the mainloop: guarded prologue (small nch) and an
// optional softplus(x + bias[col]) epilogue.
// ---------------------------------------------------------------------------
constexpr int BK = 32;
constexpr int ROWB = 80;
constexpr int TILEB = 128 * ROWB;
constexpr int STAGEB = 4 * TILEB;
constexpr int NSTAGE = 3;
constexpr int SMEM_MMA = NSTAGE * STAGEB;  // 122880 B

__global__ void __launch_bounds__(256, 1) mma_gemm_k(
    const __nv_bfloat16* __restrict__ Ah, const __nv_bfloat16* __restrict__ Al,
    const __nv_bfloat16* __restrict__ Bh, const __nv_bfloat16* __restrict__ Bl,
    float* __restrict__ C, int lda, int ldc, int kspan, size_t zstride,
    const float* __restrict__ bias)
{
    extern __shared__ __align__(16) char smem[];
    const uint32_t sb = (uint32_t)__cvta_generic_to_shared(smem);
    const int tid = threadIdx.x;
    const int wid = tid >> 5, lid = tid & 31;
    const int warpM = wid & 3, warpN = wid >> 2;   // 4 x 2

    const int rowBase = blockIdx.y * 128;
    const int colBase = blockIdx.x * 128;
    const int kstart = blockIdx.z * kspan;
    const int nch = kspan / BK;
    C += (size_t)blockIdx.z * zstride;

    float acc[2][8][4];
#pragma unroll
    for (int i = 0; i < 2; i++)
#pragma unroll
        for (int j = 0; j < 8; j++)
#pragma unroll
            for (int q = 0; q < 4; q++) acc[i][j][q] = 0.0f;

    auto load_chunk = [&](int c, int buf) {
        const uint32_t st = sb + buf * STAGEB;
        const int k0 = kstart + c * BK;
#pragma unroll
        for (int ch = tid; ch < 512; ch += 256) {
            const int row = ch >> 2;
            const int kc = ch & 3;
            const uint32_t so = row * ROWB + kc * 16;
            const size_t go = (size_t)k0 + kc * 8;
            cp_async16(st + so,             Ah + (size_t)(rowBase + row) * lda + go);
            cp_async16(st + TILEB + so,     Al + (size_t)(rowBase + row) * lda + go);
            cp_async16(st + 2 * TILEB + so, Bh + (size_t)(colBase + row) * lda + go);
            cp_async16(st + 3 * TILEB + so, Bl + (size_t)(colBase + row) * lda + go);
        }
        cp_commit();
    };

    // guarded depth-3 prologue (nch may be as small as 2)
    load_chunk(0, 0);
    if (1 < nch) load_chunk(1, 1); else cp_commit();
    if (2 < nch) load_chunk(2, 2); else cp_commit();

    const int lr = lid & 15;
    const int lc16 = (lid >> 4) * 16;

    for (int c = 0; c < nch; c++) {
        const int buf = c % NSTAGE;
        cp_wait<NSTAGE - 1>();
        __syncthreads();

        const uint32_t st = sb + buf * STAGEB;
#pragma unroll
        for (int kk = 0; kk < 2; kk++) {
            const uint32_t kb = kk * 32;
            uint32_t ah[2][4], al[2][4];
#pragma unroll
            for (int mf = 0; mf < 2; mf++) {
                const uint32_t a =
                    st + (warpM * 32 + mf * 16 + lr) * ROWB + kb + lc16;
                ldsm_x4(ah[mf], a);
                ldsm_x4(al[mf], a + TILEB);
            }
            uint32_t bh[8][2], bl[8][2];
#pragma unroll
            for (int np = 0; np < 4; np++) {
                const uint32_t a =
                    st + 2 * TILEB + (warpN * 64 + np * 16 + lr) * ROWB + kb + lc16;
                uint32_t t[4];
                ldsm_x4(t, a);
                bh[2 * np][0] = t[0]; bh[2 * np + 1][0] = t[1];
                bh[2 * np][1] = t[2]; bh[2 * np + 1][1] = t[3];
                ldsm_x4(t, a + TILEB);
                bl[2 * np][0] = t[0]; bl[2 * np + 1][0] = t[1];
                bl[2 * np][1] = t[2]; bl[2 * np + 1][1] = t[3];
            }
            // interleaved MMA order (proven fastest)
#pragma unroll
            for (int mf = 0; mf < 2; mf++)
#pragma unroll
                for (int nf = 0; nf < 8; nf++) {
                    mma16816(acc[mf][nf], ah[mf], bh[nf][0], bh[nf][1]);
                    mma16816(acc[mf][nf], ah[mf], bl[nf][0], bl[nf][1]);
                    mma16816(acc[mf][nf], al[mf], bh[nf][0], bh[nf][1]);
                }
        }
        __syncthreads();
        if (c + NSTAGE < nch) load_chunk(c + NSTAGE, buf);
        else cp_commit();
    }

    const int r = lid >> 2, cq = (lid & 3) * 2;
    float* Cw = C + (size_t)(rowBase + warpM * 32) * ldc + colBase + warpN * 64;
    const int cBase = colBase + warpN * 64;
#pragma unroll
    for (int mf = 0; mf < 2; mf++)
#pragma unroll
        for (int nf = 0; nf < 8; nf++) {
            float v0 = acc[mf][nf][0], v1 = acc[mf][nf][1];
            float v2 = acc[mf][nf][2], v3 = acc[mf][nf][3];
            if (bias) {
                const float b0 = bias[cBase + nf * 8 + cq];
                const float b1 = bias[cBase + nf * 8 + cq + 1];
                v0 = softplusf(v0 + b0); v1 = softplusf(v1 + b1);
                v2 = softplusf(v2 + b0); v3 = softplusf(v3 + b1);
            }
            *(float2*)&Cw[(size_t)(mf * 16 + r) * ldc + nf * 8 + cq] =
                make_float2(v0, v1);
            *(float2*)&Cw[(size_t)(mf * 16 + r + 8) * ldc + nf * 8 + cq] =
                make_float2(v2, v3);
        }
}

// ---------------------------------------------------------------------------
// Depthwise causal conv (width 4) + SiLU + fused bf16 split output
// ---------------------------------------------------------------------------
__global__ void conv_silu_k(const float* __restrict__ xz,
                            const float* __restrict__ w,
                            const float* __restrict__ bias,
                            float* __restrict__ xc,
                            __nv_bfloat16* __restrict__ xch,
                            __nv_bfloat16* __restrict__ xcl)
{
    const int idx = blockIdx.x * blockDim.x + threadIdx.x;
    if (idx >= M * DI) return;
    const int d = idx % DI;
    const int m = idx / DI;
    const int l = m % Lsz;

    float acc = bias[d];
    const float w0 = w[d * 4 + 0], w1 = w[d * 4 + 1],
                w2 = w[d * 4 + 2], w3 = w[d * 4 + 3];
    if (l >= 3) acc = fmaf(w0, xz[(size_t)(m - 3) * XZ_N + d], acc);
    if (l >= 2) acc = fmaf(w1, xz[(size_t)(m - 2) * XZ_N + d], acc);
    if (l >= 1) acc = fmaf(w2, xz[(size_t)(m - 1) * XZ_N + d], acc);
    acc = fmaf(w3, xz[(size_t)m * XZ_N + d], acc);
    const float v = acc * sigmoidf_fast(acc);
    xc[idx] = v;
    const __nv_bfloat16 h = __float2bfloat16(v);
    xch[idx] = h;
    xcl[idx] = __float2bfloat16(v - __bfloat162float(h));
}

// ---------------------------------------------------------------------------
// Parallel selective scan, register-state version (round-10 winning config).
// ---------------------------------------------------------------------------
__global__ void __launch_bounds__(256) scan1_k(
    const float* __restrict__ delta_, const float* __restrict__ xc,
    const float* __restrict__ dbcp, const float* __restrict__ A_log,
    float* __restrict__ yz, float* __restrict__ hend, float* __restrict__ ptot)
{
    __shared__ float sB[LC][DS];
    __shared__ float sC[LC][DS];
    const int tid = threadIdx.x;
    const int blk = blockIdx.x;
    const int c = blk & (NC - 1);
    const int t = blk >> 6;            // 0..15
    const int b = t >> 3;
    const int d = ((t & 7) << 8) + tid;
    const size_t mbase = (size_t)b * Lsz + c * LC;

    for (int i = tid; i < LC * 32; i += 256) {
        const int row = i >> 5, col = i & 31;
        const float v = dbcp[(mbase + row) * DBC_LD + DR + col];
        if (col < DS) sB[row][col] = v;
        else          sC[row][col - DS] = v;
    }
    float Aneg[DS];
#pragma unroll
    for (int s = 0; s < DS; s++) Aneg[s] = -__expf(A_log[d * DS + s]);
    __syncthreads();

    float h[DS], p[DS];
#pragma unroll
    for (int s = 0; s < DS; s++) { h[s] = 0.0f; p[s] = 1.0f; }

#pragma unroll 2
    for (int k = 0; k < LC; k++) {
        const size_t m = mbase + k;
        const float delta = delta_[m * DI + d];
        const float du = delta * xc[m * DI + d];
        float y = 0.0f;
#pragma unroll
        for (int s = 0; s < DS; s++) {
            const float a = __expf(delta * Aneg[s]);
            p[s] *= a;
            h[s] = fmaf(a, h[s], du * sB[k][s]);
            y = fmaf(h[s], sC[k][s], y);
        }
        yz[m * DI + d] = y;
    }
    const size_t idx = (size_t)c * (NCH * DS) + ((size_t)(b * DI + d)) * DS;
#pragma unroll
    for (int s = 0; s < DS; s++) { hend[idx + s] = h[s]; ptot[idx + s] = p[s]; }
}

__global__ void __launch_bounds__(256) combine_k(
    const float* __restrict__ hend, const float* __restrict__ ptot,
    float* __restrict__ hin)
{
    const int i = blockIdx.x * 256 + threadIdx.x;  // NCH*DS = 65536
    float H = 0.0f;
#pragma unroll
    for (int c = 0; c < NC; c++) {
        const size_t idx = (size_t)c * (NCH * DS) + i;
        hin[idx] = H;
        H = fmaf(ptot[idx], H, hend[idx]);
    }
}

__global__ void __launch_bounds__(256) scan2_k(
    const float* __restrict__ delta_, const float* __restrict__ xc,
    const float* __restrict__ dbcp, const float* __restrict__ xz,
    const float* __restrict__ A_log, const float* __restrict__ D_skip,
    const float* __restrict__ hin_, const float* __restrict__ yz,
    __nv_bfloat16* __restrict__ yzh, __nv_bfloat16* __restrict__ yzl)
{
    __shared__ float sC[LC][DS];
    const int tid = threadIdx.x;
    const int blk = blockIdx.x;
    const int c = blk & (NC - 1);
    const int t = blk >> 6;
    const int b = t >> 3;
    const int d = ((t & 7) << 8) + tid;
    const size_t mbase = (size_t)b * Lsz + c * LC;

    for (int i = tid; i < LC * DS; i += 256) {
        const int row = i >> 4, col = i & 15;
        sC[row][col] = dbcp[(mbase + row) * DBC_LD + DR + DS + col];
    }
    float Aneg[DS];
#pragma unroll
    for (int s = 0; s < DS; s++) Aneg[s] = -__expf(A_log[d * DS + s]);
    const float dskip = D_skip[d];

    float hin[DS], p[DS];
    const size_t hidx = (size_t)c * (NCH * DS) + ((size_t)(b * DI + d)) * DS;
#pragma unroll
    for (int s = 0; s < DS; s++) { hin[s] = hin_[hidx + s]; p[s] = 1.0f; }
    __syncthreads();

#pragma unroll 2
    for (int k = 0; k < LC; k++) {
        const size_t m = mbase + k;
        const float delta = delta_[m * DI + d];
        float yc = 0.0f;
#pragma unroll
        for (int s = 0; s < DS; s++) {
            const float a = __expf(delta * Aneg[s]);
            p[s] *= a;
            yc = fmaf(hin[s] * p[s], sC[k][s], yc);
        }
        const float u = xc[m * DI + d];
        const float z = xz[m * XZ_N + DI + d];
        const float y = yz[m * DI + d] + yc + u * dskip;
        const float val = y * (z * sigmoidf_fast(z));
        const __nv_bfloat16 hh = __float2bfloat16(val);
        yzh[m * DI + d] = hh;
        yzl[m * DI + d] = __float2bfloat16(val - __bfloat162float(hh));
    }
}

// ---------------------------------------------------------------------------
extern "C" void kernel_launch(void* const* d_in, const int* in_sizes, int n_in,
                              void* d_out, int out_size)
{
    const float* x      = (const float*)d_in[0];
    const float* W_in   = (const float*)d_in[1];
    const float* conv_w = (const float*)d_in[2];
    const float* conv_b = (const float*)d_in[3];
    const float* W_xprj = (const float*)d_in[4];
    const float* W_dt   = (const float*)d_in[5];
    const float* b_dt   = (const float*)d_in[6];
    const float* A_log  = (const float*)d_in[7];
    const float* D_skip = (const float*)d_in[8];
    const float* W_out  = (const float*)d_in[9];
    float* out = (float*)d_out;

    float *xz, *xc, *dbcp, *dbcpart, *delta, *yz, *hend, *ptot, *hin;
    cudaGetSymbolAddress((void**)&xz, g_xz);
    cudaGetSymbolAddress((void**)&xc, g_xc);
    cudaGetSymbolAddress((void**)&dbcp, g_dbcp);
    cudaGetSymbolAddress((void**)&dbcpart, g_dbcpart);
    cudaGetSymbolAddress((void**)&delta, g_delta);
    cudaGetSymbolAddress((void**)&yz, g_yz);
    cudaGetSymbolAddress((void**)&hend, g_hend);
    cudaGetSymbolAddress((void**)&ptot, g_ptot);
    cudaGetSymbolAddress((void**)&hin, g_hin);
    __nv_bfloat16 *xh, *xl, *winh, *winl, *xch, *xcl, *wxh, *wxl,
                  *dth, *dtl, *wdth, *wdtl, *yzh, *yzl, *wouth, *woutl;
    cudaGetSymbolAddress((void**)&xh, g_xh);
    cudaGetSymbolAddress((void**)&xl, g_xl);
    cudaGetSymbolAddress((void**)&winh, g_winh);
    cudaGetSymbolAddress((void**)&winl, g_winl);
    cudaGetSymbolAddress((void**)&xch, g_xch);
    cudaGetSymbolAddress((void**)&xcl, g_xcl);
    cudaGetSymbolAddress((void**)&wxh, g_wxh);
    cudaGetSymbolAddress((void**)&wxl, g_wxl);
    cudaGetSymbolAddress((void**)&dth, g_dth);
    cudaGetSymbolAddress((void**)&dtl, g_dtl);
    cudaGetSymbolAddress((void**)&wdth, g_wdth);
    cudaGetSymbolAddress((void**)&wdtl, g_wdtl);
    cudaGetSymbolAddress((void**)&yzh, g_yzh);
    cudaGetSymbolAddress((void**)&yzl, g_yzl);
    cudaGetSymbolAddress((void**)&wouth, g_wouth);
    cudaGetSymbolAddress((void**)&woutl, g_woutl);

    cudaFuncSetAttribute(mma_gemm_k, cudaFuncAttributeMaxDynamicSharedMemorySize,
                         SMEM_MMA);

    // 0) operand prep
    split_k<<<(M * DM / 4 + 255) / 256, 256>>>(x, xh, xl, M * DM / 4);
    {   // W_in [DM, XZ_N] -> [XZ_N, DM]
        dim3 grid(XZ_N / 32, DM / 32);
        tsplit_k<<<grid, dim3(32, 8)>>>(W_in, DM, XZ_N, winh, winl);
    }
    {   // W_out [DI, DM] -> [DM, DI]
        dim3 grid(DM / 32, DI / 32);
        tsplit_k<<<grid, dim3(32, 8)>>>(W_out, DI, DM, wouth, woutl);
    }
    {   // W_xproj [DI, 96] -> [96, DI], pad rows 96..127 with zeros
        dim3 grid(96 / 32, DI / 32);
        tsplit_k<<<grid, dim3(32, 8)>>>(W_xprj, DI, 96, wxh, wxl);
        padzero_k<<<(32 * DI + 255) / 256, 256>>>(wxh + (size_t)96 * DI,
                                                  wxl + (size_t)96 * DI, 32 * DI);
    }
    {   // W_dt [DR, DI] -> [DI, DR]
        dim3 grid(DI / 32, DR / 32);
        tsplit_k<<<grid, dim3(32, 8)>>>(W_dt, DR, DI, wdth, wdtl);
    }

    // 1) xz = x @ W_in
    {
        dim3 grid(XZ_N / 128, M / 128, 1);
        mma_gemm_k<<<grid, 256, SMEM_MMA>>>(xh, xl, winh, winl, xz, DM, XZ_N,
                                            DM, 0, nullptr);
    }
    // 2) conv + silu (+ bf16 split)
    conv_silu_k<<<(M * DI) / 256, 256>>>(xz, conv_w, conv_b, xc, xch, xcl);
    // 3) dbc = xc @ W_xproj (mma, padded N=128, split-K x4)
    {
        dim3 grid(1, M / 128, KSPLIT);
        mma_gemm_k<<<grid, 256, SMEM_MMA>>>(xch, xcl, wxh, wxl, dbcpart, DI,
                                            DBC_LD, DI / KSPLIT,
                                            (size_t)M * DBC_LD, nullptr);
        reduce_part_k<<<(M * DBC_LD / 4 + 255) / 256, 256>>>(
            dbcpart, dbcp, M * DBC_LD / 4, (size_t)M * DBC_LD / 4);
    }
    // 4) delta = softplus(dt_lo @ W_dt + b_dt) (mma, K=64, fused epilogue)
    {
        split_strided_k<<<(M * DR / 4 + 255) / 256, 256>>>(
            dbcp, DBC_LD, DR, dth, dtl, M * DR / 4);
        dim3 grid(DI / 128, M / 128, 1);
        mma_gemm_k<<<grid, 256, SMEM_MMA>>>(dth, dtl, wdth, wdtl, delta, DR, DI,
                                            DR, 0, b_dt);
    }
    // 5) parallel selective scan (register-state version)
    {
        const int blocks = Bsz * (DI / 256) * NC;  // 1024
        scan1_k<<<blocks, 256>>>(delta, xc, dbcp, A_log, yz, hend, ptot);
        combine_k<<<(NCH * DS) / 256, 256>>>(hend, ptot, hin);
        scan2_k<<<blocks, 256>>>(delta, xc, dbcp, xz, A_log, D_skip, hin,
                                 yz, yzh, yzl);
    }
    // 6) out = yz @ W_out
    {
        dim3 grid(DM / 128, M / 128, 1);
        mma_gemm_k<<<grid, 256, SMEM_MMA>>>(yzh, yzl, wouth, woutl, out, DI, DM,
                                            DI, 0, nullptr);
    }
}

// round 13
// speedup vs baseline: 1.5491x; 1.0391x over previous
#include <cuda_runtime.h>
#include <cuda_bf16.h>
#include <math.h>
#include <stdint.h>

// Problem constants
constexpr int Bsz = 2, Lsz = 2048, DM = 1024, DI = 2048, DS = 16, DR = 64;
constexpr int M = Bsz * Lsz;          // 4096
constexpr int XZ_N = 2 * DI;          // 4096
constexpr int DBC_LD = 128;           // padded dbc row stride (real cols: 96)
constexpr int NC = 64, LC = 32;       // scan chunking: 64 chunks x 32 steps
constexpr int NCH = Bsz * DI;         // 4096 channels
constexpr int KSPLIT = 4;             // split-K factor (dbc and out GEMMs)

// fp32 scratch
__device__ float g_xz[(size_t)M * XZ_N];
__device__ float g_xc[(size_t)M * DI];
__device__ float g_dbcp[(size_t)M * DBC_LD];
__device__ float g_dbcpart[(size_t)KSPLIT * M * DBC_LD];
__device__ float g_outpart[(size_t)KSPLIT * M * DM];
__device__ float g_delta[(size_t)M * DI];
__device__ float g_yz[(size_t)M * DI];           // raw local scan y
// scan chunk state
__device__ float g_hend[(size_t)NC * NCH * DS];
__device__ float g_ptot[(size_t)NC * NCH * DS];
__device__ float g_hin [(size_t)NC * NCH * DS];
// bf16 split operands (A row-major [rows,K]; B stored K-major as [N,K])
__device__ __nv_bfloat16 g_xh[(size_t)M * DM],      g_xl[(size_t)M * DM];
__device__ __nv_bfloat16 g_winh[(size_t)XZ_N * DM], g_winl[(size_t)XZ_N * DM];
__device__ __nv_bfloat16 g_xch[(size_t)M * DI],     g_xcl[(size_t)M * DI];
__device__ __nv_bfloat16 g_wxh[(size_t)DBC_LD * DI], g_wxl[(size_t)DBC_LD * DI];
__device__ __nv_bfloat16 g_dth[(size_t)M * DR],     g_dtl[(size_t)M * DR];
__device__ __nv_bfloat16 g_wdth[(size_t)DI * DR],   g_wdtl[(size_t)DI * DR];
__device__ __nv_bfloat16 g_yzh[(size_t)M * DI],     g_yzl[(size_t)M * DI];
__device__ __nv_bfloat16 g_wouth[(size_t)DM * DI],  g_woutl[(size_t)DM * DI];

__device__ __forceinline__ float sigmoidf_fast(float x) {
    return 1.0f / (1.0f + __expf(-x));
}
__device__ __forceinline__ float softplusf(float x) {
    return (x > 20.0f) ? x : log1pf(expf(x));
}

// ---------------------------------------------------------------------------
// PTX helpers (portable sm_80+ PTX only)
// ---------------------------------------------------------------------------
__device__ __forceinline__ void cp_async16(uint32_t dst, const void* src) {
    asm volatile("cp.async.cg.shared.global [%0], [%1], 16;"
                 :: "r"(dst), "l"(src) : "memory");
}
__device__ __forceinline__ void cp_commit() {
    asm volatile("cp.async.commit_group;" ::: "memory");
}
template <int N>
__device__ __forceinline__ void cp_wait() {
    asm volatile("cp.async.wait_group %0;" :: "n"(N) : "memory");
}
__device__ __forceinline__ void ldsm_x4(uint32_t* r, uint32_t addr) {
    asm volatile("ldmatrix.sync.aligned.m8n8.x4.shared.b16 {%0,%1,%2,%3}, [%4];"
                 : "=r"(r[0]), "=r"(r[1]), "=r"(r[2]), "=r"(r[3]) : "r"(addr));
}
__device__ __forceinline__ void mma16816(float* c, const uint32_t* a,
                                         uint32_t b0, uint32_t b1) {
    asm volatile(
        "mma.sync.aligned.m16n8k16.row.col.f32.bf16.bf16.f32 "
        "{%0,%1,%2,%3}, {%4,%5,%6,%7}, {%8,%9}, {%0,%1,%2,%3};"
        : "+f"(c[0]), "+f"(c[1]), "+f"(c[2]), "+f"(c[3])
        : "r"(a[0]), "r"(a[1]), "r"(a[2]), "r"(a[3]), "r"(b0), "r"(b1));
}

// ---------------------------------------------------------------------------
// Split fp32 -> (hi, lo) bf16, same layout
// ---------------------------------------------------------------------------
__global__ void split_k(const float* __restrict__ in,
                        __nv_bfloat16* __restrict__ hi,
                        __nv_bfloat16* __restrict__ lo, int n4)
{
    int i = blockIdx.x * blockDim.x + threadIdx.x;
    if (i >= n4) return;
    float4 v = ((const float4*)in)[i];
    __nv_bfloat16 h0 = __float2bfloat16(v.x);
    __nv_bfloat16 h1 = __float2bfloat16(v.y);
    __nv_bfloat16 h2 = __float2bfloat16(v.z);
    __nv_bfloat16 h3 = __float2bfloat16(v.w);
    ushort4 hh, ll;
    hh.x = __bfloat16_as_ushort(h0); hh.y = __bfloat16_as_ushort(h1);
    hh.z = __bfloat16_as_ushort(h2); hh.w = __bfloat16_as_ushort(h3);
    ll.x = __bfloat16_as_ushort(__float2bfloat16(v.x - __bfloat162float(h0)));
    ll.y = __bfloat16_as_ushort(__float2bfloat16(v.y - __bfloat162float(h1)));
    ll.z = __bfloat16_as_ushort(__float2bfloat16(v.z - __bfloat162float(h2)));
    ll.w = __bfloat16_as_ushort(__float2bfloat16(v.w - __bfloat162float(h3)));
    ((ushort4*)hi)[i] = hh;
    ((ushort4*)lo)[i] = ll;
}

// ---------------------------------------------------------------------------
// Transpose + split: in [K,N] fp32 row-major -> hi/lo [N,K] bf16
// ---------------------------------------------------------------------------
__global__ void tsplit_k(const float* __restrict__ in, int Kdim, int Ndim,
                         __nv_bfloat16* __restrict__ hi,
                         __nv_bfloat16* __restrict__ lo)
{
    __shared__ float t[32][33];
    const int n0 = blockIdx.x * 32, k0 = blockIdx.y * 32;
    const int tx = threadIdx.x, ty = threadIdx.y;  // block (32, 8)
    for (int i = ty; i < 32; i += 8)
        t[i][tx] = in[(size_t)(k0 + i) * Ndim + n0 + tx];
    __syncthreads();
    for (int i = ty; i < 32; i += 8) {
        float v = t[tx][i];  // = in[k0+tx][n0+i]
        __nv_bfloat16 h = __float2bfloat16(v);
        hi[(size_t)(n0 + i) * Kdim + k0 + tx] = h;
        lo[(size_t)(n0 + i) * Kdim + k0 + tx] =
            __float2bfloat16(v - __bfloat162float(h));
    }
}

__global__ void padzero_k(__nv_bfloat16* __restrict__ a,
                          __nv_bfloat16* __restrict__ b, int n)
{
    int i = blockIdx.x * blockDim.x + threadIdx.x;
    if (i < n) { a[i] = __float2bfloat16(0.0f); b[i] = __float2bfloat16(0.0f); }
}

// Reduce KSPLIT partial C buffers into one (float4 vectorized).
// Optional fused split: for rows of ld `ldc`, columns < split_ncol are also
// emitted as packed bf16 hi/lo [row, split_ncol] (used for delta GEMM input).
__global__ void reduce_part_k(const float* __restrict__ part,
                              float* __restrict__ out, int n4, size_t zstride4,
                              int ldc, int split_ncol,
                              __nv_bfloat16* __restrict__ shi,
                              __nv_bfloat16* __restrict__ slo)
{
    int i = blockIdx.x * blockDim.x + threadIdx.x;
    if (i >= n4) return;
    float4 a = ((const float4*)part)[i];
#pragma unroll
    for (int z = 1; z < KSPLIT; z++) {
        float4 b = ((const float4*)part)[(size_t)z * zstride4 + i];
        a.x += b.x; a.y += b.y; a.z += b.z; a.w += b.w;
    }
    ((float4*)out)[i] = a;
    if (shi) {
        const int per_row = ldc / 4;
        const int row = i / per_row;
        const int c4 = (i % per_row) * 4;
        if (c4 < split_ncol) {
            __nv_bfloat16 h0 = __float2bfloat16(a.x);
            __nv_bfloat16 h1 = __float2bfloat16(a.y);
            __nv_bfloat16 h2 = __float2bfloat16(a.z);
            __nv_bfloat16 h3 = __float2bfloat16(a.w);
            ushort4 hh, ll;
            hh.x = __bfloat16_as_ushort(h0); hh.y = __bfloat16_as_ushort(h1);
            hh.z = __bfloat16_as_ushort(h2); hh.w = __bfloat16_as_ushort(h3);
            ll.x = __bfloat16_as_ushort(__float2bfloat16(a.x - __bfloat162float(h0)));
            ll.y = __bfloat16_as_ushort(__float2bfloat16(a.y - __bfloat162float(h1)));
            ll.z = __bfloat16_as_ushort(__float2bfloat16(a.z - __bfloat162float(h2)));
            ll.w = __bfloat16_as_ushort(__float2bfloat16(a.w - __bfloat162float(h3)));
            const int oi = (row * split_ncol + c4) / 4;
            ((ushort4*)shi)[oi] = hh;
            ((ushort4*)slo)[oi] = ll;
        }
    }
}

// ---------------------------------------------------------------------------
// mma.sync split-bf16 GEMM (round-10 winning mainloop, FROZEN).
// Guarded prologue (small nch) and optional softplus(x+bias[col]) epilogue.
// ---------------------------------------------------------------------------
constexpr int BK = 32;
constexpr int ROWB = 80;
constexpr int TILEB = 128 * ROWB;
constexpr int STAGEB = 4 * TILEB;
constexpr int NSTAGE = 3;
constexpr int SMEM_MMA = NSTAGE * STAGEB;  // 122880 B

__global__ void __launch_bounds__(256, 1) mma_gemm_k(
    const __nv_bfloat16* __restrict__ Ah, const __nv_bfloat16* __restrict__ Al,
    const __nv_bfloat16* __restrict__ Bh, const __nv_bfloat16* __restrict__ Bl,
    float* __restrict__ C, int lda, int ldc, int kspan, size_t zstride,
    const float* __restrict__ bias)
{
    extern __shared__ __align__(16) char smem[];
    const uint32_t sb = (uint32_t)__cvta_generic_to_shared(smem);
    const int tid = threadIdx.x;
    const int wid = tid >> 5, lid = tid & 31;
    const int warpM = wid & 3, warpN = wid >> 2;   // 4 x 2

    const int rowBase = blockIdx.y * 128;
    const int colBase = blockIdx.x * 128;
    const int kstart = blockIdx.z * kspan;
    const int nch = kspan / BK;
    C += (size_t)blockIdx.z * zstride;

    float acc[2][8][4];
#pragma unroll
    for (int i = 0; i < 2; i++)
#pragma unroll
        for (int j = 0; j < 8; j++)
#pragma unroll
            for (int q = 0; q < 4; q++) acc[i][j][q] = 0.0f;

    auto load_chunk = [&](int c, int buf) {
        const uint32_t st = sb + buf * STAGEB;
        const int k0 = kstart + c * BK;
#pragma unroll
        for (int ch = tid; ch < 512; ch += 256) {
            const int row = ch >> 2;
            const int kc = ch & 3;
            const uint32_t so = row * ROWB + kc * 16;
            const size_t go = (size_t)k0 + kc * 8;
            cp_async16(st + so,             Ah + (size_t)(rowBase + row) * lda + go);
            cp_async16(st + TILEB + so,     Al + (size_t)(rowBase + row) * lda + go);
            cp_async16(st + 2 * TILEB + so, Bh + (size_t)(colBase + row) * lda + go);
            cp_async16(st + 3 * TILEB + so, Bl + (size_t)(colBase + row) * lda + go);
        }
        cp_commit();
    };

    // guarded depth-3 prologue (nch may be as small as 2)
    load_chunk(0, 0);
    if (1 < nch) load_chunk(1, 1); else cp_commit();
    if (2 < nch) load_chunk(2, 2); else cp_commit();

    const int lr = lid & 15;
    const int lc16 = (lid >> 4) * 16;

    for (int c = 0; c < nch; c++) {
        const int buf = c % NSTAGE;
        cp_wait<NSTAGE - 1>();
        __syncthreads();

        const uint32_t st = sb + buf * STAGEB;
#pragma unroll
        for (int kk = 0; kk < 2; kk++) {
            const uint32_t kb = kk * 32;
            uint32_t ah[2][4], al[2][4];
#pragma unroll
            for (int mf = 0; mf < 2; mf++) {
                const uint32_t a =
                    st + (warpM * 32 + mf * 16 + lr) * ROWB + kb + lc16;
                ldsm_x4(ah[mf], a);
                ldsm_x4(al[mf], a + TILEB);
            }
            uint32_t bh[8][2], bl[8][2];
#pragma unroll
            for (int np = 0; np < 4; np++) {
                const uint32_t a =
                    st + 2 * TILEB + (warpN * 64 + np * 16 + lr) * ROWB + kb + lc16;
                uint32_t t[4];
                ldsm_x4(t, a);
                bh[2 * np][0] = t[0]; bh[2 * np + 1][0] = t[1];
                bh[2 * np][1] = t[2]; bh[2 * np + 1][1] = t[3];
                ldsm_x4(t, a + TILEB);
                bl[2 * np][0] = t[0]; bl[2 * np + 1][0] = t[1];
                bl[2 * np][1] = t[2]; bl[2 * np + 1][1] = t[3];
            }
            // interleaved MMA order (proven fastest)
#pragma unroll
            for (int mf = 0; mf < 2; mf++)
#pragma unroll
                for (int nf = 0; nf < 8; nf++) {
                    mma16816(acc[mf][nf], ah[mf], bh[nf][0], bh[nf][1]);
                    mma16816(acc[mf][nf], ah[mf], bl[nf][0], bl[nf][1]);
                    mma16816(acc[mf][nf], al[mf], bh[nf][0], bh[nf][1]);
                }
        }
        __syncthreads();
        if (c + NSTAGE < nch) load_chunk(c + NSTAGE, buf);
        else cp_commit();
    }

    const int r = lid >> 2, cq = (lid & 3) * 2;
    float* Cw = C + (size_t)(rowBase + warpM * 32) * ldc + colBase + warpN * 64;
    const int cBase = colBase + warpN * 64;
#pragma unroll
    for (int mf = 0; mf < 2; mf++)
#pragma unroll
        for (int nf = 0; nf < 8; nf++) {
            float v0 = acc[mf][nf][0], v1 = acc[mf][nf][1];
            float v2 = acc[mf][nf][2], v3 = acc[mf][nf][3];
            if (bias) {
                const float b0 = bias[cBase + nf * 8 + cq];
                const float b1 = bias[cBase + nf * 8 + cq + 1];
                v0 = softplusf(v0 + b0); v1 = softplusf(v1 + b1);
                v2 = softplusf(v2 + b0); v3 = softplusf(v3 + b1);
            }
            *(float2*)&Cw[(size_t)(mf * 16 + r) * ldc + nf * 8 + cq] =
                make_float2(v0, v1);
            *(float2*)&Cw[(size_t)(mf * 16 + r + 8) * ldc + nf * 8 + cq] =
                make_float2(v2, v3);
        }
}

// ---------------------------------------------------------------------------
// Depthwise causal conv (width 4) + SiLU + fused bf16 split.
// Each thread handles 4 consecutive l for one channel d: 7 loads -> 4 outputs.
// ---------------------------------------------------------------------------
__global__ void conv_silu_k(const float* __restrict__ xz,
                            const float* __restrict__ w,
                            const float* __restrict__ bias,
                            float* __restrict__ xc,
                            __nv_bfloat16* __restrict__ xch,
                            __nv_bfloat16* __restrict__ xcl)
{
    const int idx = blockIdx.x * blockDim.x + threadIdx.x;  // over (M/4)*DI
    if (idx >= (M / 4) * DI) return;
    const int d = idx % DI;
    const int m4 = idx / DI;
    const int m0 = m4 * 4;
    const int l0 = m0 % Lsz;   // multiple of 4

    const float w0 = w[d * 4 + 0], w1 = w[d * 4 + 1],
                w2 = w[d * 4 + 2], w3 = w[d * 4 + 3];
    const float bz = bias[d];

    float xv[7];
#pragma unroll
    for (int j = 0; j < 7; j++) {
        const int mm = m0 - 3 + j;
        xv[j] = (l0 + j >= 3) ? xz[(size_t)mm * XZ_N + d] : 0.0f;
    }
#pragma unroll
    for (int i = 0; i < 4; i++) {
        float acc = bz;
        acc = fmaf(w0, xv[i + 0], acc);
        acc = fmaf(w1, xv[i + 1], acc);
        acc = fmaf(w2, xv[i + 2], acc);
        acc = fmaf(w3, xv[i + 3], acc);
        const float v = acc * sigmoidf_fast(acc);
        const size_t o = (size_t)(m0 + i) * DI + d;
        xc[o] = v;
        const __nv_bfloat16 h = __float2bfloat16(v);
        xch[o] = h;
        xcl[o] = __float2bfloat16(v - __bfloat162float(h));
    }
}

// ---------------------------------------------------------------------------
// Parallel selective scan, register-state version (round-10 winning config).
// ---------------------------------------------------------------------------
__global__ void __launch_bounds__(256) scan1_k(
    const float* __restrict__ delta_, const float* __restrict__ xc,
    const float* __restrict__ dbcp, const float* __restrict__ A_log,
    float* __restrict__ yz, float* __restrict__ hend, float* __restrict__ ptot)
{
    __shared__ float sB[LC][DS];
    __shared__ float sC[LC][DS];
    const int tid = threadIdx.x;
    const int blk = blockIdx.x;
    const int c = blk & (NC - 1);
    const int t = blk >> 6;            // 0..15
    const int b = t >> 3;
    const int d = ((t & 7) << 8) + tid;
    const size_t mbase = (size_t)b * Lsz + c * LC;

    for (int i = tid; i < LC * 32; i += 256) {
        const int row = i >> 5, col = i & 31;
        const float v = dbcp[(mbase + row) * DBC_LD + DR + col];
        if (col < DS) sB[row][col] = v;
        else          sC[row][col - DS] = v;
    }
    float Aneg[DS];
#pragma unroll
    for (int s = 0; s < DS; s++) Aneg[s] = -__expf(A_log[d * DS + s]);
    __syncthreads();

    float h[DS], p[DS];
#pragma unroll
    for (int s = 0; s < DS; s++) { h[s] = 0.0f; p[s] = 1.0f; }

#pragma unroll 2
    for (int k = 0; k < LC; k++) {
        const size_t m = mbase + k;
        const float delta = delta_[m * DI + d];
        const float du = delta * xc[m * DI + d];
        float y = 0.0f;
#pragma unroll
        for (int s = 0; s < DS; s++) {
            const float a = __expf(delta * Aneg[s]);
            p[s] *= a;
            h[s] = fmaf(a, h[s], du * sB[k][s]);
            y = fmaf(h[s], sC[k][s], y);
        }
        yz[m * DI + d] = y;
    }
    const size_t idx = (size_t)c * (NCH * DS) + ((size_t)(b * DI + d)) * DS;
#pragma unroll
    for (int s = 0; s < DS; s++) { hend[idx + s] = h[s]; ptot[idx + s] = p[s]; }
}

__global__ void __launch_bounds__(256) combine_k(
    const float* __restrict__ hend, const float* __restrict__ ptot,
    float* __restrict__ hin)
{
    const int i = blockIdx.x * 256 + threadIdx.x;  // NCH*DS = 65536
    float H = 0.0f;
#pragma unroll
    for (int c = 0; c < NC; c++) {
        const size_t idx = (size_t)c * (NCH * DS) + i;
        hin[idx] = H;
        H = fmaf(ptot[idx], H, hend[idx]);
    }
}

__global__ void __launch_bounds__(256) scan2_k(
    const float* __restrict__ delta_, const float* __restrict__ xc,
    const float* __restrict__ dbcp, const float* __restrict__ xz,
    const float* __restrict__ A_log, const float* __restrict__ D_skip,
    const float* __restrict__ hin_, const float* __restrict__ yz,
    __nv_bfloat16* __restrict__ yzh, __nv_bfloat16* __restrict__ yzl)
{
    __shared__ float sC[LC][DS];
    const int tid = threadIdx.x;
    const int blk = blockIdx.x;
    const int c = blk & (NC - 1);
    const int t = blk >> 6;
    const int b = t >> 3;
    const int d = ((t & 7) << 8) + tid;
    const size_t mbase = (size_t)b * Lsz + c * LC;

    for (int i = tid; i < LC * DS; i += 256) {
        const int row = i >> 4, col = i & 15;
        sC[row][col] = dbcp[(mbase + row) * DBC_LD + DR + DS + col];
    }
    float Aneg[DS];
#pragma unroll
    for (int s = 0; s < DS; s++) Aneg[s] = -__expf(A_log[d * DS + s]);
    const float dskip = D_skip[d];

    float hin[DS], p[DS];
    const size_t hidx = (size_t)c * (NCH * DS) + ((size_t)(b * DI + d)) * DS;
#pragma unroll
    for (int s = 0; s < DS; s++) { hin[s] = hin_[hidx + s]; p[s] = 1.0f; }
    __syncthreads();

#pragma unroll 2
    for (int k = 0; k < LC; k++) {
        const size_t m = mbase + k;
        const float delta = delta_[m * DI + d];
        float yc = 0.0f;
#pragma unroll
        for (int s = 0; s < DS; s++) {
            const float a = __expf(delta * Aneg[s]);
            p[s] *= a;
            yc = fmaf(hin[s] * p[s], sC[k][s], yc);
        }
        const float u = xc[m * DI + d];
        const float z = xz[m * XZ_N + DI + d];
        const float y = yz[m * DI + d] + yc + u * dskip;
        const float val = y * (z * sigmoidf_fast(z));
        const __nv_bfloat16 hh = __float2bfloat16(val);
        yzh[m * DI + d] = hh;
        yzl[m * DI + d] = __float2bfloat16(val - __bfloat162float(hh));
    }
}

// ---------------------------------------------------------------------------
extern "C" void kernel_launch(void* const* d_in, const int* in_sizes, int n_in,
                              void* d_out, int out_size)
{
    const float* x      = (const float*)d_in[0];
    const float* W_in   = (const float*)d_in[1];
    const float* conv_w = (const float*)d_in[2];
    const float* conv_b = (const float*)d_in[3];
    const float* W_xprj = (const float*)d_in[4];
    const float* W_dt   = (const float*)d_in[5];
    const float* b_dt   = (const float*)d_in[6];
    const float* A_log  = (const float*)d_in[7];
    const float* D_skip = (const float*)d_in[8];
    const float* W_out  = (const float*)d_in[9];
    float* out = (float*)d_out;

    float *xz, *xc, *dbcp, *dbcpart, *outpart, *delta, *yz, *hend, *ptot, *hin;
    cudaGetSymbolAddress((void**)&xz, g_xz);
    cudaGetSymbolAddress((void**)&xc, g_xc);
    cudaGetSymbolAddress((void**)&dbcp, g_dbcp);
    cudaGetSymbolAddress((void**)&dbcpart, g_dbcpart);
    cudaGetSymbolAddress((void**)&outpart, g_outpart);
    cudaGetSymbolAddress((void**)&delta, g_delta);
    cudaGetSymbolAddress((void**)&yz, g_yz);
    cudaGetSymbolAddress((void**)&hend, g_hend);
    cudaGetSymbolAddress((void**)&ptot, g_ptot);
    cudaGetSymbolAddress((void**)&hin, g_hin);
    __nv_bfloat16 *xh, *xl, *winh, *winl, *xch, *xcl, *wxh, *wxl,
                  *dth, *dtl, *wdth, *wdtl, *yzh, *yzl, *wouth, *woutl;
    cudaGetSymbolAddress((void**)&xh, g_xh);
    cudaGetSymbolAddress((void**)&xl, g_xl);
    cudaGetSymbolAddress((void**)&winh, g_winh);
    cudaGetSymbolAddress((void**)&winl, g_winl);
    cudaGetSymbolAddress((void**)&xch, g_xch);
    cudaGetSymbolAddress((void**)&xcl, g_xcl);
    cudaGetSymbolAddress((void**)&wxh, g_wxh);
    cudaGetSymbolAddress((void**)&wxl, g_wxl);
    cudaGetSymbolAddress((void**)&dth, g_dth);
    cudaGetSymbolAddress((void**)&dtl, g_dtl);
    cudaGetSymbolAddress((void**)&wdth, g_wdth);
    cudaGetSymbolAddress((void**)&wdtl, g_wdtl);
    cudaGetSymbolAddress((void**)&yzh, g_yzh);
    cudaGetSymbolAddress((void**)&yzl, g_yzl);
    cudaGetSymbolAddress((void**)&wouth, g_wouth);
    cudaGetSymbolAddress((void**)&woutl, g_woutl);

    cudaFuncSetAttribute(mma_gemm_k, cudaFuncAttributeMaxDynamicSharedMemorySize,
                         SMEM_MMA);

    // 0) operand prep
    split_k<<<(M * DM / 4 + 255) / 256, 256>>>(x, xh, xl, M * DM / 4);
    {   // W_in [DM, XZ_N] -> [XZ_N, DM]
        dim3 grid(XZ_N / 32, DM / 32);
        tsplit_k<<<grid, dim3(32, 8)>>>(W_in, DM, XZ_N, winh, winl);
    }
    {   // W_out [DI, DM] -> [DM, DI]
        dim3 grid(DM / 32, DI / 32);
        tsplit_k<<<grid, dim3(32, 8)>>>(W_out, DI, DM, wouth, woutl);
    }
    {   // W_xproj [DI, 96] -> [96, DI], pad rows 96..127 with zeros
        dim3 grid(96 / 32, DI / 32);
        tsplit_k<<<grid, dim3(32, 8)>>>(W_xprj, DI, 96, wxh, wxl);
        padzero_k<<<(32 * DI + 255) / 256, 256>>>(wxh + (size_t)96 * DI,
                                                  wxl + (size_t)96 * DI, 32 * DI);
    }
    {   // W_dt [DR, DI] -> [DI, DR]
        dim3 grid(DI / 32, DR / 32);
        tsplit_k<<<grid, dim3(32, 8)>>>(W_dt, DR, DI, wdth, wdtl);
    }

    // 1) xz = x @ W_in
    {
        dim3 grid(XZ_N / 128, M / 128, 1);
        mma_gemm_k<<<grid, 256, SMEM_MMA>>>(xh, xl, winh, winl, xz, DM, XZ_N,
                                            DM, 0, nullptr);
    }
    // 2) conv + silu (+ bf16 split), 4 rows per thread
    conv_silu_k<<<((M / 4) * DI + 255) / 256, 256>>>(xz, conv_w, conv_b,
                                                     xc, xch, xcl);
    // 3) dbc = xc @ W_xproj (mma, padded N=128, split-K x4)
    //    reduce also emits bf16 split of cols 0:64 (delta GEMM input)
    {
        dim3 grid(1, M / 128, KSPLIT);
        mma_gemm_k<<<grid, 256, SMEM_MMA>>>(xch, xcl, wxh, wxl, dbcpart, DI,
                                            DBC_LD, DI / KSPLIT,
                                            (size_t)M * DBC_LD, nullptr);
        reduce_part_k<<<(M * DBC_LD / 4 + 255) / 256, 256>>>(
            dbcpart, dbcp, M * DBC_LD / 4, (size_t)M * DBC_LD / 4,
            DBC_LD, DR, dth, dtl);
    }
    // 4) delta = softplus(dt_lo @ W_dt + b_dt) (mma, K=64, fused epilogue)
    {
        dim3 grid(DI / 128, M / 128, 1);
        mma_gemm_k<<<grid, 256, SMEM_MMA>>>(dth, dtl, wdth, wdtl, delta, DR, DI,
                                            DR, 0, b_dt);
    }
    // 5) parallel selective scan (register-state version)
    {
        const int blocks = Bsz * (DI / 256) * NC;  // 1024
        scan1_k<<<blocks, 256>>>(delta, xc, dbcp, A_log, yz, hend, ptot);
        combine_k<<<(NCH * DS) / 256, 256>>>(hend, ptot, hin);
        scan2_k<<<blocks, 256>>>(delta, xc, dbcp, xz, A_log, D_skip, hin,
                                 yz, yzh, yzl);
    }
    // 6) out = yz @ W_out (mma, split-K x4 to kill wave quantization)
    {
        dim3 grid(DM / 128, M / 128, KSPLIT);
        mma_gemm_k<<<grid, 256, SMEM_MMA>>>(yzh, yzl, wouth, woutl, outpart,
                                            DI, DM, DI / KSPLIT,
                                            (size_t)M * DM, nullptr);
        reduce_part_k<<<(M * DM / 4 + 255) / 256, 256>>>(
            outpart, out, M * DM / 4, (size_t)M * DM / 4,
            DM, 0, nullptr, nullptr);
    }
}

// round 14
// speedup vs baseline: 1.6962x; 1.0949x over previous
#include <cuda_runtime.h>
#include <cuda_bf16.h>
#include <math.h>
#include <stdint.h>

// Problem constants
constexpr int Bsz = 2, Lsz = 2048, DM = 1024, DI = 2048, DS = 16, DR = 64;
constexpr int M = Bsz * Lsz;          // 4096
constexpr int XZ_N = 2 * DI;          // 4096
constexpr int DBC_LD = 128;           // padded dbc row stride (real cols: 96)
constexpr int NC = 64, LC = 32;       // scan chunking: 64 chunks x 32 steps
constexpr int NCH = Bsz * DI;         // 4096 channels
constexpr int KSPLIT = 4;             // split-K factor (dbc and out GEMMs)

// fp32 scratch
__device__ float g_xz[(size_t)M * XZ_N];
__device__ float g_xc[(size_t)M * DI];
__device__ float g_dbcp[(size_t)M * DBC_LD];
__device__ float g_dbcpart[(size_t)KSPLIT * M * DBC_LD];
__device__ float g_outpart[(size_t)KSPLIT * M * DM];
__device__ float g_delta[(size_t)M * DI];
// scan chunk state
__device__ float g_hend[(size_t)NC * NCH * DS];
__device__ float g_ptot[(size_t)NC * NCH * DS];
__device__ float g_hin [(size_t)NC * NCH * DS];
// bf16 split operands (A row-major [rows,K]; B stored K-major as [N,K])
__device__ __nv_bfloat16 g_xh[(size_t)M * DM],      g_xl[(size_t)M * DM];
__device__ __nv_bfloat16 g_winh[(size_t)XZ_N * DM], g_winl[(size_t)XZ_N * DM];
__device__ __nv_bfloat16 g_xch[(size_t)M * DI],     g_xcl[(size_t)M * DI];
__device__ __nv_bfloat16 g_wxh[(size_t)DBC_LD * DI], g_wxl[(size_t)DBC_LD * DI];
__device__ __nv_bfloat16 g_dth[(size_t)M * DR],     g_dtl[(size_t)M * DR];
__device__ __nv_bfloat16 g_wdth[(size_t)DI * DR],   g_wdtl[(size_t)DI * DR];
__device__ __nv_bfloat16 g_yzh[(size_t)M * DI],     g_yzl[(size_t)M * DI];
__device__ __nv_bfloat16 g_wouth[(size_t)DM * DI],  g_woutl[(size_t)DM * DI];

__device__ __forceinline__ float sigmoidf_fast(float x) {
    return 1.0f / (1.0f + __expf(-x));
}
__device__ __forceinline__ float softplusf(float x) {
    return (x > 20.0f) ? x : log1pf(expf(x));
}

// ---------------------------------------------------------------------------
// PTX helpers (portable sm_80+ PTX only)
// ---------------------------------------------------------------------------
__device__ __forceinline__ void cp_async16(uint32_t dst, const void* src) {
    asm volatile("cp.async.cg.shared.global [%0], [%1], 16;"
                 :: "r"(dst), "l"(src) : "memory");
}
__device__ __forceinline__ void cp_commit() {
    asm volatile("cp.async.commit_group;" ::: "memory");
}
template <int N>
__device__ __forceinline__ void cp_wait() {
    asm volatile("cp.async.wait_group %0;" :: "n"(N) : "memory");
}
__device__ __forceinline__ void ldsm_x4(uint32_t* r, uint32_t addr) {
    asm volatile("ldmatrix.sync.aligned.m8n8.x4.shared.b16 {%0,%1,%2,%3}, [%4];"
                 : "=r"(r[0]), "=r"(r[1]), "=r"(r[2]), "=r"(r[3]) : "r"(addr));
}
__device__ __forceinline__ void mma16816(float* c, const uint32_t* a,
                                         uint32_t b0, uint32_t b1) {
    asm volatile(
        "mma.sync.aligned.m16n8k16.row.col.f32.bf16.bf16.f32 "
        "{%0,%1,%2,%3}, {%4,%5,%6,%7}, {%8,%9}, {%0,%1,%2,%3};"
        : "+f"(c[0]), "+f"(c[1]), "+f"(c[2]), "+f"(c[3])
        : "r"(a[0]), "r"(a[1]), "r"(a[2]), "r"(a[3]), "r"(b0), "r"(b1));
}

// ---------------------------------------------------------------------------
// Split fp32 -> (hi, lo) bf16, same layout (used for x)
// ---------------------------------------------------------------------------
__global__ void split_k(const float* __restrict__ in,
                        __nv_bfloat16* __restrict__ hi,
                        __nv_bfloat16* __restrict__ lo, int n4)
{
    int i = blockIdx.x * blockDim.x + threadIdx.x;
    if (i >= n4) return;
    float4 v = ((const float4*)in)[i];
    __nv_bfloat16 h0 = __float2bfloat16(v.x);
    __nv_bfloat16 h1 = __float2bfloat16(v.y);
    __nv_bfloat16 h2 = __float2bfloat16(v.z);
    __nv_bfloat16 h3 = __float2bfloat16(v.w);
    ushort4 hh, ll;
    hh.x = __bfloat16_as_ushort(h0); hh.y = __bfloat16_as_ushort(h1);
    hh.z = __bfloat16_as_ushort(h2); hh.w = __bfloat16_as_ushort(h3);
    ll.x = __bfloat16_as_ushort(__float2bfloat16(v.x - __bfloat162float(h0)));
    ll.y = __bfloat16_as_ushort(__float2bfloat16(v.y - __bfloat162float(h1)));
    ll.z = __bfloat16_as_ushort(__float2bfloat16(v.z - __bfloat162float(h2)));
    ll.w = __bfloat16_as_ushort(__float2bfloat16(v.w - __bfloat162float(h3)));
    ((ushort4*)hi)[i] = hh;
    ((ushort4*)lo)[i] = ll;
}

// ---------------------------------------------------------------------------
// Merged weight prep: transpose+split all 4 weight matrices in one launch.
// Sections (32x32 tiles, block (32,8)):
//   0: W_in   [1024,4096] -> [4096,1024]   128x32  = 4096 tiles
//   1: W_out  [2048,1024] -> [1024,2048]    32x64  = 2048 tiles
//   2: W_xprj [2048,  96] -> [ 128,2048]     4x64  =  256 tiles (zero-pad rows)
//   3: W_dt   [  64,2048] -> [2048,  64]    64x 2  =  128 tiles
// ---------------------------------------------------------------------------
__global__ void prep_w_k(const float* __restrict__ Win,
                         const float* __restrict__ Wout,
                         const float* __restrict__ Wxp,
                         const float* __restrict__ Wdt,
                         __nv_bfloat16* __restrict__ winh, __nv_bfloat16* __restrict__ winl,
                         __nv_bfloat16* __restrict__ wouth, __nv_bfloat16* __restrict__ woutl,
                         __nv_bfloat16* __restrict__ wxh, __nv_bfloat16* __restrict__ wxl,
                         __nv_bfloat16* __restrict__ wdth, __nv_bfloat16* __restrict__ wdtl)
{
    const int t = blockIdx.x;
    const float* src; int K, Nsrc, tilesN, local;
    __nv_bfloat16 *hi, *lo;
    if (t < 4096)      { src = Win;  K = 1024; Nsrc = 4096; hi = winh;  lo = winl;  tilesN = 128; local = t; }
    else if (t < 6144) { src = Wout; K = 2048; Nsrc = 1024; hi = wouth; lo = woutl; tilesN = 32;  local = t - 4096; }
    else if (t < 6400) { src = Wxp;  K = 2048; Nsrc = 96;   hi = wxh;   lo = wxl;   tilesN = 4;   local = t - 6144; }
    else               { src = Wdt;  K = 64;   Nsrc = 2048; hi = wdth;  lo = wdtl;  tilesN = 64;  local = t - 6400; }
    const int nt = local % tilesN, kt = local / tilesN;
    const int n0 = nt * 32, k0 = kt * 32;

    __shared__ float sm[32][33];
    const int tx = threadIdx.x, ty = threadIdx.y;
    for (int i = ty; i < 32; i += 8) {
        float v = 0.0f;
        if (n0 + tx < Nsrc) v = src[(size_t)(k0 + i) * Nsrc + n0 + tx];
        sm[i][tx] = v;
    }
    __syncthreads();
    for (int i = ty; i < 32; i += 8) {
        const float v = sm[tx][i];   // = src[k0+tx][n0+i] (or 0 pad)
        const __nv_bfloat16 h = __float2bfloat16(v);
        hi[(size_t)(n0 + i) * K + k0 + tx] = h;
        lo[(size_t)(n0 + i) * K + k0 + tx] =
            __float2bfloat16(v - __bfloat162float(h));
    }
}

// Reduce KSPLIT partial C buffers into one (float4 vectorized).
// Optional fused split of leading split_ncol columns (delta GEMM input).
__global__ void reduce_part_k(const float* __restrict__ part,
                              float* __restrict__ out, int n4, size_t zstride4,
                              int ldc, int split_ncol,
                              __nv_bfloat16* __restrict__ shi,
                              __nv_bfloat16* __restrict__ slo)
{
    int i = blockIdx.x * blockDim.x + threadIdx.x;
    if (i >= n4) return;
    float4 a = ((const float4*)part)[i];
#pragma unroll
    for (int z = 1; z < KSPLIT; z++) {
        float4 b = ((const float4*)part)[(size_t)z * zstride4 + i];
        a.x += b.x; a.y += b.y; a.z += b.z; a.w += b.w;
    }
    ((float4*)out)[i] = a;
    if (shi) {
        const int per_row = ldc / 4;
        const int row = i / per_row;
        const int c4 = (i % per_row) * 4;
        if (c4 < split_ncol) {
            __nv_bfloat16 h0 = __float2bfloat16(a.x);
            __nv_bfloat16 h1 = __float2bfloat16(a.y);
            __nv_bfloat16 h2 = __float2bfloat16(a.z);
            __nv_bfloat16 h3 = __float2bfloat16(a.w);
            ushort4 hh, ll;
            hh.x = __bfloat16_as_ushort(h0); hh.y = __bfloat16_as_ushort(h1);
            hh.z = __bfloat16_as_ushort(h2); hh.w = __bfloat16_as_ushort(h3);
            ll.x = __bfloat16_as_ushort(__float2bfloat16(a.x - __bfloat162float(h0)));
            ll.y = __bfloat16_as_ushort(__float2bfloat16(a.y - __bfloat162float(h1)));
            ll.z = __bfloat16_as_ushort(__float2bfloat16(a.z - __bfloat162float(h2)));
            ll.w = __bfloat16_as_ushort(__float2bfloat16(a.w - __bfloat162float(h3)));
            const int oi = (row * split_ncol + c4) / 4;
            ((ushort4*)shi)[oi] = hh;
            ((ushort4*)slo)[oi] = ll;
        }
    }
}

// ---------------------------------------------------------------------------
// mma.sync split-bf16 GEMM (round-10 winning mainloop, FROZEN).
// Guarded prologue (small nch) and optional softplus(x+bias[col]) epilogue.
// ---------------------------------------------------------------------------
constexpr int BK = 32;
constexpr int ROWB = 80;
constexpr int TILEB = 128 * ROWB;
constexpr int STAGEB = 4 * TILEB;
constexpr int NSTAGE = 3;
constexpr int SMEM_MMA = NSTAGE * STAGEB;  // 122880 B

__global__ void __launch_bounds__(256, 1) mma_gemm_k(
    const __nv_bfloat16* __restrict__ Ah, const __nv_bfloat16* __restrict__ Al,
    const __nv_bfloat16* __restrict__ Bh, const __nv_bfloat16* __restrict__ Bl,
    float* __restrict__ C, int lda, int ldc, int kspan, size_t zstride,
    const float* __restrict__ bias)
{
    extern __shared__ __align__(16) char smem[];
    const uint32_t sb = (uint32_t)__cvta_generic_to_shared(smem);
    const int tid = threadIdx.x;
    const int wid = tid >> 5, lid = tid & 31;
    const int warpM = wid & 3, warpN = wid >> 2;   // 4 x 2

    const int rowBase = blockIdx.y * 128;
    const int colBase = blockIdx.x * 128;
    const int kstart = blockIdx.z * kspan;
    const int nch = kspan / BK;
    C += (size_t)blockIdx.z * zstride;

    float acc[2][8][4];
#pragma unroll
    for (int i = 0; i < 2; i++)
#pragma unroll
        for (int j = 0; j < 8; j++)
#pragma unroll
            for (int q = 0; q < 4; q++) acc[i][j][q] = 0.0f;

    auto load_chunk = [&](int c, int buf) {
        const uint32_t st = sb + buf * STAGEB;
        const int k0 = kstart + c * BK;
#pragma unroll
        for (int ch = tid; ch < 512; ch += 256) {
            const int row = ch >> 2;
            const int kc = ch & 3;
            const uint32_t so = row * ROWB + kc * 16;
            const size_t go = (size_t)k0 + kc * 8;
            cp_async16(st + so,             Ah + (size_t)(rowBase + row) * lda + go);
            cp_async16(st + TILEB + so,     Al + (size_t)(rowBase + row) * lda + go);
            cp_async16(st + 2 * TILEB + so, Bh + (size_t)(colBase + row) * lda + go);
            cp_async16(st + 3 * TILEB + so, Bl + (size_t)(colBase + row) * lda + go);
        }
        cp_commit();
    };

    // guarded depth-3 prologue (nch may be as small as 2)
    load_chunk(0, 0);
    if (1 < nch) load_chunk(1, 1); else cp_commit();
    if (2 < nch) load_chunk(2, 2); else cp_commit();

    const int lr = lid & 15;
    const int lc16 = (lid >> 4) * 16;

    for (int c = 0; c < nch; c++) {
        const int buf = c % NSTAGE;
        cp_wait<NSTAGE - 1>();
        __syncthreads();

        const uint32_t st = sb + buf * STAGEB;
#pragma unroll
        for (int kk = 0; kk < 2; kk++) {
            const uint32_t kb = kk * 32;
            uint32_t ah[2][4], al[2][4];
#pragma unroll
            for (int mf = 0; mf < 2; mf++) {
                const uint32_t a =
                    st + (warpM * 32 + mf * 16 + lr) * ROWB + kb + lc16;
                ldsm_x4(ah[mf], a);
                ldsm_x4(al[mf], a + TILEB);
            }
            uint32_t bh[8][2], bl[8][2];
#pragma unroll
            for (int np = 0; np < 4; np++) {
                const uint32_t a =
                    st + 2 * TILEB + (warpN * 64 + np * 16 + lr) * ROWB + kb + lc16;
                uint32_t t[4];
                ldsm_x4(t, a);
                bh[2 * np][0] = t[0]; bh[2 * np + 1][0] = t[1];
                bh[2 * np][1] = t[2]; bh[2 * np + 1][1] = t[3];
                ldsm_x4(t, a + TILEB);
                bl[2 * np][0] = t[0]; bl[2 * np + 1][0] = t[1];
                bl[2 * np][1] = t[2]; bl[2 * np + 1][1] = t[3];
            }
            // interleaved MMA order (proven fastest)
#pragma unroll
            for (int mf = 0; mf < 2; mf++)
#pragma unroll
                for (int nf = 0; nf < 8; nf++) {
                    mma16816(acc[mf][nf], ah[mf], bh[nf][0], bh[nf][1]);
                    mma16816(acc[mf][nf], ah[mf], bl[nf][0], bl[nf][1]);
                    mma16816(acc[mf][nf], al[mf], bh[nf][0], bh[nf][1]);
                }
        }
        __syncthreads();
        if (c + NSTAGE < nch) load_chunk(c + NSTAGE, buf);
        else cp_commit();
    }

    const int r = lid >> 2, cq = (lid & 3) * 2;
    float* Cw = C + (size_t)(rowBase + warpM * 32) * ldc + colBase + warpN * 64;
    const int cBase = colBase + warpN * 64;
#pragma unroll
    for (int mf = 0; mf < 2; mf++)
#pragma unroll
        for (int nf = 0; nf < 8; nf++) {
            float v0 = acc[mf][nf][0], v1 = acc[mf][nf][1];
            float v2 = acc[mf][nf][2], v3 = acc[mf][nf][3];
            if (bias) {
                const float b0 = bias[cBase + nf * 8 + cq];
                const float b1 = bias[cBase + nf * 8 + cq + 1];
                v0 = softplusf(v0 + b0); v1 = softplusf(v1 + b1);
                v2 = softplusf(v2 + b0); v3 = softplusf(v3 + b1);
            }
            *(float2*)&Cw[(size_t)(mf * 16 + r) * ldc + nf * 8 + cq] =
                make_float2(v0, v1);
            *(float2*)&Cw[(size_t)(mf * 16 + r + 8) * ldc + nf * 8 + cq] =
                make_float2(v2, v3);
        }
}

// ---------------------------------------------------------------------------
// Depthwise causal conv (width 4) + SiLU + fused bf16 split.
// Each thread handles 4 consecutive l for one channel d: 7 loads -> 4 outputs.
// ---------------------------------------------------------------------------
__global__ void conv_silu_k(const float* __restrict__ xz,
                            const float* __restrict__ w,
                            const float* __restrict__ bias,
                            float* __restrict__ xc,
                            __nv_bfloat16* __restrict__ xch,
                            __nv_bfloat16* __restrict__ xcl)
{
    const int idx = blockIdx.x * blockDim.x + threadIdx.x;  // over (M/4)*DI
    if (idx >= (M / 4) * DI) return;
    const int d = idx % DI;
    const int m4 = idx / DI;
    const int m0 = m4 * 4;
    const int l0 = m0 % Lsz;   // multiple of 4

    const float w0 = w[d * 4 + 0], w1 = w[d * 4 + 1],
                w2 = w[d * 4 + 2], w3 = w[d * 4 + 3];
    const float bz = bias[d];

    float xv[7];
#pragma unroll
    for (int j = 0; j < 7; j++) {
        const int mm = m0 - 3 + j;
        xv[j] = (l0 + j >= 3) ? xz[(size_t)mm * XZ_N + d] : 0.0f;
    }
#pragma unroll
    for (int i = 0; i < 4; i++) {
        float acc = bz;
        acc = fmaf(w0, xv[i + 0], acc);
        acc = fmaf(w1, xv[i + 1], acc);
        acc = fmaf(w2, xv[i + 2], acc);
        acc = fmaf(w3, xv[i + 3], acc);
        const float v = acc * sigmoidf_fast(acc);
        const size_t o = (size_t)(m0 + i) * DI + d;
        xc[o] = v;
        const __nv_bfloat16 h = __float2bfloat16(v);
        xch[o] = h;
        xcl[o] = __float2bfloat16(v - __bfloat162float(h));
    }
}

// ---------------------------------------------------------------------------
// Parallel selective scan, simplified:
// scan1 computes only (hend, ptot) per chunk; combine stitches chunk inits;
// scan2 re-runs the SAME recurrence with h initialized to hin, producing the
// final y directly (h_total = h_local + hin*p satisfies the same recurrence).
// exp via exp2f with log2(e) folded into the per-state constant.
// ---------------------------------------------------------------------------
constexpr float L2E = 1.4426950408889634f;

__global__ void __launch_bounds__(256) scan1_k(
    const float* __restrict__ delta_, const float* __restrict__ xc,
    const float* __restrict__ dbcp, const float* __restrict__ A_log,
    float* __restrict__ hend, float* __restrict__ ptot)
{
    __shared__ float sB[LC][DS];
    const int tid = threadIdx.x;
    const int blk = blockIdx.x;
    const int c = blk & (NC - 1);
    const int t = blk >> 6;            // 0..15
    const int b = t >> 3;
    const int d = ((t & 7) << 8) + tid;
    const size_t mbase = (size_t)b * Lsz + c * LC;

    for (int i = tid; i < LC * DS; i += 256) {
        const int row = i >> 4, col = i & 15;
        sB[row][col] = dbcp[(mbase + row) * DBC_LD + DR + col];
    }
    float An2[DS];
#pragma unroll
    for (int s = 0; s < DS; s++) An2[s] = -__expf(A_log[d * DS + s]) * L2E;
    __syncthreads();

    float h[DS], p[DS];
#pragma unroll
    for (int s = 0; s < DS; s++) { h[s] = 0.0f; p[s] = 1.0f; }

#pragma unroll 2
    for (int k = 0; k < LC; k++) {
        const size_t m = mbase + k;
        const float delta = delta_[m * DI + d];
        const float du = delta * xc[m * DI + d];
#pragma unroll
        for (int s = 0; s < DS; s++) {
            const float a = exp2f(delta * An2[s]);
            p[s] *= a;
            h[s] = fmaf(a, h[s], du * sB[k][s]);
        }
    }
    const size_t idx = (size_t)c * (NCH * DS) + ((size_t)(b * DI + d)) * DS;
#pragma unroll
    for (int s = 0; s < DS; s++) { hend[idx + s] = h[s]; ptot[idx + s] = p[s]; }
}

__global__ void __launch_bounds__(256) combine_k(
    const float* __restrict__ hend, const float* __restrict__ ptot,
    float* __restrict__ hin)
{
    const int i = blockIdx.x * 256 + threadIdx.x;  // NCH*DS = 65536
    float H = 0.0f;
#pragma unroll
    for (int c = 0; c < NC; c++) {
        const size_t idx = (size_t)c * (NCH * DS) + i;
        hin[idx] = H;
        H = fmaf(ptot[idx], H, hend[idx]);
    }
}

__global__ void __launch_bounds__(256) scan2_k(
    const float* __restrict__ delta_, const float* __restrict__ xc,
    const float* __restrict__ dbcp, const float* __restrict__ xz,
    const float* __restrict__ A_log, const float* __restrict__ D_skip,
    const float* __restrict__ hin_,
    __nv_bfloat16* __restrict__ yzh, __nv_bfloat16* __restrict__ yzl)
{
    __shared__ float sB[LC][DS];
    __shared__ float sC[LC][DS];
    const int tid = threadIdx.x;
    const int blk = blockIdx.x;
    const int c = blk & (NC - 1);
    const int t = blk >> 6;
    const int b = t >> 3;
    const int d = ((t & 7) << 8) + tid;
    const size_t mbase = (size_t)b * Lsz + c * LC;

    for (int i = tid; i < LC * 32; i += 256) {
        const int row = i >> 5, col = i & 31;
        const float v = dbcp[(mbase + row) * DBC_LD + DR + col];
        if (col < DS) sB[row][col] = v;
        else          sC[row][col - DS] = v;
    }
    float An2[DS];
#pragma unroll
    for (int s = 0; s < DS; s++) An2[s] = -__expf(A_log[d * DS + s]) * L2E;
    const float dskip = D_skip[d];

    float h[DS];
    const size_t hidx = (size_t)c * (NCH * DS) + ((size_t)(b * DI + d)) * DS;
#pragma unroll
    for (int s = 0; s < DS; s++) h[s] = hin_[hidx + s];
    __syncthreads();

#pragma unroll 2
    for (int k = 0; k < LC; k++) {
        const size_t m = mbase + k;
        const float delta = delta_[m * DI + d];
        const float u = xc[m * DI + d];
        const float du = delta * u;
        float y = 0.0f;
#pragma unroll
        for (int s = 0; s < DS; s++) {
            const float a = exp2f(delta * An2[s]);
            h[s] = fmaf(a, h[s], du * sB[k][s]);
            y = fmaf(h[s], sC[k][s], y);
        }
        const float z = xz[m * XZ_N + DI + d];
        const float val = (y + u * dskip) * (z * sigmoidf_fast(z));
        const __nv_bfloat16 hh = __float2bfloat16(val);
        yzh[m * DI + d] = hh;
        yzl[m * DI + d] = __float2bfloat16(val - __bfloat162float(hh));
    }
}

// ---------------------------------------------------------------------------
extern "C" void kernel_launch(void* const* d_in, const int* in_sizes, int n_in,
                              void* d_out, int out_size)
{
    const float* x      = (const float*)d_in[0];
    const float* W_in   = (const float*)d_in[1];
    const float* conv_w = (const float*)d_in[2];
    const float* conv_b = (const float*)d_in[3];
    const float* W_xprj = (const float*)d_in[4];
    const float* W_dt   = (const float*)d_in[5];
    const float* b_dt   = (const float*)d_in[6];
    const float* A_log  = (const float*)d_in[7];
    const float* D_skip = (const float*)d_in[8];
    const float* W_out  = (const float*)d_in[9];
    float* out = (float*)d_out;

    float *xz, *xc, *dbcp, *dbcpart, *outpart, *delta, *hend, *ptot, *hin;
    cudaGetSymbolAddress((void**)&xz, g_xz);
    cudaGetSymbolAddress((void**)&xc, g_xc);
    cudaGetSymbolAddress((void**)&dbcp, g_dbcp);
    cudaGetSymbolAddress((void**)&dbcpart, g_dbcpart);
    cudaGetSymbolAddress((void**)&outpart, g_outpart);
    cudaGetSymbolAddress((void**)&delta, g_delta);
    cudaGetSymbolAddress((void**)&hend, g_hend);
    cudaGetSymbolAddress((void**)&ptot, g_ptot);
    cudaGetSymbolAddress((void**)&hin, g_hin);
    __nv_bfloat16 *xh, *xl, *winh, *winl, *xch, *xcl, *wxh, *wxl,
                  *dth, *dtl, *wdth, *wdtl, *yzh, *yzl, *wouth, *woutl;
    cudaGetSymbolAddress((void**)&xh, g_xh);
    cudaGetSymbolAddress((void**)&xl, g_xl);
    cudaGetSymbolAddress((void**)&winh, g_winh);
    cudaGetSymbolAddress((void**)&winl, g_winl);
    cudaGetSymbolAddress((void**)&xch, g_xch);
    cudaGetSymbolAddress((void**)&xcl, g_xcl);
    cudaGetSymbolAddress((void**)&wxh, g_wxh);
    cudaGetSymbolAddress((void**)&wxl, g_wxl);
    cudaGetSymbolAddress((void**)&dth, g_dth);
    cudaGetSymbolAddress((void**)&dtl, g_dtl);
    cudaGetSymbolAddress((void**)&wdth, g_wdth);
    cudaGetSymbolAddress((void**)&wdtl, g_wdtl);
    cudaGetSymbolAddress((void**)&yzh, g_yzh);
    cudaGetSymbolAddress((void**)&yzl, g_yzl);
    cudaGetSymbolAddress((void**)&wouth, g_wouth);
    cudaGetSymbolAddress((void**)&woutl, g_woutl);

    cudaFuncSetAttribute(mma_gemm_k, cudaFuncAttributeMaxDynamicSharedMemorySize,
                         SMEM_MMA);

    // 0) operand prep: x split + all weight transposes/splits (one launch each)
    split_k<<<(M * DM / 4 + 255) / 256, 256>>>(x, xh, xl, M * DM / 4);
    prep_w_k<<<6528, dim3(32, 8)>>>(W_in, W_out, W_xprj, W_dt,
                                    winh, winl, wouth, woutl,
                                    wxh, wxl, wdth, wdtl);

    // 1) xz = x @ W_in
    {
        dim3 grid(XZ_N / 128, M / 128, 1);
        mma_gemm_k<<<grid, 256, SMEM_MMA>>>(xh, xl, winh, winl, xz, DM, XZ_N,
                                            DM, 0, nullptr);
    }
    // 2) conv + silu (+ bf16 split), 4 rows per thread
    conv_silu_k<<<((M / 4) * DI + 255) / 256, 256>>>(xz, conv_w, conv_b,
                                                     xc, xch, xcl);
    // 3) dbc = xc @ W_xproj (mma, padded N=128, split-K x4)
    //    reduce also emits bf16 split of cols 0:64 (delta GEMM input)
    {
        dim3 grid(1, M / 128, KSPLIT);
        mma_gemm_k<<<grid, 256, SMEM_MMA>>>(xch, xcl, wxh, wxl, dbcpart, DI,
                                            DBC_LD, DI / KSPLIT,
                                            (size_t)M * DBC_LD, nullptr);
        reduce_part_k<<<(M * DBC_LD / 4 + 255) / 256, 256>>>(
            dbcpart, dbcp, M * DBC_LD / 4, (size_t)M * DBC_LD / 4,
            DBC_LD, DR, dth, dtl);
    }
    // 4) delta = softplus(dt_lo @ W_dt + b_dt) (mma, K=64, fused epilogue)
    {
        dim3 grid(DI / 128, M / 128, 1);
        mma_gemm_k<<<grid, 256, SMEM_MMA>>>(dth, dtl, wdth, wdtl, delta, DR, DI,
                                            DR, 0, b_dt);
    }
    // 5) parallel selective scan (recurrence-reinit version)
    {
        const int blocks = Bsz * (DI / 256) * NC;  // 1024
        scan1_k<<<blocks, 256>>>(delta, xc, dbcp, A_log, hend, ptot);
        combine_k<<<(NCH * DS) / 256, 256>>>(hend, ptot, hin);
        scan2_k<<<blocks, 256>>>(delta, xc, dbcp, xz, A_log, D_skip, hin,
                                 yzh, yzl);
    }
    // 6) out = yz @ W_out (mma, split-K x4 to kill wave quantization)
    {
        dim3 grid(DM / 128, M / 128, KSPLIT);
        mma_gemm_k<<<grid, 256, SMEM_MMA>>>(yzh, yzl, wouth, woutl, outpart,
                                            DI, DM, DI / KSPLIT,
                                            (size_t)M * DM, nullptr);
        reduce_part_k<<<(M * DM / 4 + 255) / 256, 256>>>(
            outpart, out, M * DM / 4, (size_t)M * DM / 4,
            DM, 0, nullptr, nullptr);
    }
}

// round 15
// speedup vs baseline: 1.7183x; 1.0131x over previous
#include <cuda_runtime.h>
#include <cuda_bf16.h>
#include <math.h>
#include <stdint.h>

// Problem constants
constexpr int Bsz = 2, Lsz = 2048, DM = 1024, DI = 2048, DS = 16, DR = 64;
constexpr int M = Bsz * Lsz;          // 4096
constexpr int XZ_N = 2 * DI;          // 4096
constexpr int DBC_LD = 128;           // padded dbc row stride (real cols: 96)
constexpr int NC = 64, LC = 32;       // scan chunking: 64 chunks x 32 steps
constexpr int NCH = Bsz * DI;         // 4096 channels
constexpr int KSPLIT = 4;             // split-K factor (dbc and out GEMMs)

// fp32 scratch
__device__ float g_xz[(size_t)M * XZ_N];
__device__ float g_xc[(size_t)M * DI];
__device__ float g_dbcp[(size_t)M * DBC_LD];
__device__ float g_dbcpart[(size_t)KSPLIT * M * DBC_LD];
__device__ float g_outpart[(size_t)KSPLIT * M * DM];
__device__ float g_delta[(size_t)M * DI];
// scan chunk state
__device__ float g_hend[(size_t)NC * NCH * DS];
__device__ float g_ptot[(size_t)NC * NCH * DS];
__device__ float g_hin [(size_t)NC * NCH * DS];
// bf16 split operands (A row-major [rows,K]; B stored K-major as [N,K])
__device__ __nv_bfloat16 g_xh[(size_t)M * DM],      g_xl[(size_t)M * DM];
__device__ __nv_bfloat16 g_winh[(size_t)XZ_N * DM], g_winl[(size_t)XZ_N * DM];
__device__ __nv_bfloat16 g_xch[(size_t)M * DI],     g_xcl[(size_t)M * DI];
__device__ __nv_bfloat16 g_wxh[(size_t)DBC_LD * DI], g_wxl[(size_t)DBC_LD * DI];
__device__ __nv_bfloat16 g_dth[(size_t)M * DR],     g_dtl[(size_t)M * DR];
__device__ __nv_bfloat16 g_wdth[(size_t)DI * DR],   g_wdtl[(size_t)DI * DR];
__device__ __nv_bfloat16 g_yzh[(size_t)M * DI],     g_yzl[(size_t)M * DI];
__device__ __nv_bfloat16 g_wouth[(size_t)DM * DI],  g_woutl[(size_t)DM * DI];

__device__ __forceinline__ float sigmoidf_fast(float x) {
    return 1.0f / (1.0f + __expf(-x));
}
__device__ __forceinline__ float softplusf(float x) {
    return (x > 20.0f) ? x : log1pf(expf(x));
}
__device__ __forceinline__ float ex2f(float x) {
    float r;
    asm("ex2.approx.f32 %0, %1;" : "=f"(r) : "f"(x));
    return r;
}

// ---------------------------------------------------------------------------
// PTX helpers (portable sm_80+ PTX only)
// ---------------------------------------------------------------------------
__device__ __forceinline__ void cp_async16(uint32_t dst, const void* src) {
    asm volatile("cp.async.cg.shared.global [%0], [%1], 16;"
                 :: "r"(dst), "l"(src) : "memory");
}
__device__ __forceinline__ void cp_commit() {
    asm volatile("cp.async.commit_group;" ::: "memory");
}
template <int N>
__device__ __forceinline__ void cp_wait() {
    asm volatile("cp.async.wait_group %0;" :: "n"(N) : "memory");
}
__device__ __forceinline__ void ldsm_x4(uint32_t* r, uint32_t addr) {
    asm volatile("ldmatrix.sync.aligned.m8n8.x4.shared.b16 {%0,%1,%2,%3}, [%4];"
                 : "=r"(r[0]), "=r"(r[1]), "=r"(r[2]), "=r"(r[3]) : "r"(addr));
}
__device__ __forceinline__ void mma16816(float* c, const uint32_t* a,
                                         uint32_t b0, uint32_t b1) {
    asm volatile(
        "mma.sync.aligned.m16n8k16.row.col.f32.bf16.bf16.f32 "
        "{%0,%1,%2,%3}, {%4,%5,%6,%7}, {%8,%9}, {%0,%1,%2,%3};"
        : "+f"(c[0]), "+f"(c[1]), "+f"(c[2]), "+f"(c[3])
        : "r"(a[0]), "r"(a[1]), "r"(a[2]), "r"(a[3]), "r"(b0), "r"(b1));
}

// ---------------------------------------------------------------------------
// Split fp32 -> (hi, lo) bf16, same layout (used for x)
// ---------------------------------------------------------------------------
__global__ void split_k(const float* __restrict__ in,
                        __nv_bfloat16* __restrict__ hi,
                        __nv_bfloat16* __restrict__ lo, int n4)
{
    int i = blockIdx.x * blockDim.x + threadIdx.x;
    if (i >= n4) return;
    float4 v = ((const float4*)in)[i];
    __nv_bfloat16 h0 = __float2bfloat16(v.x);
    __nv_bfloat16 h1 = __float2bfloat16(v.y);
    __nv_bfloat16 h2 = __float2bfloat16(v.z);
    __nv_bfloat16 h3 = __float2bfloat16(v.w);
    ushort4 hh, ll;
    hh.x = __bfloat16_as_ushort(h0); hh.y = __bfloat16_as_ushort(h1);
    hh.z = __bfloat16_as_ushort(h2); hh.w = __bfloat16_as_ushort(h3);
    ll.x = __bfloat16_as_ushort(__float2bfloat16(v.x - __bfloat162float(h0)));
    ll.y = __bfloat16_as_ushort(__float2bfloat16(v.y - __bfloat162float(h1)));
    ll.z = __bfloat16_as_ushort(__float2bfloat16(v.z - __bfloat162float(h2)));
    ll.w = __bfloat16_as_ushort(__float2bfloat16(v.w - __bfloat162float(h3)));
    ((ushort4*)hi)[i] = hh;
    ((ushort4*)lo)[i] = ll;
}

// ---------------------------------------------------------------------------
// Merged weight prep: transpose+split all 4 weight matrices in one launch.
// ---------------------------------------------------------------------------
__global__ void prep_w_k(const float* __restrict__ Win,
                         const float* __restrict__ Wout,
                         const float* __restrict__ Wxp,
                         const float* __restrict__ Wdt,
                         __nv_bfloat16* __restrict__ winh, __nv_bfloat16* __restrict__ winl,
                         __nv_bfloat16* __restrict__ wouth, __nv_bfloat16* __restrict__ woutl,
                         __nv_bfloat16* __restrict__ wxh, __nv_bfloat16* __restrict__ wxl,
                         __nv_bfloat16* __restrict__ wdth, __nv_bfloat16* __restrict__ wdtl)
{
    const int t = blockIdx.x;
    const float* src; int K, Nsrc, tilesN, local;
    __nv_bfloat16 *hi, *lo;
    if (t < 4096)      { src = Win;  K = 1024; Nsrc = 4096; hi = winh;  lo = winl;  tilesN = 128; local = t; }
    else if (t < 6144) { src = Wout; K = 2048; Nsrc = 1024; hi = wouth; lo = woutl; tilesN = 32;  local = t - 4096; }
    else if (t < 6400) { src = Wxp;  K = 2048; Nsrc = 96;   hi = wxh;   lo = wxl;   tilesN = 4;   local = t - 6144; }
    else               { src = Wdt;  K = 64;   Nsrc = 2048; hi = wdth;  lo = wdtl;  tilesN = 64;  local = t - 6400; }
    const int nt = local % tilesN, kt = local / tilesN;
    const int n0 = nt * 32, k0 = kt * 32;

    __shared__ float sm[32][33];
    const int tx = threadIdx.x, ty = threadIdx.y;
    for (int i = ty; i < 32; i += 8) {
        float v = 0.0f;
        if (n0 + tx < Nsrc) v = src[(size_t)(k0 + i) * Nsrc + n0 + tx];
        sm[i][tx] = v;
    }
    __syncthreads();
    for (int i = ty; i < 32; i += 8) {
        const float v = sm[tx][i];
        const __nv_bfloat16 h = __float2bfloat16(v);
        hi[(size_t)(n0 + i) * K + k0 + tx] = h;
        lo[(size_t)(n0 + i) * K + k0 + tx] =
            __float2bfloat16(v - __bfloat162float(h));
    }
}

// Reduce KSPLIT partial C buffers into one (float4 vectorized).
// Optional fused split of leading split_ncol columns (delta GEMM input).
__global__ void reduce_part_k(const float* __restrict__ part,
                              float* __restrict__ out, int n4, size_t zstride4,
                              int ldc, int split_ncol,
                              __nv_bfloat16* __restrict__ shi,
                              __nv_bfloat16* __restrict__ slo)
{
    int i = blockIdx.x * blockDim.x + threadIdx.x;
    if (i >= n4) return;
    float4 a = ((const float4*)part)[i];
#pragma unroll
    for (int z = 1; z < KSPLIT; z++) {
        float4 b = ((const float4*)part)[(size_t)z * zstride4 + i];
        a.x += b.x; a.y += b.y; a.z += b.z; a.w += b.w;
    }
    ((float4*)out)[i] = a;
    if (shi) {
        const int per_row = ldc / 4;
        const int row = i / per_row;
        const int c4 = (i % per_row) * 4;
        if (c4 < split_ncol) {
            __nv_bfloat16 h0 = __float2bfloat16(a.x);
            __nv_bfloat16 h1 = __float2bfloat16(a.y);
            __nv_bfloat16 h2 = __float2bfloat16(a.z);
            __nv_bfloat16 h3 = __float2bfloat16(a.w);
            ushort4 hh, ll;
            hh.x = __bfloat16_as_ushort(h0); hh.y = __bfloat16_as_ushort(h1);
            hh.z = __bfloat16_as_ushort(h2); hh.w = __bfloat16_as_ushort(h3);
            ll.x = __bfloat16_as_ushort(__float2bfloat16(a.x - __bfloat162float(h0)));
            ll.y = __bfloat16_as_ushort(__float2bfloat16(a.y - __bfloat162float(h1)));
            ll.z = __bfloat16_as_ushort(__float2bfloat16(a.z - __bfloat162float(h2)));
            ll.w = __bfloat16_as_ushort(__float2bfloat16(a.w - __bfloat162float(h3)));
            const int oi = (row * split_ncol + c4) / 4;
            ((ushort4*)shi)[oi] = hh;
            ((ushort4*)slo)[oi] = ll;
        }
    }
}

// ---------------------------------------------------------------------------
// mma.sync split-bf16 GEMM (round-10 winning mainloop, FROZEN).
// ---------------------------------------------------------------------------
constexpr int BK = 32;
constexpr int ROWB = 80;
constexpr int TILEB = 128 * ROWB;
constexpr int STAGEB = 4 * TILEB;
constexpr int NSTAGE = 3;
constexpr int SMEM_MMA = NSTAGE * STAGEB;  // 122880 B

__global__ void __launch_bounds__(256, 1) mma_gemm_k(
    const __nv_bfloat16* __restrict__ Ah, const __nv_bfloat16* __restrict__ Al,
    const __nv_bfloat16* __restrict__ Bh, const __nv_bfloat16* __restrict__ Bl,
    float* __restrict__ C, int lda, int ldc, int kspan, size_t zstride,
    const float* __restrict__ bias)
{
    extern __shared__ __align__(16) char smem[];
    const uint32_t sb = (uint32_t)__cvta_generic_to_shared(smem);
    const int tid = threadIdx.x;
    const int wid = tid >> 5, lid = tid & 31;
    const int warpM = wid & 3, warpN = wid >> 2;   // 4 x 2

    const int rowBase = blockIdx.y * 128;
    const int colBase = blockIdx.x * 128;
    const int kstart = blockIdx.z * kspan;
    const int nch = kspan / BK;
    C += (size_t)blockIdx.z * zstride;

    float acc[2][8][4];
#pragma unroll
    for (int i = 0; i < 2; i++)
#pragma unroll
        for (int j = 0; j < 8; j++)
#pragma unroll
            for (int q = 0; q < 4; q++) acc[i][j][q] = 0.0f;

    auto load_chunk = [&](int c, int buf) {
        const uint32_t st = sb + buf * STAGEB;
        const int k0 = kstart + c * BK;
#pragma unroll
        for (int ch = tid; ch < 512; ch += 256) {
            const int row = ch >> 2;
            const int kc = ch & 3;
            const uint32_t so = row * ROWB + kc * 16;
            const size_t go = (size_t)k0 + kc * 8;
            cp_async16(st + so,             Ah + (size_t)(rowBase + row) * lda + go);
            cp_async16(st + TILEB + so,     Al + (size_t)(rowBase + row) * lda + go);
            cp_async16(st + 2 * TILEB + so, Bh + (size_t)(colBase + row) * lda + go);
            cp_async16(st + 3 * TILEB + so, Bl + (size_t)(colBase + row) * lda + go);
        }
        cp_commit();
    };

    load_chunk(0, 0);
    if (1 < nch) load_chunk(1, 1); else cp_commit();
    if (2 < nch) load_chunk(2, 2); else cp_commit();

    const int lr = lid & 15;
    const int lc16 = (lid >> 4) * 16;

    for (int c = 0; c < nch; c++) {
        const int buf = c % NSTAGE;
        cp_wait<NSTAGE - 1>();
        __syncthreads();

        const uint32_t st = sb + buf * STAGEB;
#pragma unroll
        for (int kk = 0; kk < 2; kk++) {
            const uint32_t kb = kk * 32;
            uint32_t ah[2][4], al[2][4];
#pragma unroll
            for (int mf = 0; mf < 2; mf++) {
                const uint32_t a =
                    st + (warpM * 32 + mf * 16 + lr) * ROWB + kb + lc16;
                ldsm_x4(ah[mf], a);
                ldsm_x4(al[mf], a + TILEB);
            }
            uint32_t bh[8][2], bl[8][2];
#pragma unroll
            for (int np = 0; np < 4; np++) {
                const uint32_t a =
                    st + 2 * TILEB + (warpN * 64 + np * 16 + lr) * ROWB + kb + lc16;
                uint32_t t[4];
                ldsm_x4(t, a);
                bh[2 * np][0] = t[0]; bh[2 * np + 1][0] = t[1];
                bh[2 * np][1] = t[2]; bh[2 * np + 1][1] = t[3];
                ldsm_x4(t, a + TILEB);
                bl[2 * np][0] = t[0]; bl[2 * np + 1][0] = t[1];
                bl[2 * np][1] = t[2]; bl[2 * np + 1][1] = t[3];
            }
            // interleaved MMA order (proven fastest)
#pragma unroll
            for (int mf = 0; mf < 2; mf++)
#pragma unroll
                for (int nf = 0; nf < 8; nf++) {
                    mma16816(acc[mf][nf], ah[mf], bh[nf][0], bh[nf][1]);
                    mma16816(acc[mf][nf], ah[mf], bl[nf][0], bl[nf][1]);
                    mma16816(acc[mf][nf], al[mf], bh[nf][0], bh[nf][1]);
                }
        }
        __syncthreads();
        if (c + NSTAGE < nch) load_chunk(c + NSTAGE, buf);
        else cp_commit();
    }

    const int r = lid >> 2, cq = (lid & 3) * 2;
    float* Cw = C + (size_t)(rowBase + warpM * 32) * ldc + colBase + warpN * 64;
    const int cBase = colBase + warpN * 64;
#pragma unroll
    for (int mf = 0; mf < 2; mf++)
#pragma unroll
        for (int nf = 0; nf < 8; nf++) {
            float v0 = acc[mf][nf][0], v1 = acc[mf][nf][1];
            float v2 = acc[mf][nf][2], v3 = acc[mf][nf][3];
            if (bias) {
                const float b0 = bias[cBase + nf * 8 + cq];
                const float b1 = bias[cBase + nf * 8 + cq + 1];
                v0 = softplusf(v0 + b0); v1 = softplusf(v1 + b1);
                v2 = softplusf(v2 + b0); v3 = softplusf(v3 + b1);
            }
            *(float2*)&Cw[(size_t)(mf * 16 + r) * ldc + nf * 8 + cq] =
                make_float2(v0, v1);
            *(float2*)&Cw[(size_t)(mf * 16 + r + 8) * ldc + nf * 8 + cq] =
                make_float2(v2, v3);
        }
}

// ---------------------------------------------------------------------------
// Depthwise causal conv (width 4) + SiLU + fused bf16 split.
// Each thread: 4 consecutive l x 2 consecutive channels (float2 vectorized).
// ---------------------------------------------------------------------------
__global__ void conv_silu_k(const float* __restrict__ xz,
                            const float* __restrict__ w,
                            const float* __restrict__ bias,
                            float* __restrict__ xc,
                            __nv_bfloat16* __restrict__ xch,
                            __nv_bfloat16* __restrict__ xcl)
{
    const int idx = blockIdx.x * blockDim.x + threadIdx.x;  // (M/4)*(DI/2)
    if (idx >= (M / 4) * (DI / 2)) return;
    const int d0 = (idx % (DI / 2)) * 2;
    const int m0 = (idx / (DI / 2)) * 4;
    const int l0 = m0 % Lsz;   // multiple of 4

    const float4 wa = *(const float4*)&w[d0 * 4];        // w[d0][0..3]
    const float4 wb = *(const float4*)&w[d0 * 4 + 4];    // w[d0+1][0..3]
    const float2 bz = *(const float2*)&bias[d0];

    float2 xv[7];
#pragma unroll
    for (int j = 0; j < 7; j++) {
        const int mm = m0 - 3 + j;
        if (l0 + j >= 3) xv[j] = *(const float2*)&xz[(size_t)mm * XZ_N + d0];
        else             xv[j] = make_float2(0.0f, 0.0f);
    }
#pragma unroll
    for (int i = 0; i < 4; i++) {
        float a0 = bz.x, a1 = bz.y;
        a0 = fmaf(wa.x, xv[i + 0].x, a0); a1 = fmaf(wb.x, xv[i + 0].y, a1);
        a0 = fmaf(wa.y, xv[i + 1].x, a0); a1 = fmaf(wb.y, xv[i + 1].y, a1);
        a0 = fmaf(wa.z, xv[i + 2].x, a0); a1 = fmaf(wb.z, xv[i + 2].y, a1);
        a0 = fmaf(wa.w, xv[i + 3].x, a0); a1 = fmaf(wb.w, xv[i + 3].y, a1);
        const float v0 = a0 * sigmoidf_fast(a0);
        const float v1 = a1 * sigmoidf_fast(a1);
        const size_t o = (size_t)(m0 + i) * DI + d0;
        *(float2*)&xc[o] = make_float2(v0, v1);
        const __nv_bfloat16 h0 = __float2bfloat16(v0);
        const __nv_bfloat16 h1 = __float2bfloat16(v1);
        uint32_t hp = (uint32_t)__bfloat16_as_ushort(h0) |
                      ((uint32_t)__bfloat16_as_ushort(h1) << 16);
        uint32_t lp = (uint32_t)__bfloat16_as_ushort(
                          __float2bfloat16(v0 - __bfloat162float(h0))) |
                      ((uint32_t)__bfloat16_as_ushort(
                          __float2bfloat16(v1 - __bfloat162float(h1))) << 16);
        *(uint32_t*)&xch[o] = hp;
        *(uint32_t*)&xcl[o] = lp;
    }
}

// ---------------------------------------------------------------------------
// Parallel selective scan (recurrence-reinit), ex2.approx, ptot via delta-sum.
// ---------------------------------------------------------------------------
constexpr float L2E = 1.4426950408889634f;

__global__ void __launch_bounds__(256) scan1_k(
    const float* __restrict__ delta_, const float* __restrict__ xc,
    const float* __restrict__ dbcp, const float* __restrict__ A_log,
    float* __restrict__ hend, float* __restrict__ ptot)
{
    __shared__ float sB[LC][DS];
    const int tid = threadIdx.x;
    const int blk = blockIdx.x;
    const int c = blk & (NC - 1);
    const int t = blk >> 6;            // 0..15
    const int b = t >> 3;
    const int d = ((t & 7) << 8) + tid;
    const size_t mbase = (size_t)b * Lsz + c * LC;

    for (int i = tid; i < LC * DS; i += 256) {
        const int row = i >> 4, col = i & 15;
        sB[row][col] = dbcp[(mbase + row) * DBC_LD + DR + col];
    }
    float An2[DS];
#pragma unroll
    for (int s = 0; s < DS; s++) An2[s] = -__expf(A_log[d * DS + s]) * L2E;
    __syncthreads();

    float h[DS];
#pragma unroll
    for (int s = 0; s < DS; s++) h[s] = 0.0f;
    float sd = 0.0f;

#pragma unroll 2
    for (int k = 0; k < LC; k++) {
        const size_t m = mbase + k;
        const float delta = delta_[m * DI + d];
        const float du = delta * xc[m * DI + d];
        sd += delta;
#pragma unroll
        for (int s = 0; s < DS; s++) {
            const float a = ex2f(delta * An2[s]);
            h[s] = fmaf(a, h[s], du * sB[k][s]);
        }
    }
    const size_t idx = (size_t)c * (NCH * DS) + ((size_t)(b * DI + d)) * DS;
#pragma unroll
    for (int s = 0; s < DS; s++) {
        hend[idx + s] = h[s];
        ptot[idx + s] = ex2f(sd * An2[s]);
    }
}

__global__ void __launch_bounds__(256) combine_k(
    const float* __restrict__ hend, const float* __restrict__ ptot,
    float* __restrict__ hin)
{
    const int i = blockIdx.x * 256 + threadIdx.x;  // NCH*DS = 65536
    float H = 0.0f;
#pragma unroll
    for (int c = 0; c < NC; c++) {
        const size_t idx = (size_t)c * (NCH * DS) + i;
        hin[idx] = H;
        H = fmaf(ptot[idx], H, hend[idx]);
    }
}

__global__ void __launch_bounds__(256) scan2_k(
    const float* __restrict__ delta_, const float* __restrict__ xc,
    const float* __restrict__ dbcp, const float* __restrict__ xz,
    const float* __restrict__ A_log, const float* __restrict__ D_skip,
    const float* __restrict__ hin_,
    __nv_bfloat16* __restrict__ yzh, __nv_bfloat16* __restrict__ yzl)
{
    __shared__ float sB[LC][DS];
    __shared__ float sC[LC][DS];
    const int tid = threadIdx.x;
    const int blk = blockIdx.x;
    const int c = blk & (NC - 1);
    const int t = blk >> 6;
    const int b = t >> 3;
    const int d = ((t & 7) << 8) + tid;
    const size_t mbase = (size_t)b * Lsz + c * LC;

    for (int i = tid; i < LC * 32; i += 256) {
        const int row = i >> 5, col = i & 31;
        const float v = dbcp[(mbase + row) * DBC_LD + DR + col];
        if (col < DS) sB[row][col] = v;
        else          sC[row][col - DS] = v;
    }
    float An2[DS];
#pragma unroll
    for (int s = 0; s < DS; s++) An2[s] = -__expf(A_log[d * DS + s]) * L2E;
    const float dskip = D_skip[d];

    float h[DS];
    const size_t hidx = (size_t)c * (NCH * DS) + ((size_t)(b * DI + d)) * DS;
#pragma unroll
    for (int s = 0; s < DS; s++) h[s] = hin_[hidx + s];
    __syncthreads();

#pragma unroll 2
    for (int k = 0; k < LC; k++) {
        const size_t m = mbase + k;
        const float delta = delta_[m * DI + d];
        const float u = xc[m * DI + d];
        const float du = delta * u;
        float y = 0.0f;
#pragma unroll
        for (int s = 0; s < DS; s++) {
            const float a = ex2f(delta * An2[s]);
            h[s] = fmaf(a, h[s], du * sB[k][s]);
            y = fmaf(h[s], sC[k][s], y);
        }
        const float z = xz[m * XZ_N + DI + d];
        const float val = (y + u * dskip) * (z * sigmoidf_fast(z));
        const __nv_bfloat16 hh = __float2bfloat16(val);
        yzh[m * DI + d] = hh;
        yzl[m * DI + d] = __float2bfloat16(val - __bfloat162float(hh));
    }
}

// ---------------------------------------------------------------------------
extern "C" void kernel_launch(void* const* d_in, const int* in_sizes, int n_in,
                              void* d_out, int out_size)
{
    const float* x      = (const float*)d_in[0];
    const float* W_in   = (const float*)d_in[1];
    const float* conv_w = (const float*)d_in[2];
    const float* conv_b = (const float*)d_in[3];
    const float* W_xprj = (const float*)d_in[4];
    const float* W_dt   = (const float*)d_in[5];
    const float* b_dt   = (const float*)d_in[6];
    const float* A_log  = (const float*)d_in[7];
    const float* D_skip = (const float*)d_in[8];
    const float* W_out  = (const float*)d_in[9];
    float* out = (float*)d_out;

    float *xz, *xc, *dbcp, *dbcpart, *outpart, *delta, *hend, *ptot, *hin;
    cudaGetSymbolAddress((void**)&xz, g_xz);
    cudaGetSymbolAddress((void**)&xc, g_xc);
    cudaGetSymbolAddress((void**)&dbcp, g_dbcp);
    cudaGetSymbolAddress((void**)&dbcpart, g_dbcpart);
    cudaGetSymbolAddress((void**)&outpart, g_outpart);
    cudaGetSymbolAddress((void**)&delta, g_delta);
    cudaGetSymbolAddress((void**)&hend, g_hend);
    cudaGetSymbolAddress((void**)&ptot, g_ptot);
    cudaGetSymbolAddress((void**)&hin, g_hin);
    __nv_bfloat16 *xh, *xl, *winh, *winl, *xch, *xcl, *wxh, *wxl,
                  *dth, *dtl, *wdth, *wdtl, *yzh, *yzl, *wouth, *woutl;
    cudaGetSymbolAddress((void**)&xh, g_xh);
    cudaGetSymbolAddress((void**)&xl, g_xl);
    cudaGetSymbolAddress((void**)&winh, g_winh);
    cudaGetSymbolAddress((void**)&winl, g_winl);
    cudaGetSymbolAddress((void**)&xch, g_xch);
    cudaGetSymbolAddress((void**)&xcl, g_xcl);
    cudaGetSymbolAddress((void**)&wxh, g_wxh);
    cudaGetSymbolAddress((void**)&wxl, g_wxl);
    cudaGetSymbolAddress((void**)&dth, g_dth);
    cudaGetSymbolAddress((void**)&dtl, g_dtl);
    cudaGetSymbolAddress((void**)&wdth, g_wdth);
    cudaGetSymbolAddress((void**)&wdtl, g_wdtl);
    cudaGetSymbolAddress((void**)&yzh, g_yzh);
    cudaGetSymbolAddress((void**)&yzl, g_yzl);
    cudaGetSymbolAddress((void**)&wouth, g_wouth);
    cudaGetSymbolAddress((void**)&woutl, g_woutl);

    cudaFuncSetAttribute(mma_gemm_k, cudaFuncAttributeMaxDynamicSharedMemorySize,
                         SMEM_MMA);

    // 0) operand prep
    split_k<<<(M * DM / 4 + 255) / 256, 256>>>(x, xh, xl, M * DM / 4);
    prep_w_k<<<6528, dim3(32, 8)>>>(W_in, W_out, W_xprj, W_dt,
                                    winh, winl, wouth, woutl,
                                    wxh, wxl, wdth, wdtl);

    // 1) xz = x @ W_in
    {
        dim3 grid(XZ_N / 128, M / 128, 1);
        mma_gemm_k<<<grid, 256, SMEM_MMA>>>(xh, xl, winh, winl, xz, DM, XZ_N,
                                            DM, 0, nullptr);
    }
    // 2) conv + silu (+ bf16 split), 4 rows x 2 channels per thread
    conv_silu_k<<<((M / 4) * (DI / 2) + 255) / 256, 256>>>(xz, conv_w, conv_b,
                                                           xc, xch, xcl);
    // 3) dbc = xc @ W_xproj (mma, padded N=128, split-K x4)
    {
        dim3 grid(1, M / 128, KSPLIT);
        mma_gemm_k<<<grid, 256, SMEM_MMA>>>(xch, xcl, wxh, wxl, dbcpart, DI,
                                            DBC_LD, DI / KSPLIT,
                                            (size_t)M * DBC_LD, nullptr);
        reduce_part_k<<<(M * DBC_LD / 4 + 255) / 256, 256>>>(
            dbcpart, dbcp, M * DBC_LD / 4, (size_t)M * DBC_LD / 4,
            DBC_LD, DR, dth, dtl);
    }
    // 4) delta = softplus(dt_lo @ W_dt + b_dt) (mma, K=64, fused epilogue)
    {
        dim3 grid(DI / 128, M / 128, 1);
        mma_gemm_k<<<grid, 256, SMEM_MMA>>>(dth, dtl, wdth, wdtl, delta, DR, DI,
                                            DR, 0, b_dt);
    }
    // 5) parallel selective scan
    {
        const int blocks = Bsz * (DI / 256) * NC;  // 1024
        scan1_k<<<blocks, 256>>>(delta, xc, dbcp, A_log, hend, ptot);
        combine_k<<<(NCH * DS) / 256, 256>>>(hend, ptot, hin);
        scan2_k<<<blocks, 256>>>(delta, xc, dbcp, xz, A_log, D_skip, hin,
                                 yzh, yzl);
    }
    // 6) out = yz @ W_out (mma, split-K x4)
    {
        dim3 grid(DM / 128, M / 128, KSPLIT);
        mma_gemm_k<<<grid, 256, SMEM_MMA>>>(yzh, yzl, wouth, woutl, outpart,
                                            DI, DM, DI / KSPLIT,
                                            (size_t)M * DM, nullptr);
        reduce_part_k<<<(M * DM / 4 + 255) / 256, 256>>>(
            outpart, out, M * DM / 4, (size_t)M * DM / 4,
            DM, 0, nullptr, nullptr);
    }
}

// round 16
// speedup vs baseline: 1.7383x; 1.0116x over previous
#include <cuda_runtime.h>
#include <cuda_bf16.h>
#include <math.h>
#include <stdint.h>

// Problem constants
constexpr int Bsz = 2, Lsz = 2048, DM = 1024, DI = 2048, DS = 16, DR = 64;
constexpr int M = Bsz * Lsz;          // 4096
constexpr int XZ_N = 2 * DI;          // 4096
constexpr int DBC_LD = 128;           // padded dbc row stride (real cols: 96)
constexpr int NC = 32, LC = 64;       // scan chunking: 32 chunks x 64 steps
constexpr int NCH = Bsz * DI;         // 4096 channels
constexpr int KSPLIT = 4;             // split-K factor (dbc and out GEMMs)

// fp32 scratch
__device__ float g_xz[(size_t)M * XZ_N];
__device__ float g_xc[(size_t)M * DI];
__device__ float g_dbcp[(size_t)M * DBC_LD];
__device__ float g_dbcpart[(size_t)KSPLIT * M * DBC_LD];
__device__ float g_outpart[(size_t)KSPLIT * M * DM];
__device__ float g_delta[(size_t)M * DI];
// scan chunk state
__device__ float g_hend[(size_t)NC * NCH * DS];
__device__ float g_ptot[(size_t)NC * NCH * DS];
__device__ float g_hin [(size_t)NC * NCH * DS];
// bf16 split operands (A row-major [rows,K]; B stored K-major as [N,K])
__device__ __nv_bfloat16 g_xh[(size_t)M * DM],      g_xl[(size_t)M * DM];
__device__ __nv_bfloat16 g_winh[(size_t)XZ_N * DM], g_winl[(size_t)XZ_N * DM];
__device__ __nv_bfloat16 g_xch[(size_t)M * DI],     g_xcl[(size_t)M * DI];
__device__ __nv_bfloat16 g_wxh[(size_t)DBC_LD * DI], g_wxl[(size_t)DBC_LD * DI];
__device__ __nv_bfloat16 g_dth[(size_t)M * DR],     g_dtl[(size_t)M * DR];
__device__ __nv_bfloat16 g_wdth[(size_t)DI * DR],   g_wdtl[(size_t)DI * DR];
__device__ __nv_bfloat16 g_yzh[(size_t)M * DI],     g_yzl[(size_t)M * DI];
__device__ __nv_bfloat16 g_wouth[(size_t)DM * DI],  g_woutl[(size_t)DM * DI];

__device__ __forceinline__ float sigmoidf_fast(float x) {
    return 1.0f / (1.0f + __expf(-x));
}
__device__ __forceinline__ float softplusf(float x) {
    return (x > 20.0f) ? x : log1pf(expf(x));
}
__device__ __forceinline__ float ex2f(float x) {
    float r;
    asm("ex2.approx.f32 %0, %1;" : "=f"(r) : "f"(x));
    return r;
}

// ---------------------------------------------------------------------------
// PTX helpers (portable sm_80+ PTX only)
// ---------------------------------------------------------------------------
__device__ __forceinline__ void cp_async16(uint32_t dst, const void* src) {
    asm volatile("cp.async.cg.shared.global [%0], [%1], 16;"
                 :: "r"(dst), "l"(src) : "memory");
}
__device__ __forceinline__ void cp_commit() {
    asm volatile("cp.async.commit_group;" ::: "memory");
}
template <int N>
__device__ __forceinline__ void cp_wait() {
    asm volatile("cp.async.wait_group %0;" :: "n"(N) : "memory");
}
__device__ __forceinline__ void ldsm_x4(uint32_t* r, uint32_t addr) {
    asm volatile("ldmatrix.sync.aligned.m8n8.x4.shared.b16 {%0,%1,%2,%3}, [%4];"
                 : "=r"(r[0]), "=r"(r[1]), "=r"(r[2]), "=r"(r[3]) : "r"(addr));
}
__device__ __forceinline__ void mma16816(float* c, const uint32_t* a,
                                         uint32_t b0, uint32_t b1) {
    asm volatile(
        "mma.sync.aligned.m16n8k16.row.col.f32.bf16.bf16.f32 "
        "{%0,%1,%2,%3}, {%4,%5,%6,%7}, {%8,%9}, {%0,%1,%2,%3};"
        : "+f"(c[0]), "+f"(c[1]), "+f"(c[2]), "+f"(c[3])
        : "r"(a[0]), "r"(a[1]), "r"(a[2]), "r"(a[3]), "r"(b0), "r"(b1));
}

// ---------------------------------------------------------------------------
// Merged operand prep: transpose+split the 4 weight matrices AND straight-split
// x, all in one launch. Sections (32x32 tiles, block (32,8)):
//   [0,4096):      W_in   [1024,4096] -> [4096,1024]
//   [4096,6144):   W_out  [2048,1024] -> [1024,2048]
//   [6144,6400):   W_xprj [2048,  96] -> [ 128,2048]  (zero-pad rows)
//   [6400,6528):   W_dt   [  64,2048] -> [2048,  64]
//   [6528,10624):  x      [4096,1024] straight split (no transpose)
// ---------------------------------------------------------------------------
__global__ void prep_w_k(const float* __restrict__ Win,
                         const float* __restrict__ Wout,
                         const float* __restrict__ Wxp,
                         const float* __restrict__ Wdt,
                         const float* __restrict__ X,
                         __nv_bfloat16* __restrict__ winh, __nv_bfloat16* __restrict__ winl,
                         __nv_bfloat16* __restrict__ wouth, __nv_bfloat16* __restrict__ woutl,
                         __nv_bfloat16* __restrict__ wxh, __nv_bfloat16* __restrict__ wxl,
                         __nv_bfloat16* __restrict__ wdth, __nv_bfloat16* __restrict__ wdtl,
                         __nv_bfloat16* __restrict__ xh, __nv_bfloat16* __restrict__ xl)
{
    const int t = blockIdx.x;
    const int tx = threadIdx.x, ty = threadIdx.y;

    if (t >= 6528) {  // x straight split: [4096,1024], tile grid 128 x 32
        const int local = t - 6528;
        const int rt = local >> 5, ct = local & 31;
        const int r0 = rt * 32, c0 = ct * 32;
        for (int i = ty; i < 32; i += 8) {
            const size_t o = (size_t)(r0 + i) * DM + c0 + tx;
            const float v = X[o];
            const __nv_bfloat16 h = __float2bfloat16(v);
            xh[o] = h;
            xl[o] = __float2bfloat16(v - __bfloat162float(h));
        }
        return;
    }

    const float* src; int K, Nsrc, tilesN, local;
    __nv_bfloat16 *hi, *lo;
    if (t < 4096)      { src = Win;  K = 1024; Nsrc = 4096; hi = winh;  lo = winl;  tilesN = 128; local = t; }
    else if (t < 6144) { src = Wout; K = 2048; Nsrc = 1024; hi = wouth; lo = woutl; tilesN = 32;  local = t - 4096; }
    else if (t < 6400) { src = Wxp;  K = 2048; Nsrc = 96;   hi = wxh;   lo = wxl;   tilesN = 4;   local = t - 6144; }
    else               { src = Wdt;  K = 64;   Nsrc = 2048; hi = wdth;  lo = wdtl;  tilesN = 64;  local = t - 6400; }
    const int nt = local % tilesN, kt = local / tilesN;
    const int n0 = nt * 32, k0 = kt * 32;

    __shared__ float sm[32][33];
    for (int i = ty; i < 32; i += 8) {
        float v = 0.0f;
        if (n0 + tx < Nsrc) v = src[(size_t)(k0 + i) * Nsrc + n0 + tx];
        sm[i][tx] = v;
    }
    __syncthreads();
    for (int i = ty; i < 32; i += 8) {
        const float v = sm[tx][i];
        const __nv_bfloat16 h = __float2bfloat16(v);
        hi[(size_t)(n0 + i) * K + k0 + tx] = h;
        lo[(size_t)(n0 + i) * K + k0 + tx] =
            __float2bfloat16(v - __bfloat162float(h));
    }
}

// Reduce KSPLIT partial C buffers into one (float4 vectorized).
// Optional fused split of leading split_ncol columns (delta GEMM input).
__global__ void reduce_part_k(const float* __restrict__ part,
                              float* __restrict__ out, int n4, size_t zstride4,
                              int ldc, int split_ncol,
                              __nv_bfloat16* __restrict__ shi,
                              __nv_bfloat16* __restrict__ slo)
{
    int i = blockIdx.x * blockDim.x + threadIdx.x;
    if (i >= n4) return;
    float4 a = ((const float4*)part)[i];
#pragma unroll
    for (int z = 1; z < KSPLIT; z++) {
        float4 b = ((const float4*)part)[(size_t)z * zstride4 + i];
        a.x += b.x; a.y += b.y; a.z += b.z; a.w += b.w;
    }
    ((float4*)out)[i] = a;
    if (shi) {
        const int per_row = ldc / 4;
        const int row = i / per_row;
        const int c4 = (i % per_row) * 4;
        if (c4 < split_ncol) {
            __nv_bfloat16 h0 = __float2bfloat16(a.x);
            __nv_bfloat16 h1 = __float2bfloat16(a.y);
            __nv_bfloat16 h2 = __float2bfloat16(a.z);
            __nv_bfloat16 h3 = __float2bfloat16(a.w);
            ushort4 hh, ll;
            hh.x = __bfloat16_as_ushort(h0); hh.y = __bfloat16_as_ushort(h1);
            hh.z = __bfloat16_as_ushort(h2); hh.w = __bfloat16_as_ushort(h3);
            ll.x = __bfloat16_as_ushort(__float2bfloat16(a.x - __bfloat162float(h0)));
            ll.y = __bfloat16_as_ushort(__float2bfloat16(a.y - __bfloat162float(h1)));
            ll.z = __bfloat16_as_ushort(__float2bfloat16(a.z - __bfloat162float(h2)));
            ll.w = __bfloat16_as_ushort(__float2bfloat16(a.w - __bfloat162float(h3)));
            const int oi = (row * split_ncol + c4) / 4;
            ((ushort4*)shi)[oi] = hh;
            ((ushort4*)slo)[oi] = ll;
        }
    }
}

// ---------------------------------------------------------------------------
// mma.sync split-bf16 GEMM (round-10 winning mainloop, FROZEN).
// ---------------------------------------------------------------------------
constexpr int BK = 32;
constexpr int ROWB = 80;
constexpr int TILEB = 128 * ROWB;
constexpr int STAGEB = 4 * TILEB;
constexpr int NSTAGE = 3;
constexpr int SMEM_MMA = NSTAGE * STAGEB;  // 122880 B

__global__ void __launch_bounds__(256, 1) mma_gemm_k(
    const __nv_bfloat16* __restrict__ Ah, const __nv_bfloat16* __restrict__ Al,
    const __nv_bfloat16* __restrict__ Bh, const __nv_bfloat16* __restrict__ Bl,
    float* __restrict__ C, int lda, int ldc, int kspan, size_t zstride,
    const float* __restrict__ bias)
{
    extern __shared__ __align__(16) char smem[];
    const uint32_t sb = (uint32_t)__cvta_generic_to_shared(smem);
    const int tid = threadIdx.x;
    const int wid = tid >> 5, lid = tid & 31;
    const int warpM = wid & 3, warpN = wid >> 2;   // 4 x 2

    const int rowBase = blockIdx.y * 128;
    const int colBase = blockIdx.x * 128;
    const int kstart = blockIdx.z * kspan;
    const int nch = kspan / BK;
    C += (size_t)blockIdx.z * zstride;

    float acc[2][8][4];
#pragma unroll
    for (int i = 0; i < 2; i++)
#pragma unroll
        for (int j = 0; j < 8; j++)
#pragma unroll
            for (int q = 0; q < 4; q++) acc[i][j][q] = 0.0f;

    auto load_chunk = [&](int c, int buf) {
        const uint32_t st = sb + buf * STAGEB;
        const int k0 = kstart + c * BK;
#pragma unroll
        for (int ch = tid; ch < 512; ch += 256) {
            const int row = ch >> 2;
            const int kc = ch & 3;
            const uint32_t so = row * ROWB + kc * 16;
            const size_t go = (size_t)k0 + kc * 8;
            cp_async16(st + so,             Ah + (size_t)(rowBase + row) * lda + go);
            cp_async16(st + TILEB + so,     Al + (size_t)(rowBase + row) * lda + go);
            cp_async16(st + 2 * TILEB + so, Bh + (size_t)(colBase + row) * lda + go);
            cp_async16(st + 3 * TILEB + so, Bl + (size_t)(colBase + row) * lda + go);
        }
        cp_commit();
    };

    load_chunk(0, 0);
    if (1 < nch) load_chunk(1, 1); else cp_commit();
    if (2 < nch) load_chunk(2, 2); else cp_commit();

    const int lr = lid & 15;
    const int lc16 = (lid >> 4) * 16;

    for (int c = 0; c < nch; c++) {
        const int buf = c % NSTAGE;
        cp_wait<NSTAGE - 1>();
        __syncthreads();

        const uint32_t st = sb + buf * STAGEB;
#pragma unroll
        for (int kk = 0; kk < 2; kk++) {
            const uint32_t kb = kk * 32;
            uint32_t ah[2][4], al[2][4];
#pragma unroll
            for (int mf = 0; mf < 2; mf++) {
                const uint32_t a =
                    st + (warpM * 32 + mf * 16 + lr) * ROWB + kb + lc16;
                ldsm_x4(ah[mf], a);
                ldsm_x4(al[mf], a + TILEB);
            }
            uint32_t bh[8][2], bl[8][2];
#pragma unroll
            for (int np = 0; np < 4; np++) {
                const uint32_t a =
                    st + 2 * TILEB + (warpN * 64 + np * 16 + lr) * ROWB + kb + lc16;
                uint32_t t[4];
                ldsm_x4(t, a);
                bh[2 * np][0] = t[0]; bh[2 * np + 1][0] = t[1];
                bh[2 * np][1] = t[2]; bh[2 * np + 1][1] = t[3];
                ldsm_x4(t, a + TILEB);
                bl[2 * np][0] = t[0]; bl[2 * np + 1][0] = t[1];
                bl[2 * np][1] = t[2]; bl[2 * np + 1][1] = t[3];
            }
            // interleaved MMA order (proven fastest)
#pragma unroll
            for (int mf = 0; mf < 2; mf++)
#pragma unroll
                for (int nf = 0; nf < 8; nf++) {
                    mma16816(acc[mf][nf], ah[mf], bh[nf][0], bh[nf][1]);
                    mma16816(acc[mf][nf], ah[mf], bl[nf][0], bl[nf][1]);
                    mma16816(acc[mf][nf], al[mf], bh[nf][0], bh[nf][1]);
                }
        }
        __syncthreads();
        if (c + NSTAGE < nch) load_chunk(c + NSTAGE, buf);
        else cp_commit();
    }

    const int r = lid >> 2, cq = (lid & 3) * 2;
    float* Cw = C + (size_t)(rowBase + warpM * 32) * ldc + colBase + warpN * 64;
    const int cBase = colBase + warpN * 64;
#pragma unroll
    for (int mf = 0; mf < 2; mf++)
#pragma unroll
        for (int nf = 0; nf < 8; nf++) {
            float v0 = acc[mf][nf][0], v1 = acc[mf][nf][1];
            float v2 = acc[mf][nf][2], v3 = acc[mf][nf][3];
            if (bias) {
                const float b0 = bias[cBase + nf * 8 + cq];
                const float b1 = bias[cBase + nf * 8 + cq + 1];
                v0 = softplusf(v0 + b0); v1 = softplusf(v1 + b1);
                v2 = softplusf(v2 + b0); v3 = softplusf(v3 + b1);
            }
            *(float2*)&Cw[(size_t)(mf * 16 + r) * ldc + nf * 8 + cq] =
                make_float2(v0, v1);
            *(float2*)&Cw[(size_t)(mf * 16 + r + 8) * ldc + nf * 8 + cq] =
                make_float2(v2, v3);
        }
}

// ---------------------------------------------------------------------------
// Depthwise causal conv (width 4) + SiLU + fused bf16 split.
// Each thread: 4 consecutive l x 2 consecutive channels (float2 vectorized).
// ---------------------------------------------------------------------------
__global__ void conv_silu_k(const float* __restrict__ xz,
                            const float* __restrict__ w,
                            const float* __restrict__ bias,
                            float* __restrict__ xc,
                            __nv_bfloat16* __restrict__ xch,
                            __nv_bfloat16* __restrict__ xcl)
{
    const int idx = blockIdx.x * blockDim.x + threadIdx.x;  // (M/4)*(DI/2)
    if (idx >= (M / 4) * (DI / 2)) return;
    const int d0 = (idx % (DI / 2)) * 2;
    const int m0 = (idx / (DI / 2)) * 4;
    const int l0 = m0 % Lsz;   // multiple of 4

    const float4 wa = *(const float4*)&w[d0 * 4];
    const float4 wb = *(const float4*)&w[d0 * 4 + 4];
    const float2 bz = *(const float2*)&bias[d0];

    float2 xv[7];
#pragma unroll
    for (int j = 0; j < 7; j++) {
        const int mm = m0 - 3 + j;
        if (l0 + j >= 3) xv[j] = *(const float2*)&xz[(size_t)mm * XZ_N + d0];
        else             xv[j] = make_float2(0.0f, 0.0f);
    }
#pragma unroll
    for (int i = 0; i < 4; i++) {
        float a0 = bz.x, a1 = bz.y;
        a0 = fmaf(wa.x, xv[i + 0].x, a0); a1 = fmaf(wb.x, xv[i + 0].y, a1);
        a0 = fmaf(wa.y, xv[i + 1].x, a0); a1 = fmaf(wb.y, xv[i + 1].y, a1);
        a0 = fmaf(wa.z, xv[i + 2].x, a0); a1 = fmaf(wb.z, xv[i + 2].y, a1);
        a0 = fmaf(wa.w, xv[i + 3].x, a0); a1 = fmaf(wb.w, xv[i + 3].y, a1);
        const float v0 = a0 * sigmoidf_fast(a0);
        const float v1 = a1 * sigmoidf_fast(a1);
        const size_t o = (size_t)(m0 + i) * DI + d0;
        *(float2*)&xc[o] = make_float2(v0, v1);
        const __nv_bfloat16 h0 = __float2bfloat16(v0);
        const __nv_bfloat16 h1 = __float2bfloat16(v1);
        uint32_t hp = (uint32_t)__bfloat16_as_ushort(h0) |
                      ((uint32_t)__bfloat16_as_ushort(h1) << 16);
        uint32_t lp = (uint32_t)__bfloat16_as_ushort(
                          __float2bfloat16(v0 - __bfloat162float(h0))) |
                      ((uint32_t)__bfloat16_as_ushort(
                          __float2bfloat16(v1 - __bfloat162float(h1))) << 16);
        *(uint32_t*)&xch[o] = hp;
        *(uint32_t*)&xcl[o] = lp;
    }
}

// ---------------------------------------------------------------------------
// Parallel selective scan (recurrence-reinit), ex2.approx, ptot via delta-sum.
// NC=32 chunks x LC=64 steps; 512 blocks of 256 threads.
// ---------------------------------------------------------------------------
constexpr float L2E = 1.4426950408889634f;

__global__ void __launch_bounds__(256) scan1_k(
    const float* __restrict__ delta_, const float* __restrict__ xc,
    const float* __restrict__ dbcp, const float* __restrict__ A_log,
    float* __restrict__ hend, float* __restrict__ ptot)
{
    __shared__ float sB[LC][DS];
    const int tid = threadIdx.x;
    const int blk = blockIdx.x;
    const int c = blk & (NC - 1);
    const int t = blk >> 5;            // 0..15
    const int b = t >> 3;
    const int d = ((t & 7) << 8) + tid;
    const size_t mbase = (size_t)b * Lsz + c * LC;

    for (int i = tid; i < LC * DS; i += 256) {
        const int row = i >> 4, col = i & 15;
        sB[row][col] = dbcp[(mbase + row) * DBC_LD + DR + col];
    }
    float An2[DS];
#pragma unroll
    for (int s = 0; s < DS; s++) An2[s] = -__expf(A_log[d * DS + s]) * L2E;
    __syncthreads();

    float h[DS];
#pragma unroll
    for (int s = 0; s < DS; s++) h[s] = 0.0f;
    float sd = 0.0f;

#pragma unroll 2
    for (int k = 0; k < LC; k++) {
        const size_t m = mbase + k;
        const float delta = delta_[m * DI + d];
        const float du = delta * xc[m * DI + d];
        sd += delta;
#pragma unroll
        for (int s = 0; s < DS; s++) {
            const float a = ex2f(delta * An2[s]);
            h[s] = fmaf(a, h[s], du * sB[k][s]);
        }
    }
    const size_t idx = (size_t)c * (NCH * DS) + ((size_t)(b * DI + d)) * DS;
#pragma unroll
    for (int s = 0; s < DS; s++) {
        hend[idx + s] = h[s];
        ptot[idx + s] = ex2f(sd * An2[s]);
    }
}

__global__ void __launch_bounds__(256) combine_k(
    const float* __restrict__ hend, const float* __restrict__ ptot,
    float* __restrict__ hin)
{
    const int i = blockIdx.x * 256 + threadIdx.x;  // NCH*DS = 65536
    float H = 0.0f;
#pragma unroll
    for (int c = 0; c < NC; c++) {
        const size_t idx = (size_t)c * (NCH * DS) + i;
        hin[idx] = H;
        H = fmaf(ptot[idx], H, hend[idx]);
    }
}

__global__ void __launch_bounds__(256) scan2_k(
    const float* __restrict__ delta_, const float* __restrict__ xc,
    const float* __restrict__ dbcp, const float* __restrict__ xz,
    const float* __restrict__ A_log, const float* __restrict__ D_skip,
    const float* __restrict__ hin_,
    __nv_bfloat16* __restrict__ yzh, __nv_bfloat16* __restrict__ yzl)
{
    __shared__ float sB[LC][DS];
    __shared__ float sC[LC][DS];
    const int tid = threadIdx.x;
    const int blk = blockIdx.x;
    const int c = blk & (NC - 1);
    const int t = blk >> 5;
    const int b = t >> 3;
    const int d = ((t & 7) << 8) + tid;
    const size_t mbase = (size_t)b * Lsz + c * LC;

    for (int i = tid; i < LC * 32; i += 256) {
        const int row = i >> 5, col = i & 31;
        const float v = dbcp[(mbase + row) * DBC_LD + DR + col];
        if (col < DS) sB[row][col] = v;
        else          sC[row][col - DS] = v;
    }
    float An2[DS];
#pragma unroll
    for (int s = 0; s < DS; s++) An2[s] = -__expf(A_log[d * DS + s]) * L2E;
    const float dskip = D_skip[d];

    float h[DS];
    const size_t hidx = (size_t)c * (NCH * DS) + ((size_t)(b * DI + d)) * DS;
#pragma unroll
    for (int s = 0; s < DS; s++) h[s] = hin_[hidx + s];
    __syncthreads();

#pragma unroll 2
    for (int k = 0; k < LC; k++) {
        const size_t m = mbase + k;
        const float delta = delta_[m * DI + d];
        const float u = xc[m * DI + d];
        const float du = delta * u;
        float y = 0.0f;
#pragma unroll
        for (int s = 0; s < DS; s++) {
            const float a = ex2f(delta * An2[s]);
            h[s] = fmaf(a, h[s], du * sB[k][s]);
            y = fmaf(h[s], sC[k][s], y);
        }
        const float z = xz[m * XZ_N + DI + d];
        const float val = (y + u * dskip) * (z * sigmoidf_fast(z));
        const __nv_bfloat16 hh = __float2bfloat16(val);
        yzh[m * DI + d] = hh;
        yzl[m * DI + d] = __float2bfloat16(val - __bfloat162float(hh));
    }
}

// ---------------------------------------------------------------------------
extern "C" void kernel_launch(void* const* d_in, const int* in_sizes, int n_in,
                              void* d_out, int out_size)
{
    const float* x      = (const float*)d_in[0];
    const float* W_in   = (const float*)d_in[1];
    const float* conv_w = (const float*)d_in[2];
    const float* conv_b = (const float*)d_in[3];
    const float* W_xprj = (const float*)d_in[4];
    const float* W_dt   = (const float*)d_in[5];
    const float* b_dt   = (const float*)d_in[6];
    const float* A_log  = (const float*)d_in[7];
    const float* D_skip = (const float*)d_in[8];
    const float* W_out  = (const float*)d_in[9];
    float* out = (float*)d_out;

    float *xz, *xc, *dbcp, *dbcpart, *outpart, *delta, *hend, *ptot, *hin;
    cudaGetSymbolAddress((void**)&xz, g_xz);
    cudaGetSymbolAddress((void**)&xc, g_xc);
    cudaGetSymbolAddress((void**)&dbcp, g_dbcp);
    cudaGetSymbolAddress((void**)&dbcpart, g_dbcpart);
    cudaGetSymbolAddress((void**)&outpart, g_outpart);
    cudaGetSymbolAddress((void**)&delta, g_delta);
    cudaGetSymbolAddress((void**)&hend, g_hend);
    cudaGetSymbolAddress((void**)&ptot, g_ptot);
    cudaGetSymbolAddress((void**)&hin, g_hin);
    __nv_bfloat16 *xh, *xl, *winh, *winl, *xch, *xcl, *wxh, *wxl,
                  *dth, *dtl, *wdth, *wdtl, *yzh, *yzl, *wouth, *woutl;
    cudaGetSymbolAddress((void**)&xh, g_xh);
    cudaGetSymbolAddress((void**)&xl, g_xl);
    cudaGetSymbolAddress((void**)&winh, g_winh);
    cudaGetSymbolAddress((void**)&winl, g_winl);
    cudaGetSymbolAddress((void**)&xch, g_xch);
    cudaGetSymbolAddress((void**)&xcl, g_xcl);
    cudaGetSymbolAddress((void**)&wxh, g_wxh);
    cudaGetSymbolAddress((void**)&wxl, g_wxl);
    cudaGetSymbolAddress((void**)&dth, g_dth);
    cudaGetSymbolAddress((void**)&dtl, g_dtl);
    cudaGetSymbolAddress((void**)&wdth, g_wdth);
    cudaGetSymbolAddress((void**)&wdtl, g_wdtl);
    cudaGetSymbolAddress((void**)&yzh, g_yzh);
    cudaGetSymbolAddress((void**)&yzl, g_yzl);
    cudaGetSymbolAddress((void**)&wouth, g_wouth);
    cudaGetSymbolAddress((void**)&woutl, g_woutl);

    cudaFuncSetAttribute(mma_gemm_k, cudaFuncAttributeMaxDynamicSharedMemorySize,
                         SMEM_MMA);

    // 0) operand prep: weights + x, single launch
    prep_w_k<<<10624, dim3(32, 8)>>>(W_in, W_out, W_xprj, W_dt, x,
                                     winh, winl, wouth, woutl,
                                     wxh, wxl, wdth, wdtl, xh, xl);

    // 1) xz = x @ W_in
    {
        dim3 grid(XZ_N / 128, M / 128, 1);
        mma_gemm_k<<<grid, 256, SMEM_MMA>>>(xh, xl, winh, winl, xz, DM, XZ_N,
                                            DM, 0, nullptr);
    }
    // 2) conv + silu (+ bf16 split), 4 rows x 2 channels per thread
    conv_silu_k<<<((M / 4) * (DI / 2) + 255) / 256, 256>>>(xz, conv_w, conv_b,
                                                           xc, xch, xcl);
    // 3) dbc = xc @ W_xproj (mma, padded N=128, split-K x4)
    {
        dim3 grid(1, M / 128, KSPLIT);
        mma_gemm_k<<<grid, 256, SMEM_MMA>>>(xch, xcl, wxh, wxl, dbcpart, DI,
                                            DBC_LD, DI / KSPLIT,
                                            (size_t)M * DBC_LD, nullptr);
        reduce_part_k<<<(M * DBC_LD / 4 + 255) / 256, 256>>>(
            dbcpart, dbcp, M * DBC_LD / 4, (size_t)M * DBC_LD / 4,
            DBC_LD, DR, dth, dtl);
    }
    // 4) delta = softplus(dt_lo @ W_dt + b_dt) (mma, K=64, fused epilogue)
    {
        dim3 grid(DI / 128, M / 128, 1);
        mma_gemm_k<<<grid, 256, SMEM_MMA>>>(dth, dtl, wdth, wdtl, delta, DR, DI,
                                            DR, 0, b_dt);
    }
    // 5) parallel selective scan (NC=32 x LC=64)
    {
        const int blocks = Bsz * (DI / 256) * NC;  // 512
        scan1_k<<<blocks, 256>>>(delta, xc, dbcp, A_log, hend, ptot);
        combine_k<<<(NCH * DS) / 256, 256>>>(hend, ptot, hin);
        scan2_k<<<blocks, 256>>>(delta, xc, dbcp, xz, A_log, D_skip, hin,
                                 yzh, yzl);
    }
    // 6) out = yz @ W_out (mma, split-K x4)
    {
        dim3 grid(DM / 128, M / 128, KSPLIT);
        mma_gemm_k<<<grid, 256, SMEM_MMA>>>(yzh, yzl, wouth, woutl, outpart,
                                            DI, DM, DI / KSPLIT,
                                            (size_t)M * DM, nullptr);
        reduce_part_k<<<(M * DM / 4 + 255) / 256, 256>>>(
            outpart, out, M * DM / 4, (size_t)M * DM / 4,
            DM, 0, nullptr, nullptr);
    }
}

// round 17
// speedup vs baseline: 1.7469x; 1.0049x over previous
#include <cuda_runtime.h>
#include <cuda_bf16.h>
#include <math.h>
#include <stdint.h>

// Problem constants
constexpr int Bsz = 2, Lsz = 2048, DM = 1024, DI = 2048, DS = 16, DR = 64;
constexpr int M = Bsz * Lsz;          // 4096
constexpr int XZ_N = 2 * DI;          // 4096
constexpr int DBC_LD = 128;           // padded dbc row stride (real cols: 96)
constexpr int NC = 32, LC = 64;       // scan chunking: 32 chunks x 64 steps
constexpr int NCH = Bsz * DI;         // 4096 channels
constexpr int KSPLIT = 4;             // split-K factor (dbc and out GEMMs)

// fp32 scratch
__device__ float g_xz[(size_t)M * XZ_N];
__device__ float g_xc[(size_t)M * DI];
__device__ float g_dbcp[(size_t)M * DBC_LD];
__device__ float g_dbcpart[(size_t)KSPLIT * M * DBC_LD];
__device__ float g_outpart[(size_t)KSPLIT * M * DM];
__device__ float g_delta[(size_t)M * DI];
// scan chunk state
__device__ float g_hend[(size_t)NC * NCH * DS];
__device__ float g_ptot[(size_t)NC * NCH * DS];
__device__ float g_hin [(size_t)NC * NCH * DS];
// bf16 split operands (A row-major [rows,K]; B stored K-major as [N,K])
__device__ __nv_bfloat16 g_xh[(size_t)M * DM],      g_xl[(size_t)M * DM];
__device__ __nv_bfloat16 g_winh[(size_t)XZ_N * DM], g_winl[(size_t)XZ_N * DM];
__device__ __nv_bfloat16 g_xch[(size_t)M * DI],     g_xcl[(size_t)M * DI];
__device__ __nv_bfloat16 g_wxh[(size_t)DBC_LD * DI], g_wxl[(size_t)DBC_LD * DI];
__device__ __nv_bfloat16 g_dth[(size_t)M * DR],     g_dtl[(size_t)M * DR];
__device__ __nv_bfloat16 g_wdth[(size_t)DI * DR],   g_wdtl[(size_t)DI * DR];
__device__ __nv_bfloat16 g_yzh[(size_t)M * DI],     g_yzl[(size_t)M * DI];
__device__ __nv_bfloat16 g_wouth[(size_t)DM * DI],  g_woutl[(size_t)DM * DI];

__device__ __forceinline__ float sigmoidf_fast(float x) {
    return 1.0f / (1.0f + __expf(-x));
}
__device__ __forceinline__ float softplusf(float x) {
    return (x > 20.0f) ? x : log1pf(expf(x));
}
__device__ __forceinline__ float ex2f(float x) {
    float r;
    asm("ex2.approx.f32 %0, %1;" : "=f"(r) : "f"(x));
    return r;
}

// ---------------------------------------------------------------------------
// PTX helpers (portable sm_80+ PTX only)
// ---------------------------------------------------------------------------
__device__ __forceinline__ void cp_async16(uint32_t dst, const void* src) {
    asm volatile("cp.async.cg.shared.global [%0], [%1], 16;"
                 :: "r"(dst), "l"(src) : "memory");
}
__device__ __forceinline__ void cp_commit() {
    asm volatile("cp.async.commit_group;" ::: "memory");
}
template <int N>
__device__ __forceinline__ void cp_wait() {
    asm volatile("cp.async.wait_group %0;" :: "n"(N) : "memory");
}
__device__ __forceinline__ void ldsm_x4(uint32_t* r, uint32_t addr) {
    asm volatile("ldmatrix.sync.aligned.m8n8.x4.shared.b16 {%0,%1,%2,%3}, [%4];"
                 : "=r"(r[0]), "=r"(r[1]), "=r"(r[2]), "=r"(r[3]) : "r"(addr));
}
__device__ __forceinline__ void mma16816(float* c, const uint32_t* a,
                                         uint32_t b0, uint32_t b1) {
    asm volatile(
        "mma.sync.aligned.m16n8k16.row.col.f32.bf16.bf16.f32 "
        "{%0,%1,%2,%3}, {%4,%5,%6,%7}, {%8,%9}, {%0,%1,%2,%3};"
        : "+f"(c[0]), "+f"(c[1]), "+f"(c[2]), "+f"(c[3])
        : "r"(a[0]), "r"(a[1]), "r"(a[2]), "r"(a[3]), "r"(b0), "r"(b1));
}

// ---------------------------------------------------------------------------
// Merged operand prep: transpose+split the 4 weight matrices AND straight-split
// x, all in one launch. Sections (32x32 tiles, block (32,8)):
//   [0,4096):      W_in   [1024,4096] -> [4096,1024]
//   [4096,6144):   W_out  [2048,1024] -> [1024,2048]
//   [6144,6400):   W_xprj [2048,  96] -> [ 128,2048]  (zero-pad rows)
//   [6400,6528):   W_dt   [  64,2048] -> [2048,  64]
//   [6528,10624):  x      [4096,1024] straight split (no transpose)
// ---------------------------------------------------------------------------
__global__ void prep_w_k(const float* __restrict__ Win,
                         const float* __restrict__ Wout,
                         const float* __restrict__ Wxp,
                         const float* __restrict__ Wdt,
                         const float* __restrict__ X,
                         __nv_bfloat16* __restrict__ winh, __nv_bfloat16* __restrict__ winl,
                         __nv_bfloat16* __restrict__ wouth, __nv_bfloat16* __restrict__ woutl,
                         __nv_bfloat16* __restrict__ wxh, __nv_bfloat16* __restrict__ wxl,
                         __nv_bfloat16* __restrict__ wdth, __nv_bfloat16* __restrict__ wdtl,
                         __nv_bfloat16* __restrict__ xh, __nv_bfloat16* __restrict__ xl)
{
    const int t = blockIdx.x;
    const int tx = threadIdx.x, ty = threadIdx.y;

    if (t >= 6528) {  // x straight split: [4096,1024], tile grid 128 x 32
        const int local = t - 6528;
        const int rt = local >> 5, ct = local & 31;
        const int r0 = rt * 32, c0 = ct * 32;
        for (int i = ty; i < 32; i += 8) {
            const size_t o = (size_t)(r0 + i) * DM + c0 + tx;
            const float v = X[o];
            const __nv_bfloat16 h = __float2bfloat16(v);
            xh[o] = h;
            xl[o] = __float2bfloat16(v - __bfloat162float(h));
        }
        return;
    }

    const float* src; int K, Nsrc, tilesN, local;
    __nv_bfloat16 *hi, *lo;
    if (t < 4096)      { src = Win;  K = 1024; Nsrc = 4096; hi = winh;  lo = winl;  tilesN = 128; local = t; }
    else if (t < 6144) { src = Wout; K = 2048; Nsrc = 1024; hi = wouth; lo = woutl; tilesN = 32;  local = t - 4096; }
    else if (t < 6400) { src = Wxp;  K = 2048; Nsrc = 96;   hi = wxh;   lo = wxl;   tilesN = 4;   local = t - 6144; }
    else               { src = Wdt;  K = 64;   Nsrc = 2048; hi = wdth;  lo = wdtl;  tilesN = 64;  local = t - 6400; }
    const int nt = local % tilesN, kt = local / tilesN;
    const int n0 = nt * 32, k0 = kt * 32;

    __shared__ float sm[32][33];
    for (int i = ty; i < 32; i += 8) {
        float v = 0.0f;
        if (n0 + tx < Nsrc) v = src[(size_t)(k0 + i) * Nsrc + n0 + tx];
        sm[i][tx] = v;
    }
    __syncthreads();
    for (int i = ty; i < 32; i += 8) {
        const float v = sm[tx][i];
        const __nv_bfloat16 h = __float2bfloat16(v);
        hi[(size_t)(n0 + i) * K + k0 + tx] = h;
        lo[(size_t)(n0 + i) * K + k0 + tx] =
            __float2bfloat16(v - __bfloat162float(h));
    }
}

// Reduce KSPLIT partial C buffers into one (float4 vectorized).
// Optional fused split of leading split_ncol columns (delta GEMM input).
__global__ void reduce_part_k(const float* __restrict__ part,
                              float* __restrict__ out, int n4, size_t zstride4,
                              int ldc, int split_ncol,
                              __nv_bfloat16* __restrict__ shi,
                              __nv_bfloat16* __restrict__ slo)
{
    int i = blockIdx.x * blockDim.x + threadIdx.x;
    if (i >= n4) return;
    float4 a = ((const float4*)part)[i];
#pragma unroll
    for (int z = 1; z < KSPLIT; z++) {
        float4 b = ((const float4*)part)[(size_t)z * zstride4 + i];
        a.x += b.x; a.y += b.y; a.z += b.z; a.w += b.w;
    }
    ((float4*)out)[i] = a;
    if (shi) {
        const int per_row = ldc / 4;
        const int row = i / per_row;
        const int c4 = (i % per_row) * 4;
        if (c4 < split_ncol) {
            __nv_bfloat16 h0 = __float2bfloat16(a.x);
            __nv_bfloat16 h1 = __float2bfloat16(a.y);
            __nv_bfloat16 h2 = __float2bfloat16(a.z);
            __nv_bfloat16 h3 = __float2bfloat16(a.w);
            ushort4 hh, ll;
            hh.x = __bfloat16_as_ushort(h0); hh.y = __bfloat16_as_ushort(h1);
            hh.z = __bfloat16_as_ushort(h2); hh.w = __bfloat16_as_ushort(h3);
            ll.x = __bfloat16_as_ushort(__float2bfloat16(a.x - __bfloat162float(h0)));
            ll.y = __bfloat16_as_ushort(__float2bfloat16(a.y - __bfloat162float(h1)));
            ll.z = __bfloat16_as_ushort(__float2bfloat16(a.z - __bfloat162float(h2)));
            ll.w = __bfloat16_as_ushort(__float2bfloat16(a.w - __bfloat162float(h3)));
            const int oi = (row * split_ncol + c4) / 4;
            ((ushort4*)shi)[oi] = hh;
            ((ushort4*)slo)[oi] = ll;
        }
    }
}

// ---------------------------------------------------------------------------
// mma.sync split-bf16 GEMM (round-10 winning mainloop, FROZEN).
// ---------------------------------------------------------------------------
constexpr int BK = 32;
constexpr int ROWB = 80;
constexpr int TILEB = 128 * ROWB;
constexpr int STAGEB = 4 * TILEB;
constexpr int NSTAGE = 3;
constexpr int SMEM_MMA = NSTAGE * STAGEB;  // 122880 B

__global__ void __launch_bounds__(256, 1) mma_gemm_k(
    const __nv_bfloat16* __restrict__ Ah, const __nv_bfloat16* __restrict__ Al,
    const __nv_bfloat16* __restrict__ Bh, const __nv_bfloat16* __restrict__ Bl,
    float* __restrict__ C, int lda, int ldc, int kspan, size_t zstride,
    const float* __restrict__ bias)
{
    extern __shared__ __align__(16) char smem[];
    const uint32_t sb = (uint32_t)__cvta_generic_to_shared(smem);
    const int tid = threadIdx.x;
    const int wid = tid >> 5, lid = tid & 31;
    const int warpM = wid & 3, warpN = wid >> 2;   // 4 x 2

    const int rowBase = blockIdx.y * 128;
    const int colBase = blockIdx.x * 128;
    const int kstart = blockIdx.z * kspan;
    const int nch = kspan / BK;
    C += (size_t)blockIdx.z * zstride;

    float acc[2][8][4];
#pragma unroll
    for (int i = 0; i < 2; i++)
#pragma unroll
        for (int j = 0; j < 8; j++)
#pragma unroll
            for (int q = 0; q < 4; q++) acc[i][j][q] = 0.0f;

    auto load_chunk = [&](int c, int buf) {
        const uint32_t st = sb + buf * STAGEB;
        const int k0 = kstart + c * BK;
#pragma unroll
        for (int ch = tid; ch < 512; ch += 256) {
            const int row = ch >> 2;
            const int kc = ch & 3;
            const uint32_t so = row * ROWB + kc * 16;
            const size_t go = (size_t)k0 + kc * 8;
            cp_async16(st + so,             Ah + (size_t)(rowBase + row) * lda + go);
            cp_async16(st + TILEB + so,     Al + (size_t)(rowBase + row) * lda + go);
            cp_async16(st + 2 * TILEB + so, Bh + (size_t)(colBase + row) * lda + go);
            cp_async16(st + 3 * TILEB + so, Bl + (size_t)(colBase + row) * lda + go);
        }
        cp_commit();
    };

    load_chunk(0, 0);
    if (1 < nch) load_chunk(1, 1); else cp_commit();
    if (2 < nch) load_chunk(2, 2); else cp_commit();

    const int lr = lid & 15;
    const int lc16 = (lid >> 4) * 16;

    for (int c = 0; c < nch; c++) {
        const int buf = c % NSTAGE;
        cp_wait<NSTAGE - 1>();
        __syncthreads();

        const uint32_t st = sb + buf * STAGEB;
#pragma unroll
        for (int kk = 0; kk < 2; kk++) {
            const uint32_t kb = kk * 32;
            uint32_t ah[2][4], al[2][4];
#pragma unroll
            for (int mf = 0; mf < 2; mf++) {
                const uint32_t a =
                    st + (warpM * 32 + mf * 16 + lr) * ROWB + kb + lc16;
                ldsm_x4(ah[mf], a);
                ldsm_x4(al[mf], a + TILEB);
            }
            uint32_t bh[8][2], bl[8][2];
#pragma unroll
            for (int np = 0; np < 4; np++) {
                const uint32_t a =
                    st + 2 * TILEB + (warpN * 64 + np * 16 + lr) * ROWB + kb + lc16;
                uint32_t t[4];
                ldsm_x4(t, a);
                bh[2 * np][0] = t[0]; bh[2 * np + 1][0] = t[1];
                bh[2 * np][1] = t[2]; bh[2 * np + 1][1] = t[3];
                ldsm_x4(t, a + TILEB);
                bl[2 * np][0] = t[0]; bl[2 * np + 1][0] = t[1];
                bl[2 * np][1] = t[2]; bl[2 * np + 1][1] = t[3];
            }
            // interleaved MMA order (proven fastest)
#pragma unroll
            for (int mf = 0; mf < 2; mf++)
#pragma unroll
                for (int nf = 0; nf < 8; nf++) {
                    mma16816(acc[mf][nf], ah[mf], bh[nf][0], bh[nf][1]);
                    mma16816(acc[mf][nf], ah[mf], bl[nf][0], bl[nf][1]);
                    mma16816(acc[mf][nf], al[mf], bh[nf][0], bh[nf][1]);
                }
        }
        __syncthreads();
        if (c + NSTAGE < nch) load_chunk(c + NSTAGE, buf);
        else cp_commit();
    }

    const int r = lid >> 2, cq = (lid & 3) * 2;
    float* Cw = C + (size_t)(rowBase + warpM * 32) * ldc + colBase + warpN * 64;
    const int cBase = colBase + warpN * 64;
#pragma unroll
    for (int mf = 0; mf < 2; mf++)
#pragma unroll
        for (int nf = 0; nf < 8; nf++) {
            float v0 = acc[mf][nf][0], v1 = acc[mf][nf][1];
            float v2 = acc[mf][nf][2], v3 = acc[mf][nf][3];
            if (bias) {
                const float b0 = bias[cBase + nf * 8 + cq];
                const float b1 = bias[cBase + nf * 8 + cq + 1];
                v0 = softplusf(v0 + b0); v1 = softplusf(v1 + b1);
                v2 = softplusf(v2 + b0); v3 = softplusf(v3 + b1);
            }
            *(float2*)&Cw[(size_t)(mf * 16 + r) * ldc + nf * 8 + cq] =
                make_float2(v0, v1);
            *(float2*)&Cw[(size_t)(mf * 16 + r + 8) * ldc + nf * 8 + cq] =
                make_float2(v2, v3);
        }
}

// ---------------------------------------------------------------------------
// Depthwise causal conv (width 4) + SiLU + fused bf16 split.
// Each thread: 4 consecutive l x 2 consecutive channels (float2 vectorized).
// ---------------------------------------------------------------------------
__global__ void conv_silu_k(const float* __restrict__ xz,
                            const float* __restrict__ w,
                            const float* __restrict__ bias,
                            float* __restrict__ xc,
                            __nv_bfloat16* __restrict__ xch,
                            __nv_bfloat16* __restrict__ xcl)
{
    const int idx = blockIdx.x * blockDim.x + threadIdx.x;  // (M/4)*(DI/2)
    if (idx >= (M / 4) * (DI / 2)) return;
    const int d0 = (idx % (DI / 2)) * 2;
    const int m0 = (idx / (DI / 2)) * 4;
    const int l0 = m0 % Lsz;   // multiple of 4

    const float4 wa = *(const float4*)&w[d0 * 4];
    const float4 wb = *(const float4*)&w[d0 * 4 + 4];
    const float2 bz = *(const float2*)&bias[d0];

    float2 xv[7];
#pragma unroll
    for (int j = 0; j < 7; j++) {
        const int mm = m0 - 3 + j;
        if (l0 + j >= 3) xv[j] = *(const float2*)&xz[(size_t)mm * XZ_N + d0];
        else             xv[j] = make_float2(0.0f, 0.0f);
    }
#pragma unroll
    for (int i = 0; i < 4; i++) {
        float a0 = bz.x, a1 = bz.y;
        a0 = fmaf(wa.x, xv[i + 0].x, a0); a1 = fmaf(wb.x, xv[i + 0].y, a1);
        a0 = fmaf(wa.y, xv[i + 1].x, a0); a1 = fmaf(wb.y, xv[i + 1].y, a1);
        a0 = fmaf(wa.z, xv[i + 2].x, a0); a1 = fmaf(wb.z, xv[i + 2].y, a1);
        a0 = fmaf(wa.w, xv[i + 3].x, a0); a1 = fmaf(wb.w, xv[i + 3].y, a1);
        const float v0 = a0 * sigmoidf_fast(a0);
        const float v1 = a1 * sigmoidf_fast(a1);
        const size_t o = (size_t)(m0 + i) * DI + d0;
        *(float2*)&xc[o] = make_float2(v0, v1);
        const __nv_bfloat16 h0 = __float2bfloat16(v0);
        const __nv_bfloat16 h1 = __float2bfloat16(v1);
        uint32_t hp = (uint32_t)__bfloat16_as_ushort(h0) |
                      ((uint32_t)__bfloat16_as_ushort(h1) << 16);
        uint32_t lp = (uint32_t)__bfloat16_as_ushort(
                          __float2bfloat16(v0 - __bfloat162float(h0))) |
                      ((uint32_t)__bfloat16_as_ushort(
                          __float2bfloat16(v1 - __bfloat162float(h1))) << 16);
        *(uint32_t*)&xch[o] = hp;
        *(uint32_t*)&xcl[o] = lp;
    }
}

// ---------------------------------------------------------------------------
// Parallel selective scan (recurrence-reinit), ex2.approx, ptot via delta-sum.
// NC=32 chunks x LC=64 steps; 512 blocks of 256 threads.
// ---------------------------------------------------------------------------
constexpr float L2E = 1.4426950408889634f;

__global__ void __launch_bounds__(256) scan1_k(
    const float* __restrict__ delta_, const float* __restrict__ xc,
    const float* __restrict__ dbcp, const float* __restrict__ A_log,
    float* __restrict__ hend, float* __restrict__ ptot)
{
    __shared__ float sB[LC][DS];
    const int tid = threadIdx.x;
    const int blk = blockIdx.x;
    const int c = blk & (NC - 1);
    const int t = blk >> 5;            // 0..15
    const int b = t >> 3;
    const int d = ((t & 7) << 8) + tid;
    const size_t mbase = (size_t)b * Lsz + c * LC;

    for (int i = tid; i < LC * DS; i += 256) {
        const int row = i >> 4, col = i & 15;
        sB[row][col] = dbcp[(mbase + row) * DBC_LD + DR + col];
    }
    float An2[DS];
#pragma unroll
    for (int s = 0; s < DS; s++) An2[s] = -__expf(A_log[d * DS + s]) * L2E;
    __syncthreads();

    float h[DS];
#pragma unroll
    for (int s = 0; s < DS; s++) h[s] = 0.0f;
    float sd = 0.0f;

#pragma unroll 2
    for (int k = 0; k < LC; k++) {
        const size_t m = mbase + k;
        const float delta = delta_[m * DI + d];
        const float du = delta * xc[m * DI + d];
        sd += delta;
#pragma unroll
        for (int s = 0; s < DS; s++) {
            const float a = ex2f(delta * An2[s]);
            h[s] = fmaf(a, h[s], du * sB[k][s]);
        }
    }
    const size_t idx = (size_t)c * (NCH * DS) + ((size_t)(b * DI + d)) * DS;
#pragma unroll
    for (int s = 0; s < DS; s++) {
        hend[idx + s] = h[s];
        ptot[idx + s] = ex2f(sd * An2[s]);
    }
}

__global__ void __launch_bounds__(256) combine_k(
    const float* __restrict__ hend, const float* __restrict__ ptot,
    float* __restrict__ hin)
{
    const int i = blockIdx.x * 256 + threadIdx.x;  // NCH*DS = 65536
    float H = 0.0f;
#pragma unroll
    for (int c = 0; c < NC; c++) {
        const size_t idx = (size_t)c * (NCH * DS) + i;
        hin[idx] = H;
        H = fmaf(ptot[idx], H, hend[idx]);
    }
}

__global__ void __launch_bounds__(256) scan2_k(
    const float* __restrict__ delta_, const float* __restrict__ xc,
    const float* __restrict__ dbcp, const float* __restrict__ xz,
    const float* __restrict__ A_log, const float* __restrict__ D_skip,
    const float* __restrict__ hin_,
    __nv_bfloat16* __restrict__ yzh, __nv_bfloat16* __restrict__ yzl)
{
    __shared__ float sB[LC][DS];
    __shared__ float sC[LC][DS];
    const int tid = threadIdx.x;
    const int blk = blockIdx.x;
    const int c = blk & (NC - 1);
    const int t = blk >> 5;
    const int b = t >> 3;
    const int d = ((t & 7) << 8) + tid;
    const size_t mbase = (size_t)b * Lsz + c * LC;

    for (int i = tid; i < LC * 32; i += 256) {
        const int row = i >> 5, col = i & 31;
        const float v = dbcp[(mbase + row) * DBC_LD + DR + col];
        if (col < DS) sB[row][col] = v;
        else          sC[row][col - DS] = v;
    }
    float An2[DS];
#pragma unroll
    for (int s = 0; s < DS; s++) An2[s] = -__expf(A_log[d * DS + s]) * L2E;
    const float dskip = D_skip[d];

    float h[DS];
    const size_t hidx = (size_t)c * (NCH * DS) + ((size_t)(b * DI + d)) * DS;
#pragma unroll
    for (int s = 0; s < DS; s++) h[s] = hin_[hidx + s];
    __syncthreads();

#pragma unroll 2
    for (int k = 0; k < LC; k++) {
        const size_t m = mbase + k;
        const float delta = delta_[m * DI + d];
        const float u = xc[m * DI + d];
        const float du = delta * u;
        float y = 0.0f;
#pragma unroll
        for (int s = 0; s < DS; s++) {
            const float a = ex2f(delta * An2[s]);
            h[s] = fmaf(a, h[s], du * sB[k][s]);
            y = fmaf(h[s], sC[k][s], y);
        }
        const float z = xz[m * XZ_N + DI + d];
        const float val = (y + u * dskip) * (z * sigmoidf_fast(z));
        const __nv_bfloat16 hh = __float2bfloat16(val);
        yzh[m * DI + d] = hh;
        yzl[m * DI + d] = __float2bfloat16(val - __bfloat162float(hh));
    }
}

// ---------------------------------------------------------------------------
extern "C" void kernel_launch(void* const* d_in, const int* in_sizes, int n_in,
                              void* d_out, int out_size)
{
    const float* x      = (const float*)d_in[0];
    const float* W_in   = (const float*)d_in[1];
    const float* conv_w = (const float*)d_in[2];
    const float* conv_b = (const float*)d_in[3];
    const float* W_xprj = (const float*)d_in[4];
    const float* W_dt   = (const float*)d_in[5];
    const float* b_dt   = (const float*)d_in[6];
    const float* A_log  = (const float*)d_in[7];
    const float* D_skip = (const float*)d_in[8];
    const float* W_out  = (const float*)d_in[9];
    float* out = (float*)d_out;

    float *xz, *xc, *dbcp, *dbcpart, *outpart, *delta, *hend, *ptot, *hin;
    cudaGetSymbolAddress((void**)&xz, g_xz);
    cudaGetSymbolAddress((void**)&xc, g_xc);
    cudaGetSymbolAddress((void**)&dbcp, g_dbcp);
    cudaGetSymbolAddress((void**)&dbcpart, g_dbcpart);
    cudaGetSymbolAddress((void**)&outpart, g_outpart);
    cudaGetSymbolAddress((void**)&delta, g_delta);
    cudaGetSymbolAddress((void**)&hend, g_hend);
    cudaGetSymbolAddress((void**)&ptot, g_ptot);
    cudaGetSymbolAddress((void**)&hin, g_hin);
    __nv_bfloat16 *xh, *xl, *winh, *winl, *xch, *xcl, *wxh, *wxl,
                  *dth, *dtl, *wdth, *wdtl, *yzh, *yzl, *wouth, *woutl;
    cudaGetSymbolAddress((void**)&xh, g_xh);
    cudaGetSymbolAddress((void**)&xl, g_xl);
    cudaGetSymbolAddress((void**)&winh, g_winh);
    cudaGetSymbolAddress((void**)&winl, g_winl);
    cudaGetSymbolAddress((void**)&xch, g_xch);
    cudaGetSymbolAddress((void**)&xcl, g_xcl);
    cudaGetSymbolAddress((void**)&wxh, g_wxh);
    cudaGetSymbolAddress((void**)&wxl, g_wxl);
    cudaGetSymbolAddress((void**)&dth, g_dth);
    cudaGetSymbolAddress((void**)&dtl, g_dtl);
    cudaGetSymbolAddress((void**)&wdth, g_wdth);
    cudaGetSymbolAddress((void**)&wdtl, g_wdtl);
    cudaGetSymbolAddress((void**)&yzh, g_yzh);
    cudaGetSymbolAddress((void**)&yzl, g_yzl);
    cudaGetSymbolAddress((void**)&wouth, g_wouth);
    cudaGetSymbolAddress((void**)&woutl, g_woutl);

    cudaFuncSetAttribute(mma_gemm_k, cudaFuncAttributeMaxDynamicSharedMemorySize,
                         SMEM_MMA);

    // Side stream + fork/join events (created once on the first, uncaptured
    // correctness call; reused identically on every subsequent call so the
    // launched work is the same each time).
    static cudaStream_t s2 = nullptr;
    static cudaEvent_t evFork = nullptr, evJoin = nullptr;
    if (s2 == nullptr) {
        cudaStreamCreateWithFlags(&s2, cudaStreamNonBlocking);
        cudaEventCreateWithFlags(&evFork, cudaEventDisableTiming);
        cudaEventCreateWithFlags(&evJoin, cudaEventDisableTiming);
    }

    // 0) operand prep: weights + x, single launch
    prep_w_k<<<10624, dim3(32, 8)>>>(W_in, W_out, W_xprj, W_dt, x,
                                     winh, winl, wouth, woutl,
                                     wxh, wxl, wdth, wdtl, xh, xl);

    // Fork: z-half of GEMM1 runs on s2, overlapping the conv->scan1 chain.
    cudaEventRecord(evFork, 0);
    cudaStreamWaitEvent(s2, evFork, 0);
    {   // 1b) xz[:, DI:2DI] = x @ W_in[:, DI:2DI]   (on s2)
        dim3 grid(DI / 128, M / 128, 1);
        mma_gemm_k<<<grid, 256, SMEM_MMA, s2>>>(
            xh, xl, winh + (size_t)DI * DM, winl + (size_t)DI * DM,
            xz + DI, DM, XZ_N, DM, 0, nullptr);
    }
    cudaEventRecord(evJoin, s2);

    // 1a) xz[:, 0:DI] = x @ W_in[:, 0:DI]   (main stream)
    {
        dim3 grid(DI / 128, M / 128, 1);
        mma_gemm_k<<<grid, 256, SMEM_MMA>>>(xh, xl, winh, winl, xz, DM, XZ_N,
                                            DM, 0, nullptr);
    }
    // 2) conv + silu (+ bf16 split) — needs only the xin half
    conv_silu_k<<<((M / 4) * (DI / 2) + 255) / 256, 256>>>(xz, conv_w, conv_b,
                                                           xc, xch, xcl);
    // 3) dbc = xc @ W_xproj (mma, padded N=128, split-K x4)
    {
        dim3 grid(1, M / 128, KSPLIT);
        mma_gemm_k<<<grid, 256, SMEM_MMA>>>(xch, xcl, wxh, wxl, dbcpart, DI,
                                            DBC_LD, DI / KSPLIT,
                                            (size_t)M * DBC_LD, nullptr);
        reduce_part_k<<<(M * DBC_LD / 4 + 255) / 256, 256>>>(
            dbcpart, dbcp, M * DBC_LD / 4, (size_t)M * DBC_LD / 4,
            DBC_LD, DR, dth, dtl);
    }
    // 4) delta = softplus(dt_lo @ W_dt + b_dt) (mma, K=64, fused epilogue)
    {
        dim3 grid(DI / 128, M / 128, 1);
        mma_gemm_k<<<grid, 256, SMEM_MMA>>>(dth, dtl, wdth, wdtl, delta, DR, DI,
                                            DR, 0, b_dt);
    }
    // 5) parallel selective scan (scan2 needs the z half -> join first)
    {
        const int blocks = Bsz * (DI / 256) * NC;  // 512
        scan1_k<<<blocks, 256>>>(delta, xc, dbcp, A_log, hend, ptot);
        combine_k<<<(NCH * DS) / 256, 256>>>(hend, ptot, hin);
        cudaStreamWaitEvent(0, evJoin, 0);   // join z-half GEMM
        scan2_k<<<blocks, 256>>>(delta, xc, dbcp, xz, A_log, D_skip, hin,
                                 yzh, yzl);
    }
    // 6) out = yz @ W_out (mma, split-K x4)
    {
        dim3 grid(DM / 128, M / 128, KSPLIT);
        mma_gemm_k<<<grid, 256, SMEM_MMA>>>(yzh, yzl, wouth, woutl, outpart,
                                            DI, DM, DI / KSPLIT,
                                            (size_t)M * DM, nullptr);
        reduce_part_k<<<(M * DM / 4 + 255) / 256, 256>>>(
            outpart, out, M * DM / 4, (size_t)M * DM / 4,
            DM, 0, nullptr, nullptr);
    }
}